// round 6
// baseline (speedup 1.0000x reference)
#include <cuda_runtime.h>
#include <cstddef>
#include <cstdint>

// Problem constants
#define BQ 8
#define NN 2000
#define TT 64
#define FF 32
#define HH 128
#define NG 512           // 4*H gates
#define KT 160           // H + F combined GEMM depth
#define EE 32000
#define MM 16000         // B*N sequences
#define GHD 128

#define MT 32            // LSTM rows per CTA (4 pairs x 8 rows)
#define PITCH 336        // duplicated A row: 2*KT + 16 pad (floats)
#define KB 16            // K-block size for staged B
#define NKB (KT / KB)    // 10 blocks

// dynamic smem layout (floats)
#define HS_F   (4 * 8 * PITCH)        // 10752
#define BS_F   (2 * KB * NG)          // 16384
#define BSM_F  (NG)                   // 512
#define SMEM_BYTES ((HS_F + BS_F + BSM_F) * 4)   // 110592 B

typedef unsigned long long ull_t;

// ------------------------- device scratch (static, no allocs) -------------
__device__ __align__(16) float g_WT[KT * NG];   // transposed weights [k][gate-col]
__device__ __align__(16) float g_bias[NG];      // bih + bhh
__device__ float g_deg[NN];
__device__ float g_dinv[NN];
__device__ float g_norm[EE];
__device__ __align__(16) float g_h[MM * HH];    // LSTM final hidden
__device__ __align__(16) float g_xw[MM * GHD];  // node_features @ gcn_W
__device__ __align__(16) float g_agg[(size_t)BQ * NN * GHD];

// ------------------------- helpers ----------------------------------------
__device__ __forceinline__ void upk2(ull_t v, float &x, float &y) {
    asm("mov.b64 {%0,%1}, %2;" : "=f"(x), "=f"(y) : "l"(v));
}
__device__ __forceinline__ void fma2(ull_t &d, ull_t a, ull_t b) {
    asm("fma.rn.f32x2 %0, %1, %2, %0;" : "+l"(d) : "l"(a), "l"(b));
}
__device__ __forceinline__ float sigmf(float x) {
    return __fdividef(1.f, 1.f + __expf(-x));
}
__device__ __forceinline__ float tanhfast(float x) {
    return __fdividef(2.f, 1.f + __expf(-2.f * x)) - 1.f;
}
__device__ __forceinline__ void cp16(uint32_t dst, const void* src) {
    asm volatile("cp.async.cg.shared.global [%0], [%1], 16;" :: "r"(dst), "l"(src));
}
__device__ __forceinline__ void cp_commit() {
    asm volatile("cp.async.commit_group;" ::: "memory");
}
__device__ __forceinline__ void cp_wait1() {
    asm volatile("cp.async.wait_group 1;" ::: "memory");
}
__device__ __forceinline__ void cp_wait0() {
    asm volatile("cp.async.wait_group 0;" ::: "memory");
}

// ------------------------- prep: weights + bias + deg init ----------------
__global__ void k_prep(const float* __restrict__ Wih,
                       const float* __restrict__ Whh,
                       const float* __restrict__ bih,
                       const float* __restrict__ bhh) {
    int idx = blockIdx.x * blockDim.x + threadIdx.x;
    if (idx < KT * NG) {
        int k = idx / NG;
        int n = idx % NG;
        float v = (k < HH) ? Whh[n * HH + k] : Wih[n * FF + (k - HH)];
        g_WT[idx] = v;
    }
    if (idx < NG) g_bias[idx] = bih[idx] + bhh[idx];
    if (idx < NN) g_deg[idx] = 1.0f;  // self-loop
}

__global__ void k_deg(const int* __restrict__ ei) {
    int e = blockIdx.x * blockDim.x + threadIdx.x;
    if (e < EE) atomicAdd(&g_deg[ei[EE + e]], 1.0f);
}
__global__ void k_dinv() {
    int n = blockIdx.x * blockDim.x + threadIdx.x;
    if (n < NN) g_dinv[n] = rsqrtf(g_deg[n]);
}
__global__ void k_norm(const int* __restrict__ ei) {
    int e = blockIdx.x * blockDim.x + threadIdx.x;
    if (e < EE) g_norm[e] = g_dinv[ei[e]] * g_dinv[ei[EE + e]];
}

// ------------------------- fused LSTM --------------------------------------
// 500 CTAs x 256 threads = 4 warp-pairs; pair p owns rows [8p, 8p+8).
// Lane-in-pair q (0..63) owns hidden units {2q, 2q+1} of every gate.
// A (h|x) duplicated in smem so LDS.64 yields packed {a,a} for fma.rn.f32x2.
// B (weights) cooperatively staged per CTA into a double-buffered smem ring
// via cp.async: one 32KB block of [16 k][512 gates] fp32 at a time.
__global__ __launch_bounds__(256, 2) void k_lstm(const float* __restrict__ x) {
    extern __shared__ __align__(16) float smem[];
    float* hsbase = smem;                 // [4][8][PITCH]
    float* bs     = smem + HS_F;          // [2][KB][NG]
    float* bsm    = smem + HS_F + BS_F;   // [NG]

    const int tid = threadIdx.x;
    const int q   = tid & 63;     // lane within pair
    const int p   = tid >> 6;     // pair id
    const int l   = tid & 31;     // lane within warp
    const int mbase = blockIdx.x * MT + p * 8;

    float* myhs = hsbase + p * (8 * PITCH);

    // bias into smem
    for (int i = tid; i < NG; i += 256) bsm[i] = g_bias[i];

    // zero h-region (dup cols 0..255) of this pair's 8 rows
    for (int idx = q; idx < 8 * 256; idx += 64)
        myhs[(idx >> 8) * PITCH + (idx & 255)] = 0.f;

    // stage x_0 (each warp writes dups for all 8 rows: benign double-write)
    {
        int j0 = l, j1 = l + 32;
        int r0 = j0 >> 3, q0 = j0 & 7;
        int r1 = j1 >> 3, q1 = j1 & 7;
        float4 v0 = __ldg((const float4*)&x[((size_t)(mbase + r0) * TT + 0) * FF + 4 * q0]);
        float4 v1 = __ldg((const float4*)&x[((size_t)(mbase + r1) * TT + 0) * FF + 4 * q1]);
        *(float4*)&myhs[r0 * PITCH + 256 + 8 * q0]     = make_float4(v0.x, v0.x, v0.y, v0.y);
        *(float4*)&myhs[r0 * PITCH + 256 + 8 * q0 + 4] = make_float4(v0.z, v0.z, v0.w, v0.w);
        *(float4*)&myhs[r1 * PITCH + 256 + 8 * q1]     = make_float4(v1.x, v1.x, v1.y, v1.y);
        *(float4*)&myhs[r1 * PITCH + 256 + 8 * q1 + 4] = make_float4(v1.z, v1.z, v1.w, v1.w);
    }
    __syncthreads();

    float c0[8], c1[8];
#pragma unroll
    for (int i = 0; i < 8; i++) { c0[i] = 0.f; c1[i] = 0.f; }

    // cp.async staging addresses for this thread
    const uint32_t bs_s32 = (uint32_t)__cvta_generic_to_shared(bs);
    const int jr0 = l >> 3,        jq0 = (l & 7);
    const int jr1 = (l + 32) >> 3, jq1 = ((l + 32) & 7);

    for (int t = 0; t < TT; t++) {
        // prefetch x_{t+1}
        float4 xr0, xr1;
        if (t < TT - 1) {
            xr0 = __ldg((const float4*)&x[((size_t)(mbase + jr0) * TT + t + 1) * FF + 4 * jq0]);
            xr1 = __ldg((const float4*)&x[((size_t)(mbase + jr1) * TT + t + 1) * FF + 4 * jq1]);
        }

        // init accumulators from bias (smem)
        ull_t bias2[4];
#pragma unroll
        for (int g = 0; g < 4; g++)
            bias2[g] = *(const ull_t*)&bsm[g * HH + 2 * q];

        ull_t acc[8][4];
#pragma unroll
        for (int i = 0; i < 8; i++) {
#pragma unroll
            for (int g = 0; g < 4; g++) acc[i][g] = bias2[g];
        }

        // stage block 0 into buffer 0
        {
            const float* src = g_WT;
#pragma unroll
            for (int j = 0; j < 8; j++) {
                int off = (tid + j * 256) * 4;   // float index, 16B granular
                cp16(bs_s32 + off * 4, src + off);
            }
            cp_commit();
        }

        for (int kb = 0; kb < NKB; kb++) {
            if (kb < NKB - 1) {
                const float* src = g_WT + (kb + 1) * (KB * NG);
                uint32_t dstb = bs_s32 + (((kb + 1) & 1) * KB * NG) * 4;
#pragma unroll
                for (int j = 0; j < 8; j++) {
                    int off = (tid + j * 256) * 4;
                    cp16(dstb + off * 4, src + off);
                }
                cp_commit();
                cp_wait1();
            } else {
                cp_wait0();
            }
            __syncthreads();   // buffer kb ready for all

            const float* bb = bs + (kb & 1) * (KB * NG) + 2 * q;
            const float* a0 = myhs + 2 * (kb * KB);

#pragma unroll
            for (int kk = 0; kk < KB; kk++) {
                const float* wk = bb + kk * NG;
                ull_t b0 = *(const ull_t*)(wk);
                ull_t b1 = *(const ull_t*)(wk + HH);
                ull_t b2 = *(const ull_t*)(wk + 2 * HH);
                ull_t b3 = *(const ull_t*)(wk + 3 * HH);
#pragma unroll
                for (int i = 0; i < 8; i++) {
                    ull_t aa = *(const ull_t*)(a0 + i * PITCH + 2 * kk);
                    fma2(acc[i][0], aa, b0);
                    fma2(acc[i][1], aa, b1);
                    fma2(acc[i][2], aa, b2);
                    fma2(acc[i][3], aa, b3);
                }
            }
            __syncthreads();   // all done reading buf before it is restaged
        }

        // gates (torch order i,f,g,o); h written as dup pairs into smem
#pragma unroll
        for (int i = 0; i < 8; i++) {
            float zi0, zi1, zf0, zf1, zg0, zg1, zo0, zo1;
            upk2(acc[i][0], zi0, zi1);
            upk2(acc[i][1], zf0, zf1);
            upk2(acc[i][2], zg0, zg1);
            upk2(acc[i][3], zo0, zo1);

            float ig = sigmf(zi0), fg = sigmf(zf0);
            float gg = tanhfast(zg0), og = sigmf(zo0);
            float cc = fg * c0[i] + ig * gg;
            c0[i] = cc;
            float h0 = og * tanhfast(cc);

            ig = sigmf(zi1); fg = sigmf(zf1);
            gg = tanhfast(zg1); og = sigmf(zo1);
            cc = fg * c1[i] + ig * gg;
            c1[i] = cc;
            float h1 = og * tanhfast(cc);

            *(float4*)&myhs[i * PITCH + 4 * q] = make_float4(h0, h0, h1, h1);

            if (t == TT - 1)
                *(float2*)&g_h[(size_t)(mbase + i) * HH + 2 * q] =
                    make_float2(h0, h1);
        }

        if (t < TT - 1) {
            *(float4*)&myhs[jr0 * PITCH + 256 + 8 * jq0]     = make_float4(xr0.x, xr0.x, xr0.y, xr0.y);
            *(float4*)&myhs[jr0 * PITCH + 256 + 8 * jq0 + 4] = make_float4(xr0.z, xr0.z, xr0.w, xr0.w);
            *(float4*)&myhs[jr1 * PITCH + 256 + 8 * jq1]     = make_float4(xr1.x, xr1.x, xr1.y, xr1.y);
            *(float4*)&myhs[jr1 * PITCH + 256 + 8 * jq1 + 4] = make_float4(xr1.z, xr1.z, xr1.w, xr1.w);
        }
        // visibility of h/x writes is guaranteed by the __syncthreads at the
        // start of the next step's first K-block.
    }
}

// ------------------------- GCN: xw = h @ gcn_W -----------------------------
__global__ void k_xw(const float* __restrict__ gW) {
    __shared__ float hsm[16][HH];
    const int tid = threadIdx.x;
    const int rowbase = blockIdx.x * 16;

#pragma unroll
    for (int r = 0; r < 16; r++) {
        int idx = tid + r * 128;
        hsm[idx >> 7][idx & 127] = g_h[(size_t)rowbase * HH + idx];
    }
    __syncthreads();

    float acc[16];
#pragma unroll
    for (int r = 0; r < 16; r++) acc[r] = 0.f;

#pragma unroll 4
    for (int k = 0; k < HH; k++) {
        float wv = __ldg(&gW[k * GHD + tid]);
#pragma unroll
        for (int r = 0; r < 16; r++) acc[r] += hsm[r][k] * wv;
    }
#pragma unroll
    for (int r = 0; r < 16; r++)
        g_xw[(size_t)(rowbase + r) * GHD + tid] = acc[r];
}

// ------------------------- GCN scatter --------------------------------------
__global__ void k_agg_zero() {
    size_t idx = (size_t)blockIdx.x * blockDim.x + threadIdx.x;
    if (idx < (size_t)BQ * NN * GHD) g_agg[idx] = 0.f;
}

__global__ void k_scatter(const int* __restrict__ ei) {
    const int e = blockIdx.x;
    const int ch = threadIdx.x;
    int s, d;
    float wv;
    if (e < EE) {
        s = ei[e];
        d = ei[EE + e];
        wv = g_norm[e];
    } else {
        s = d = e - EE;
        float di = g_dinv[s];
        wv = di * di;
    }
#pragma unroll
    for (int b = 0; b < BQ; b++) {
        float v = g_xw[((size_t)b * NN + s) * GHD + ch] * wv;
        atomicAdd(&g_agg[((size_t)b * NN + d) * GHD + ch], v);
    }
}

// ------------------------- MLP head -----------------------------------------
__global__ void k_mlp(const float* __restrict__ gb,
                      const float* __restrict__ W1,
                      const float* __restrict__ b1,
                      const float* __restrict__ W2,
                      const float* __restrict__ b2,
                      float* __restrict__ out) {
    __shared__ float in_s[GHD];
    __shared__ float red[64];
    const int m = blockIdx.x;
    const int ch = threadIdx.x;

    in_s[ch] = g_agg[(size_t)m * GHD + ch] + __ldg(&gb[ch]);
    __syncthreads();

    if (ch < 64) {
        float s = __ldg(&b1[ch]);
#pragma unroll 8
        for (int k = 0; k < GHD; k++)
            s += in_s[k] * __ldg(&W1[k * 64 + ch]);
        float h1 = s * sigmf(s);           // silu
        red[ch] = h1 * __ldg(&W2[ch]);
    }
    __syncthreads();

    if (ch == 0) {
        float s = __ldg(&b2[0]);
#pragma unroll
        for (int j = 0; j < 64; j++) s += red[j];
        out[m] = s;
    }
}

// ------------------------- launch --------------------------------------------
extern "C" void kernel_launch(void* const* d_in, const int* in_sizes, int n_in,
                              void* d_out, int out_size) {
    const float* x   = (const float*)d_in[0];
    const int*   ei  = (const int*)d_in[1];
    const float* Wih = (const float*)d_in[2];
    const float* Whh = (const float*)d_in[3];
    const float* bih = (const float*)d_in[4];
    const float* bhh = (const float*)d_in[5];
    const float* gW  = (const float*)d_in[6];
    const float* gb  = (const float*)d_in[7];
    const float* W1  = (const float*)d_in[8];
    const float* b1  = (const float*)d_in[9];
    const float* W2  = (const float*)d_in[10];
    const float* b2  = (const float*)d_in[11];
    float* out = (float*)d_out;

    static int attr_done = 0;
    if (!attr_done) {
        cudaFuncSetAttribute(k_lstm,
                             cudaFuncAttributeMaxDynamicSharedMemorySize,
                             SMEM_BYTES);
        attr_done = 1;
    }

    // k_lstm is the 4th launch -> lands in the profiler's fixed sampling slot
    k_prep<<<(KT * NG + 255) / 256, 256>>>(Wih, Whh, bih, bhh);
    k_deg<<<(EE + 255) / 256, 256>>>(ei);
    k_dinv<<<(NN + 255) / 256, 256>>>();
    k_lstm<<<MM / MT, 256, SMEM_BYTES>>>(x);
    k_norm<<<(EE + 255) / 256, 256>>>(ei);

    k_xw<<<MM / 16, 128>>>(gW);
    k_agg_zero<<<((size_t)BQ * NN * GHD + 255) / 256, 256>>>();
    k_scatter<<<EE + NN, 128>>>(ei);
    k_mlp<<<MM, 128>>>(gb, W1, b1, W2, b2, out);
}

// round 8
// speedup vs baseline: 1.3219x; 1.3219x over previous
#include <cuda_runtime.h>
#include <cuda_bf16.h>
#include <cstddef>
#include <cstdint>

#define BQ 8
#define NN 2000
#define TT 64
#define FF 32
#define HH 128
#define NG 512
#define EE 32000
#define MM 16000
#define GHD 128

// ---- mma LSTM geometry ----
#define MROWS 64            // rows per CTA
#define NCHUNK 20           // W blob chunks per step
#define CHUNK_BYTES 16384   // gmem: 512 nperm x 16 k x bf16
#define CHUNK_SMEM 24576    // smem: pitch-padded 512 x 48B
#define PA 136              // A (h) pitch in bf16 elems
#define PX 72               // x pitch in bf16 elems

// smem layout (bytes)
#define AHI_OFF 0
#define ALO_OFF 17408
#define XHI_OFF 34816
#define XLO_OFF 44032
#define BR_OFF  53248
#define BIAS_OFF 102400
#define DYN_BYTES 104448

// ------------------------- device scratch ----------------------------------
__device__ __align__(16) unsigned short g_Wblob[NCHUNK * 8192];
__device__ __align__(16) float g_bias[NG];
__device__ float g_deg[NN];
__device__ float g_dinv[NN];
__device__ float g_norm[EE];
__device__ __align__(16) float g_h[MM * HH];
__device__ __align__(16) float g_xw[MM * GHD];
__device__ __align__(16) float g_agg[(size_t)BQ * NN * GHD];

// ------------------------- helpers -----------------------------------------
__device__ __forceinline__ float sigmf(float x) {
    return __fdividef(1.f, 1.f + __expf(-x));
}
__device__ __forceinline__ float tanhfast(float x) {
    return __fdividef(2.f, 1.f + __expf(-2.f * x)) - 1.f;
}
__device__ __forceinline__ void cp16(uint32_t dst, const void* src) {
    asm volatile("cp.async.cg.shared.global [%0], [%1], 16;" :: "r"(dst), "l"(src));
}
__device__ __forceinline__ void cp_commit() {
    asm volatile("cp.async.commit_group;" ::: "memory");
}
__device__ __forceinline__ void cp_wait1() {
    asm volatile("cp.async.wait_group 1;" ::: "memory");
}
__device__ __forceinline__ void cp_wait0() {
    asm volatile("cp.async.wait_group 0;" ::: "memory");
}
__device__ __forceinline__ void ldsm4(uint32_t& r0, uint32_t& r1, uint32_t& r2,
                                      uint32_t& r3, uint32_t addr) {
    asm volatile("ldmatrix.sync.aligned.m8n8.x4.shared.b16 {%0,%1,%2,%3}, [%4];"
                 : "=r"(r0), "=r"(r1), "=r"(r2), "=r"(r3) : "r"(addr));
}
__device__ __forceinline__ void mma16816(float* d, uint32_t a0, uint32_t a1,
                                         uint32_t a2, uint32_t a3,
                                         uint32_t b0, uint32_t b1) {
    asm volatile(
        "mma.sync.aligned.m16n8k16.row.col.f32.bf16.bf16.f32 "
        "{%0,%1,%2,%3}, {%4,%5,%6,%7}, {%8,%9}, {%0,%1,%2,%3};"
        : "+f"(d[0]), "+f"(d[1]), "+f"(d[2]), "+f"(d[3])
        : "r"(a0), "r"(a1), "r"(a2), "r"(a3), "r"(b0), "r"(b1));
}
__device__ __forceinline__ uint32_t bfbits(float v) {
    return (uint32_t)__bfloat16_as_ushort(__float2bfloat16(v));
}

// ------------------------- prep kernels -------------------------------------
__global__ void k_prep(const float* __restrict__ bih, const float* __restrict__ bhh) {
    int i = blockIdx.x * blockDim.x + threadIdx.x;
    if (i < NG) g_bias[i] = bih[i] + bhh[i];
    if (i < NN) g_deg[i] = 1.0f;
}

// W blob: 20 chunks x [512 nperm][16 k] bf16. nperm = 4u+g -> orig n = 128g+u.
// chunks 0-7: hi(Whh) k16c; 8-15: lo(Whh); 16-17: hi(Wih); 18-19: lo(Wih).
__global__ void k_prep_wb(const float* __restrict__ Whh, const float* __restrict__ Wih) {
    int idx = blockIdx.x * blockDim.x + threadIdx.x;
    if (idx >= NCHUNK * 8192) return;
    int c = idx >> 13, rem = idx & 8191;
    int np = rem >> 4, kk = rem & 15;
    int u = np >> 2, g = np & 3;
    int n = g * HH + u;
    float v; bool lo;
    if (c < 8)       { v = Whh[n * HH + c * 16 + kk];        lo = false; }
    else if (c < 16) { v = Whh[n * HH + (c - 8) * 16 + kk];  lo = true;  }
    else if (c < 18) { v = Wih[n * FF + (c - 16) * 16 + kk]; lo = false; }
    else             { v = Wih[n * FF + (c - 18) * 16 + kk]; lo = true;  }
    __nv_bfloat16 hi = __float2bfloat16(v);
    __nv_bfloat16 out = lo ? __float2bfloat16(v - __bfloat162float(hi)) : hi;
    g_Wblob[c * 8192 + np * 16 + kk] = __bfloat16_as_ushort(out);
}

__global__ void k_deg(const int* __restrict__ ei) {
    int e = blockIdx.x * blockDim.x + threadIdx.x;
    if (e < EE) atomicAdd(&g_deg[ei[EE + e]], 1.0f);
}
__global__ void k_dinv() {
    int n = blockIdx.x * blockDim.x + threadIdx.x;
    if (n < NN) g_dinv[n] = rsqrtf(g_deg[n]);
}
__global__ void k_norm(const int* __restrict__ ei) {
    int e = blockIdx.x * blockDim.x + threadIdx.x;
    if (e < EE) g_norm[e] = g_dinv[ei[e]] * g_dinv[ei[EE + e]];
}

// ------------------------- mma.sync LSTM ------------------------------------
// 250 CTAs x 512 threads (16 warps), M=64 rows. Warp w: m-block (w&3)*16,
// perm-cols 128*(w>>2). Per step: z[64,512] = A @ W' (3-term bf16 split),
// W' streamed chunk-by-chunk (k16 x 512 nperm) through a 2-slot cp.async ring.
// Gate-permuted W cols (4u+g) keep all 4 gates of a unit inside one warp;
// shfl.xor(1) pairs (i,f)/(g,o) lanes; c state in registers.
__global__ void __launch_bounds__(512, 1) k_lstm_mma(const float* __restrict__ x) {
    extern __shared__ __align__(16) char sm[];
    const uint32_t sbase = (uint32_t)__cvta_generic_to_shared(sm);
    const int tid = threadIdx.x;
    const int lane = tid & 31;
    const int w = tid >> 5;
    const int mb = 16 * (w & 3);
    const int nb = 128 * (w >> 2);
    const int mbase = blockIdx.x * MROWS;

    // zero A hi/lo (2 x 17408 B)
    {
        uint4 z = make_uint4(0, 0, 0, 0);
        for (int i = tid; i < 2176; i += 512) *(uint4*)(sm + i * 16) = z;
    }
    // bias as float4 per unit (i,f,g,o)
    if (tid < HH) {
        float4 b4 = make_float4(g_bias[tid], g_bias[HH + tid],
                                g_bias[2 * HH + tid], g_bias[3 * HH + tid]);
        *(float4*)(sm + BIAS_OFF + tid * 16) = b4;
    }
    // stage x(0): thread -> row tid/8, feats 4*(tid%8)..+3
    const int xr = tid >> 3, xf = (tid & 7) * 4;
    {
        const float* xp = x + (size_t)(mbase + xr) * (TT * FF) + xf;
        float4 v = __ldg((const float4*)xp);
        float vv[4] = {v.x, v.y, v.z, v.w};
        uint32_t h01, h23, l01, l23;
        {
            __nv_bfloat16 h0 = __float2bfloat16(vv[0]), h1 = __float2bfloat16(vv[1]);
            __nv_bfloat16 h2 = __float2bfloat16(vv[2]), h3 = __float2bfloat16(vv[3]);
            h01 = (uint32_t)__bfloat16_as_ushort(h0) | ((uint32_t)__bfloat16_as_ushort(h1) << 16);
            h23 = (uint32_t)__bfloat16_as_ushort(h2) | ((uint32_t)__bfloat16_as_ushort(h3) << 16);
            l01 = bfbits(vv[0] - __bfloat162float(h0)) | (bfbits(vv[1] - __bfloat162float(h1)) << 16);
            l23 = bfbits(vv[2] - __bfloat162float(h2)) | (bfbits(vv[3] - __bfloat162float(h3)) << 16);
        }
        *(uint2*)(sm + XHI_OFF + (xr * PX + xf) * 2) = make_uint2(h01, h23);
        *(uint2*)(sm + XLO_OFF + (xr * PX + xf) * 2) = make_uint2(l01, l23);
    }

    // per-lane ldmatrix address pieces
    const uint32_t a_row = mb + (lane & 7) + (((lane >> 3) & 1) << 3);
    const uint32_t a_kh = (lane & 16) ? 8 : 0;
    const uint32_t aoff_hi = sbase + AHI_OFF + (a_row * PA + a_kh) * 2;
    const uint32_t aoff_lo = sbase + ALO_OFF + (a_row * PA + a_kh) * 2;
    const uint32_t xoff_hi = sbase + XHI_OFF + (a_row * PX + a_kh) * 2;
    const uint32_t xoff_lo = sbase + XLO_OFF + (a_row * PX + a_kh) * 2;
    const uint32_t b_row = (lane & 7) + ((lane & 16) ? 8 : 0);
    const uint32_t b_kh = ((lane >> 3) & 1) * 16;
    const uint32_t boff = sbase + BR_OFF + (nb + b_row) * 48 + b_kh;

    float cst[16];
#pragma unroll
    for (int i = 0; i < 16; i++) cst[i] = 0.f;

    const bool odd = lane & 1;
    const int rbase = (lane >> 2) + (odd ? 8 : 0);

    __syncthreads();

    for (int t = 0; t < TT; t++) {
        float acc[4][16];
#pragma unroll
        for (int i = 0; i < 4; i++)
#pragma unroll
            for (int j = 0; j < 16; j++) acc[i][j] = 0.f;

        // stage chunk 0 into ring buf 0 (each thread: one 32B nperm row)
        {
            const char* src = (const char*)g_Wblob + tid * 32;
            uint32_t dst = sbase + BR_OFF + tid * 48;
            cp16(dst, src);
            cp16(dst + 16, src + 16);
            cp_commit();
        }

        for (int c = 0; c < NCHUNK; c++) {
            if (c < NCHUNK - 1) {
                const char* src = (const char*)g_Wblob + (c + 1) * CHUNK_BYTES + tid * 32;
                uint32_t dst = sbase + BR_OFF + ((c + 1) & 1) * CHUNK_SMEM + tid * 48;
                cp16(dst, src);
                cp16(dst + 16, src + 16);
                cp_commit();
                cp_wait1();
            } else {
                cp_wait0();
            }
            __syncthreads();

            const uint32_t bB = boff + (c & 1) * CHUNK_SMEM;
            uint32_t aadr0, aadr1 = 0;
            int two;
            if (c < 8)       { aadr0 = aoff_hi + 32 * c;        aadr1 = aoff_lo + 32 * c;        two = 1; }
            else if (c < 16) { aadr0 = aoff_hi + 32 * (c - 8);                                    two = 0; }
            else if (c < 18) { aadr0 = xoff_hi + 32 * (c - 16); aadr1 = xoff_lo + 32 * (c - 16); two = 1; }
            else             { aadr0 = xoff_hi + 32 * (c - 18);                                   two = 0; }

            uint32_t a0, a1, a2, a3, e0, e1, e2, e3;
            ldsm4(a0, a1, a2, a3, aadr0);
            if (two) ldsm4(e0, e1, e2, e3, aadr1);

#pragma unroll
            for (int tau = 0; tau < 4; tau++) {
                uint32_t bt = bB + tau * (32 * 48);
                uint32_t b0, b1, b2, b3, b4, b5, b6, b7;
                ldsm4(b0, b1, b2, b3, bt);
                ldsm4(b4, b5, b6, b7, bt + 16 * 48);
                mma16816(&acc[tau][0],  a0, a1, a2, a3, b0, b1);
                mma16816(&acc[tau][4],  a0, a1, a2, a3, b2, b3);
                mma16816(&acc[tau][8],  a0, a1, a2, a3, b4, b5);
                mma16816(&acc[tau][12], a0, a1, a2, a3, b6, b7);
                if (two) {
                    mma16816(&acc[tau][0],  e0, e1, e2, e3, b0, b1);
                    mma16816(&acc[tau][4],  e0, e1, e2, e3, b2, b3);
                    mma16816(&acc[tau][8],  e0, e1, e2, e3, b4, b5);
                    mma16816(&acc[tau][12], e0, e1, e2, e3, b6, b7);
                }
            }
            __syncthreads();
        }

        // ---- gates ----
        const bool last = (t == TT - 1);
#pragma unroll
        for (int tau = 0; tau < 4; tau++) {
#pragma unroll
            for (int f = 0; f < 4; f++) {
                const int idx = tau * 4 + f;
                float c0 = acc[tau][4 * f + 0], c1 = acc[tau][4 * f + 1];
                float c2 = acc[tau][4 * f + 2], c3 = acc[tau][4 * f + 3];
                float s0 = __shfl_xor_sync(0xffffffffu, c0, 1);
                float s1 = __shfl_xor_sync(0xffffffffu, c1, 1);
                float s2 = __shfl_xor_sync(0xffffffffu, c2, 1);
                float s3 = __shfl_xor_sync(0xffffffffu, c3, 1);
                float zi = odd ? s2 : c0;
                float zf = odd ? s3 : c1;
                float zg = odd ? c2 : s0;
                float zo = odd ? c3 : s1;
                const int u = (nb >> 2) + 8 * tau + 2 * f + ((lane & 3) >> 1);
                float4 b4 = *(const float4*)(sm + BIAS_OFF + u * 16);
                zi += b4.x; zf += b4.y; zg += b4.z; zo += b4.w;
                float ig = sigmf(zi), fg = sigmf(zf);
                float gg = tanhfast(zg), og = sigmf(zo);
                float nc = fg * cst[idx] + ig * gg;
                cst[idx] = nc;
                float h = og * tanhfast(nc);
                const int m = mb + rbase;
                if (last) {
                    g_h[(size_t)(mbase + m) * HH + u] = h;
                } else {
                    __nv_bfloat16 hh = __float2bfloat16(h);
                    __nv_bfloat16 hl = __float2bfloat16(h - __bfloat162float(hh));
                    *(__nv_bfloat16*)(sm + AHI_OFF + (m * PA + u) * 2) = hh;
                    *(__nv_bfloat16*)(sm + ALO_OFF + (m * PA + u) * 2) = hl;
                }
            }
        }

        if (!last) {
            // stage x(t+1)
            const float* xp = x + (size_t)(mbase + xr) * (TT * FF) + (t + 1) * FF + xf;
            float4 v = __ldg((const float4*)xp);
            float vv[4] = {v.x, v.y, v.z, v.w};
            __nv_bfloat16 h0 = __float2bfloat16(vv[0]), h1 = __float2bfloat16(vv[1]);
            __nv_bfloat16 h2 = __float2bfloat16(vv[2]), h3 = __float2bfloat16(vv[3]);
            uint32_t h01 = (uint32_t)__bfloat16_as_ushort(h0) | ((uint32_t)__bfloat16_as_ushort(h1) << 16);
            uint32_t h23 = (uint32_t)__bfloat16_as_ushort(h2) | ((uint32_t)__bfloat16_as_ushort(h3) << 16);
            uint32_t l01 = bfbits(vv[0] - __bfloat162float(h0)) | (bfbits(vv[1] - __bfloat162float(h1)) << 16);
            uint32_t l23 = bfbits(vv[2] - __bfloat162float(h2)) | (bfbits(vv[3] - __bfloat162float(h3)) << 16);
            *(uint2*)(sm + XHI_OFF + (xr * PX + xf) * 2) = make_uint2(h01, h23);
            *(uint2*)(sm + XLO_OFF + (xr * PX + xf) * 2) = make_uint2(l01, l23);
        }
        // visibility: first __syncthreads inside next step's chunk loop
    }
}

// ------------------------- GCN + MLP ----------------------------------------
__global__ void k_xw(const float* __restrict__ gW) {
    __shared__ float hsm[16][HH];
    const int tid = threadIdx.x;
    const int rowbase = blockIdx.x * 16;
#pragma unroll
    for (int r = 0; r < 16; r++) {
        int idx = tid + r * 128;
        hsm[idx >> 7][idx & 127] = g_h[(size_t)rowbase * HH + idx];
    }
    __syncthreads();
    float acc[16];
#pragma unroll
    for (int r = 0; r < 16; r++) acc[r] = 0.f;
#pragma unroll 4
    for (int k = 0; k < HH; k++) {
        float wv = __ldg(&gW[k * GHD + tid]);
#pragma unroll
        for (int r = 0; r < 16; r++) acc[r] += hsm[r][k] * wv;
    }
#pragma unroll
    for (int r = 0; r < 16; r++)
        g_xw[(size_t)(rowbase + r) * GHD + tid] = acc[r];
}

__global__ void k_agg_zero() {
    size_t i = (size_t)blockIdx.x * blockDim.x + threadIdx.x;
    if (i < (size_t)BQ * NN * GHD) g_agg[i] = 0.f;
}

__global__ void k_scatter(const int* __restrict__ ei) {
    const int e = blockIdx.x, ch = threadIdx.x;
    int s, d; float wv;
    if (e < EE) { s = ei[e]; d = ei[EE + e]; wv = g_norm[e]; }
    else { s = d = e - EE; float di = g_dinv[s]; wv = di * di; }
#pragma unroll
    for (int b = 0; b < BQ; b++) {
        float v = g_xw[((size_t)b * NN + s) * GHD + ch] * wv;
        atomicAdd(&g_agg[((size_t)b * NN + d) * GHD + ch], v);
    }
}

__global__ void k_mlp(const float* __restrict__ gb, const float* __restrict__ W1,
                      const float* __restrict__ b1, const float* __restrict__ W2,
                      const float* __restrict__ b2, float* __restrict__ out) {
    __shared__ float in_s[GHD];
    __shared__ float red[64];
    const int m = blockIdx.x, ch = threadIdx.x;
    in_s[ch] = g_agg[(size_t)m * GHD + ch] + __ldg(&gb[ch]);
    __syncthreads();
    if (ch < 64) {
        float s = __ldg(&b1[ch]);
#pragma unroll 8
        for (int k = 0; k < GHD; k++) s += in_s[k] * __ldg(&W1[k * 64 + ch]);
        float h1 = s * sigmf(s);
        red[ch] = h1 * __ldg(&W2[ch]);
    }
    __syncthreads();
    if (ch == 0) {
        float s = __ldg(&b2[0]);
#pragma unroll
        for (int j = 0; j < 64; j++) s += red[j];
        out[m] = s;
    }
}

// ------------------------- launch --------------------------------------------
extern "C" void kernel_launch(void* const* d_in, const int* in_sizes, int n_in,
                              void* d_out, int out_size) {
    const float* x   = (const float*)d_in[0];
    const int*   ei  = (const int*)d_in[1];
    const float* Wih = (const float*)d_in[2];
    const float* Whh = (const float*)d_in[3];
    const float* bih = (const float*)d_in[4];
    const float* bhh = (const float*)d_in[5];
    const float* gW  = (const float*)d_in[6];
    const float* gb  = (const float*)d_in[7];
    const float* W1  = (const float*)d_in[8];
    const float* b1  = (const float*)d_in[9];
    const float* W2  = (const float*)d_in[10];
    const float* b2  = (const float*)d_in[11];
    float* out = (float*)d_out;

    cudaFuncSetAttribute(k_lstm_mma, cudaFuncAttributeMaxDynamicSharedMemorySize,
                         DYN_BYTES);

    // k_lstm_mma is the 4th launch -> profiler's fixed sampling slot
    k_prep<<<(NN + 255) / 256, 256>>>(bih, bhh);
    k_prep_wb<<<(NCHUNK * 8192 + 255) / 256, 256>>>(Whh, Wih);
    k_deg<<<(EE + 255) / 256, 256>>>(ei);
    k_lstm_mma<<<MM / MROWS, 512, DYN_BYTES>>>(x);
    k_dinv<<<(NN + 255) / 256, 256>>>();
    k_norm<<<(EE + 255) / 256, 256>>>(ei);

    k_xw<<<MM / 16, 128>>>(gW);
    k_agg_zero<<<((size_t)BQ * NN * GHD + 255) / 256, 256>>>();
    k_scatter<<<EE + NN, 128>>>(ei);
    k_mlp<<<MM, 128>>>(gb, W1, b1, W2, b2, out);
}

// round 9
// speedup vs baseline: 1.5691x; 1.1870x over previous
#include <cuda_runtime.h>
#include <cuda_bf16.h>
#include <cstddef>
#include <cstdint>

#define BQ 8
#define NN 2000
#define TT 64
#define FF 32
#define HH 128
#define NG 512
#define EE 32000
#define MM 16000
#define GHD 128

// ---- mma LSTM geometry ----
#define MROWS 64            // rows per CTA
#define NCHUNK 10           // chunks per step (32 k-slices each)
#define CHUNK_BYTES 32768   // gmem: 512 nperm x 32 k x bf16
#define BSLOT 40960         // smem slot: 512 rows x 80B pitch
#define PA 136              // A (h) pitch in bf16 elems
#define PX 72               // x pitch in bf16 elems

// smem layout (bytes)
#define AHI_OFF 0
#define ALO_OFF 17408
#define XHI_OFF 34816
#define XLO_OFF 44032
#define BR_OFF  53248
#define BIAS_OFF (BR_OFF + 3 * BSLOT)     // 176128
#define DYN_BYTES (BIAS_OFF + 2048)       // 178176

// ------------------------- device scratch ----------------------------------
__device__ __align__(16) unsigned short g_Wblob[NCHUNK * 16384];
__device__ __align__(16) float g_bias[NG];
__device__ float g_deg[NN];
__device__ float g_dinv[NN];
__device__ float g_norm[EE];
__device__ __align__(16) float g_h[MM * HH];
__device__ __align__(16) float g_xw[MM * GHD];
__device__ __align__(16) float g_agg[(size_t)BQ * NN * GHD];

// ------------------------- helpers -----------------------------------------
__device__ __forceinline__ float sigmf(float x) {
    return __fdividef(1.f, 1.f + __expf(-x));
}
__device__ __forceinline__ float tanhfast(float x) {
    return __fdividef(2.f, 1.f + __expf(-2.f * x)) - 1.f;
}
__device__ __forceinline__ void cp16(uint32_t dst, const void* src) {
    asm volatile("cp.async.cg.shared.global [%0], [%1], 16;" :: "r"(dst), "l"(src));
}
__device__ __forceinline__ void cp_commit() {
    asm volatile("cp.async.commit_group;" ::: "memory");
}
__device__ __forceinline__ void cp_wait1() {
    asm volatile("cp.async.wait_group 1;" ::: "memory");
}
__device__ __forceinline__ void cp_wait0() {
    asm volatile("cp.async.wait_group 0;" ::: "memory");
}
__device__ __forceinline__ void ldsm4(uint32_t& r0, uint32_t& r1, uint32_t& r2,
                                      uint32_t& r3, uint32_t addr) {
    asm volatile("ldmatrix.sync.aligned.m8n8.x4.shared.b16 {%0,%1,%2,%3}, [%4];"
                 : "=r"(r0), "=r"(r1), "=r"(r2), "=r"(r3) : "r"(addr));
}
__device__ __forceinline__ void mma16816(float* d, uint32_t a0, uint32_t a1,
                                         uint32_t a2, uint32_t a3,
                                         uint32_t b0, uint32_t b1) {
    asm volatile(
        "mma.sync.aligned.m16n8k16.row.col.f32.bf16.bf16.f32 "
        "{%0,%1,%2,%3}, {%4,%5,%6,%7}, {%8,%9}, {%0,%1,%2,%3};"
        : "+f"(d[0]), "+f"(d[1]), "+f"(d[2]), "+f"(d[3])
        : "r"(a0), "r"(a1), "r"(a2), "r"(a3), "r"(b0), "r"(b1));
}
__device__ __forceinline__ uint32_t bfbits(float v) {
    return (uint32_t)__bfloat16_as_ushort(__float2bfloat16(v));
}

// ------------------------- prep kernels -------------------------------------
__global__ void k_prep(const float* __restrict__ bih, const float* __restrict__ bhh) {
    int i = blockIdx.x * blockDim.x + threadIdx.x;
    if (i < NG) g_bias[i] = bih[i] + bhh[i];
    if (i < NN) g_deg[i] = 1.0f;
}

// W blob: 10 chunks x [512 nperm][32 k] bf16. nperm = 4u+g -> n = 128g+u.
// c0-3: hi(Whh) k=32c+kk; c4-7: lo(Whh); c8: hi(Wih); c9: lo(Wih).
__global__ void k_prep_wb(const float* __restrict__ Whh, const float* __restrict__ Wih) {
    int idx = blockIdx.x * blockDim.x + threadIdx.x;
    if (idx >= NCHUNK * 16384) return;
    int c = idx >> 14, rem = idx & 16383;
    int np = rem >> 5, kk = rem & 31;
    int u = np >> 2, g = np & 3;
    int n = g * HH + u;
    float v; bool lo;
    if (c < 4)       { v = Whh[n * HH + 32 * c + kk];        lo = false; }
    else if (c < 8)  { v = Whh[n * HH + 32 * (c - 4) + kk];  lo = true;  }
    else if (c == 8) { v = Wih[n * FF + kk];                 lo = false; }
    else             { v = Wih[n * FF + kk];                 lo = true;  }
    __nv_bfloat16 hi = __float2bfloat16(v);
    __nv_bfloat16 out = lo ? __float2bfloat16(v - __bfloat162float(hi)) : hi;
    g_Wblob[c * 16384 + np * 32 + kk] = __bfloat16_as_ushort(out);
}

__global__ void k_deg(const int* __restrict__ ei) {
    int e = blockIdx.x * blockDim.x + threadIdx.x;
    if (e < EE) atomicAdd(&g_deg[ei[EE + e]], 1.0f);
}
__global__ void k_dinv() {
    int n = blockIdx.x * blockDim.x + threadIdx.x;
    if (n < NN) g_dinv[n] = rsqrtf(g_deg[n]);
}
__global__ void k_norm(const int* __restrict__ ei) {
    int e = blockIdx.x * blockDim.x + threadIdx.x;
    if (e < EE) g_norm[e] = g_dinv[ei[e]] * g_dinv[ei[EE + e]];
}

// ------------------------- mma.sync LSTM ------------------------------------
// 250 CTAs x 512 threads (16 warps), M=64 rows. Warp w: m-block (w&3)*16,
// perm-cols 128*(w>>2). 3-slot cp.async ring, issue distance 1, ONE
// __syncthreads per chunk (overwrite target = slot read 2 iters ago, fenced
// by the previous barrier) + one end-of-step barrier for h-write/ring wrap.
__global__ void __launch_bounds__(512, 1) k_lstm_mma(const float* __restrict__ x) {
    extern __shared__ __align__(16) char sm[];
    const uint32_t sbase = (uint32_t)__cvta_generic_to_shared(sm);
    const int tid = threadIdx.x;
    const int lane = tid & 31;
    const int w = tid >> 5;
    const int mb = 16 * (w & 3);
    const int nb = 128 * (w >> 2);
    const int mbase = blockIdx.x * MROWS;

    // zero A hi/lo (2 x 17408 B)
    {
        uint4 z = make_uint4(0, 0, 0, 0);
        for (int i = tid; i < 2176; i += 512) *(uint4*)(sm + i * 16) = z;
    }
    // bias as float4 per unit (i,f,g,o)
    if (tid < HH) {
        float4 b4 = make_float4(g_bias[tid], g_bias[HH + tid],
                                g_bias[2 * HH + tid], g_bias[3 * HH + tid]);
        *(float4*)(sm + BIAS_OFF + tid * 16) = b4;
    }
    // stage x(0): thread -> row tid/8, feats 4*(tid%8)..+3
    const int xr = tid >> 3, xf = (tid & 7) * 4;
    {
        const float* xp = x + (size_t)(mbase + xr) * (TT * FF) + xf;
        float4 v = __ldg((const float4*)xp);
        __nv_bfloat16 h0 = __float2bfloat16(v.x), h1 = __float2bfloat16(v.y);
        __nv_bfloat16 h2 = __float2bfloat16(v.z), h3 = __float2bfloat16(v.w);
        uint32_t h01 = (uint32_t)__bfloat16_as_ushort(h0) | ((uint32_t)__bfloat16_as_ushort(h1) << 16);
        uint32_t h23 = (uint32_t)__bfloat16_as_ushort(h2) | ((uint32_t)__bfloat16_as_ushort(h3) << 16);
        uint32_t l01 = bfbits(v.x - __bfloat162float(h0)) | (bfbits(v.y - __bfloat162float(h1)) << 16);
        uint32_t l23 = bfbits(v.z - __bfloat162float(h2)) | (bfbits(v.w - __bfloat162float(h3)) << 16);
        *(uint2*)(sm + XHI_OFF + (xr * PX + xf) * 2) = make_uint2(h01, h23);
        *(uint2*)(sm + XLO_OFF + (xr * PX + xf) * 2) = make_uint2(l01, l23);
    }

    // per-lane ldmatrix address pieces (same mapping as R8, proven correct)
    const uint32_t a_row = mb + (lane & 7) + (((lane >> 3) & 1) << 3);
    const uint32_t a_kh = (lane & 16) ? 8 : 0;
    const uint32_t aoff_hi = sbase + AHI_OFF + (a_row * PA + a_kh) * 2;
    const uint32_t aoff_lo = sbase + ALO_OFF + (a_row * PA + a_kh) * 2;
    const uint32_t xoff_hi = sbase + XHI_OFF + (a_row * PX + a_kh) * 2;
    const uint32_t xoff_lo = sbase + XLO_OFF + (a_row * PX + a_kh) * 2;
    const uint32_t b_row = (lane & 7) + ((lane & 16) ? 8 : 0);
    const uint32_t b_kh = ((lane >> 3) & 1) * 16;
    const uint32_t boff = sbase + BR_OFF + (nb + b_row) * 80 + b_kh;

    float cst[16];
#pragma unroll
    for (int i = 0; i < 16; i++) cst[i] = 0.f;

    const bool odd = lane & 1;
    const int rbase = (lane >> 2) + (odd ? 8 : 0);

    __syncthreads();

    for (int t = 0; t < TT; t++) {
        float acc[4][16];
#pragma unroll
        for (int i = 0; i < 4; i++)
#pragma unroll
            for (int j = 0; j < 16; j++) acc[i][j] = 0.f;

        // prologue: stage chunk 0 -> slot 0 (each thread one 64B nperm row)
        {
            const char* src = (const char*)g_Wblob + tid * 64;
            uint32_t dst = sbase + BR_OFF + tid * 80;
            cp16(dst, src); cp16(dst + 16, src + 16);
            cp16(dst + 32, src + 32); cp16(dst + 48, src + 48);
            cp_commit();
        }

        for (int c = 0; c < NCHUNK; c++) {
            if (c < NCHUNK - 1) {
                int nc = c + 1, slot = nc - (nc >= 3 ? 3 : 0) - (nc >= 6 ? 3 : 0) - (nc >= 9 ? 3 : 0);
                const char* src = (const char*)g_Wblob + (size_t)nc * CHUNK_BYTES + tid * 64;
                uint32_t dst = sbase + BR_OFF + slot * BSLOT + tid * 80;
                cp16(dst, src); cp16(dst + 16, src + 16);
                cp16(dst + 32, src + 32); cp16(dst + 48, src + 48);
                cp_commit();
                cp_wait1();
            } else {
                cp_wait0();
            }
            __syncthreads();   // chunk c visible; also fences slot reuse

            int slot = c - (c >= 3 ? 3 : 0) - (c >= 6 ? 3 : 0) - (c >= 9 ? 3 : 0);
            const uint32_t bB = boff + slot * BSLOT;

            uint32_t aad0, aad1 = 0;
            int two;
            if (c < 4)       { aad0 = aoff_hi + 64 * c;       aad1 = aoff_lo + 64 * c; two = 1; }
            else if (c < 8)  { aad0 = aoff_hi + 64 * (c - 4); two = 0; }
            else if (c == 8) { aad0 = xoff_hi; aad1 = xoff_lo; two = 1; }
            else             { aad0 = xoff_hi; two = 0; }

#pragma unroll
            for (int g2 = 0; g2 < 2; g2++) {
                uint32_t a0, a1, a2, a3, e0, e1, e2, e3;
                ldsm4(a0, a1, a2, a3, aad0 + 32 * g2);
                if (two) ldsm4(e0, e1, e2, e3, aad1 + 32 * g2);
#pragma unroll
                for (int tau = 0; tau < 4; tau++) {
                    uint32_t bt = bB + 32 * g2 + tau * (32 * 80);
                    uint32_t b0, b1, b2, b3, b4, b5, b6, b7;
                    ldsm4(b0, b1, b2, b3, bt);
                    ldsm4(b4, b5, b6, b7, bt + 16 * 80);
                    mma16816(&acc[tau][0],  a0, a1, a2, a3, b0, b1);
                    mma16816(&acc[tau][4],  a0, a1, a2, a3, b2, b3);
                    mma16816(&acc[tau][8],  a0, a1, a2, a3, b4, b5);
                    mma16816(&acc[tau][12], a0, a1, a2, a3, b6, b7);
                    if (two) {
                        mma16816(&acc[tau][0],  e0, e1, e2, e3, b0, b1);
                        mma16816(&acc[tau][4],  e0, e1, e2, e3, b2, b3);
                        mma16816(&acc[tau][8],  e0, e1, e2, e3, b4, b5);
                        mma16816(&acc[tau][12], e0, e1, e2, e3, b6, b7);
                    }
                }
            }
        }

        // ---- gates (identical to R8, proven mapping) ----
        const bool last = (t == TT - 1);
#pragma unroll
        for (int tau = 0; tau < 4; tau++) {
#pragma unroll
            for (int f = 0; f < 4; f++) {
                const int idx = tau * 4 + f;
                float c0 = acc[tau][4 * f + 0], c1 = acc[tau][4 * f + 1];
                float c2 = acc[tau][4 * f + 2], c3 = acc[tau][4 * f + 3];
                float s0 = __shfl_xor_sync(0xffffffffu, c0, 1);
                float s1 = __shfl_xor_sync(0xffffffffu, c1, 1);
                float s2 = __shfl_xor_sync(0xffffffffu, c2, 1);
                float s3 = __shfl_xor_sync(0xffffffffu, c3, 1);
                float zi = odd ? s2 : c0;
                float zf = odd ? s3 : c1;
                float zg = odd ? c2 : s0;
                float zo = odd ? c3 : s1;
                const int u = (nb >> 2) + 8 * tau + 2 * f + ((lane & 3) >> 1);
                float4 b4 = *(const float4*)(sm + BIAS_OFF + u * 16);
                zi += b4.x; zf += b4.y; zg += b4.z; zo += b4.w;
                float ig = sigmf(zi), fg = sigmf(zf);
                float gg = tanhfast(zg), og = sigmf(zo);
                float nc = fg * cst[idx] + ig * gg;
                cst[idx] = nc;
                float h = og * tanhfast(nc);
                const int m = mb + rbase;
                if (last) {
                    g_h[(size_t)(mbase + m) * HH + u] = h;
                } else {
                    __nv_bfloat16 hh = __float2bfloat16(h);
                    __nv_bfloat16 hl = __float2bfloat16(h - __bfloat162float(hh));
                    *(__nv_bfloat16*)(sm + AHI_OFF + (m * PA + u) * 2) = hh;
                    *(__nv_bfloat16*)(sm + ALO_OFF + (m * PA + u) * 2) = hl;
                }
            }
        }

        if (!last) {
            // stage x(t+1)
            const float* xp = x + (size_t)(mbase + xr) * (TT * FF) + (t + 1) * FF + xf;
            float4 v = __ldg((const float4*)xp);
            __nv_bfloat16 h0 = __float2bfloat16(v.x), h1 = __float2bfloat16(v.y);
            __nv_bfloat16 h2 = __float2bfloat16(v.z), h3 = __float2bfloat16(v.w);
            uint32_t h01 = (uint32_t)__bfloat16_as_ushort(h0) | ((uint32_t)__bfloat16_as_ushort(h1) << 16);
            uint32_t h23 = (uint32_t)__bfloat16_as_ushort(h2) | ((uint32_t)__bfloat16_as_ushort(h3) << 16);
            uint32_t l01 = bfbits(v.x - __bfloat162float(h0)) | (bfbits(v.y - __bfloat162float(h1)) << 16);
            uint32_t l23 = bfbits(v.z - __bfloat162float(h2)) | (bfbits(v.w - __bfloat162float(h3)) << 16);
            *(uint2*)(sm + XHI_OFF + (xr * PX + xf) * 2) = make_uint2(h01, h23);
            *(uint2*)(sm + XLO_OFF + (xr * PX + xf) * 2) = make_uint2(l01, l23);
        }
        __syncthreads();   // h/x visible; ring wrap safe for next step
    }
}

// ------------------------- GCN + MLP ----------------------------------------
__global__ void k_xw(const float* __restrict__ gW) {
    __shared__ float hsm[16][HH];
    const int tid = threadIdx.x;
    const int rowbase = blockIdx.x * 16;
#pragma unroll
    for (int r = 0; r < 16; r++) {
        int idx = tid + r * 128;
        hsm[idx >> 7][idx & 127] = g_h[(size_t)rowbase * HH + idx];
    }
    __syncthreads();
    float acc[16];
#pragma unroll
    for (int r = 0; r < 16; r++) acc[r] = 0.f;
#pragma unroll 4
    for (int k = 0; k < HH; k++) {
        float wv = __ldg(&gW[k * GHD + tid]);
#pragma unroll
        for (int r = 0; r < 16; r++) acc[r] += hsm[r][k] * wv;
    }
#pragma unroll
    for (int r = 0; r < 16; r++)
        g_xw[(size_t)(rowbase + r) * GHD + tid] = acc[r];
}

__global__ void k_agg_zero() {
    size_t i = (size_t)blockIdx.x * blockDim.x + threadIdx.x;
    if (i < (size_t)BQ * NN * GHD) g_agg[i] = 0.f;
}

__global__ void k_scatter(const int* __restrict__ ei) {
    const int e = blockIdx.x, ch = threadIdx.x;
    int s, d; float wv;
    if (e < EE) { s = ei[e]; d = ei[EE + e]; wv = g_norm[e]; }
    else { s = d = e - EE; float di = g_dinv[s]; wv = di * di; }
#pragma unroll
    for (int b = 0; b < BQ; b++) {
        float v = g_xw[((size_t)b * NN + s) * GHD + ch] * wv;
        atomicAdd(&g_agg[((size_t)b * NN + d) * GHD + ch], v);
    }
}

__global__ void k_mlp(const float* __restrict__ gb, const float* __restrict__ W1,
                      const float* __restrict__ b1, const float* __restrict__ W2,
                      const float* __restrict__ b2, float* __restrict__ out) {
    __shared__ float in_s[GHD];
    __shared__ float red[64];
    const int m = blockIdx.x, ch = threadIdx.x;
    in_s[ch] = g_agg[(size_t)m * GHD + ch] + __ldg(&gb[ch]);
    __syncthreads();
    if (ch < 64) {
        float s = __ldg(&b1[ch]);
#pragma unroll 8
        for (int k = 0; k < GHD; k++) s += in_s[k] * __ldg(&W1[k * 64 + ch]);
        float h1 = s * sigmf(s);
        red[ch] = h1 * __ldg(&W2[ch]);
    }
    __syncthreads();
    if (ch == 0) {
        float s = __ldg(&b2[0]);
#pragma unroll
        for (int j = 0; j < 64; j++) s += red[j];
        out[m] = s;
    }
}

// ------------------------- launch --------------------------------------------
extern "C" void kernel_launch(void* const* d_in, const int* in_sizes, int n_in,
                              void* d_out, int out_size) {
    const float* x   = (const float*)d_in[0];
    const int*   ei  = (const int*)d_in[1];
    const float* Wih = (const float*)d_in[2];
    const float* Whh = (const float*)d_in[3];
    const float* bih = (const float*)d_in[4];
    const float* bhh = (const float*)d_in[5];
    const float* gW  = (const float*)d_in[6];
    const float* gb  = (const float*)d_in[7];
    const float* W1  = (const float*)d_in[8];
    const float* b1  = (const float*)d_in[9];
    const float* W2  = (const float*)d_in[10];
    const float* b2  = (const float*)d_in[11];
    float* out = (float*)d_out;

    cudaFuncSetAttribute(k_lstm_mma, cudaFuncAttributeMaxDynamicSharedMemorySize,
                         DYN_BYTES);

    // k_lstm_mma is the 4th launch -> profiler's fixed sampling slot
    k_prep<<<(NN + 255) / 256, 256>>>(bih, bhh);
    k_prep_wb<<<(NCHUNK * 16384 + 255) / 256, 256>>>(Whh, Wih);
    k_deg<<<(EE + 255) / 256, 256>>>(ei);
    k_lstm_mma<<<MM / MROWS, 512, DYN_BYTES>>>(x);
    k_dinv<<<(NN + 255) / 256, 256>>>();
    k_norm<<<(EE + 255) / 256, 256>>>(ei);

    k_xw<<<MM / 16, 128>>>(gW);
    k_agg_zero<<<((size_t)BQ * NN * GHD + 255) / 256, 256>>>();
    k_scatter<<<EE + NN, 128>>>(ei);
    k_mlp<<<MM, 128>>>(gb, W1, b1, W2, b2, out);
}

// round 10
// speedup vs baseline: 1.9965x; 1.2724x over previous
#include <cuda_runtime.h>
#include <cuda_bf16.h>
#include <cstddef>
#include <cstdint>

#define BQ 8
#define NN 2000
#define TT 64
#define FF 32
#define HH 128
#define NG 512
#define EE 32000
#define MM 16000
#define GHD 128

// ---- mma LSTM geometry ----
#define MROWS 64            // rows per CTA
#define NCHUNK 6            // 64KB W chunks per step (c5 half-used)
#define CHUNK_BYTES 65536
#define PA 136              // A (h) pitch in bf16 elems
#define PX 72               // x pitch in bf16 elems

// smem layout (bytes)
#define AHI_OFF 0
#define ALO_OFF 17408
#define XHI_OFF 34816
#define XLO_OFF 44032
#define BR_OFF  53248                      // 2 x 65536 ring
#define BIAS_OFF (BR_OFF + 2 * CHUNK_BYTES)  // 184320
#define MBAR_OFF (BIAS_OFF + 2048)           // 186368
#define DYN_BYTES (MBAR_OFF + 128)           // 186496

// ------------------------- device scratch ----------------------------------
__device__ __align__(16) unsigned short g_Wblob[NCHUNK * 32768];
__device__ __align__(16) float g_bias[NG];
__device__ float g_deg[NN];
__device__ float g_dinv[NN];
__device__ float g_norm[EE];
__device__ __align__(16) float g_h[MM * HH];
__device__ __align__(16) float g_xw[MM * GHD];
__device__ __align__(16) float g_agg[(size_t)BQ * NN * GHD];

// ------------------------- helpers -----------------------------------------
__device__ __forceinline__ float sigmf(float x) {
    return __fdividef(1.f, 1.f + __expf(-x));
}
__device__ __forceinline__ float tanhfast(float x) {
    return __fdividef(2.f, 1.f + __expf(-2.f * x)) - 1.f;
}
__device__ __forceinline__ void ldsm4(uint32_t& r0, uint32_t& r1, uint32_t& r2,
                                      uint32_t& r3, uint32_t addr) {
    asm volatile("ldmatrix.sync.aligned.m8n8.x4.shared.b16 {%0,%1,%2,%3}, [%4];"
                 : "=r"(r0), "=r"(r1), "=r"(r2), "=r"(r3) : "r"(addr));
}
__device__ __forceinline__ void mma16816(float* d, uint32_t a0, uint32_t a1,
                                         uint32_t a2, uint32_t a3,
                                         uint32_t b0, uint32_t b1) {
    asm volatile(
        "mma.sync.aligned.m16n8k16.row.col.f32.bf16.bf16.f32 "
        "{%0,%1,%2,%3}, {%4,%5,%6,%7}, {%8,%9}, {%0,%1,%2,%3};"
        : "+f"(d[0]), "+f"(d[1]), "+f"(d[2]), "+f"(d[3])
        : "r"(a0), "r"(a1), "r"(a2), "r"(a3), "r"(b0), "r"(b1));
}
__device__ __forceinline__ uint32_t bfbits(float v) {
    return (uint32_t)__bfloat16_as_ushort(__float2bfloat16(v));
}
__device__ __forceinline__ void mb_init(uint32_t a, uint32_t c) {
    asm volatile("mbarrier.init.shared.b64 [%0], %1;" :: "r"(a), "r"(c) : "memory");
}
__device__ __forceinline__ void mb_expect(uint32_t a, uint32_t bytes) {
    asm volatile("mbarrier.arrive.expect_tx.shared.b64 _, [%0], %1;"
                 :: "r"(a), "r"(bytes) : "memory");
}
__device__ __forceinline__ void mb_wait(uint32_t a, uint32_t parity) {
    asm volatile(
        "{\n\t.reg .pred P1;\n\t"
        "W0_%=:\n\t"
        "mbarrier.try_wait.parity.acquire.cta.shared::cta.b64 P1, [%0], %1, 0x989680;\n\t"
        "@P1 bra.uni W1_%=;\n\t"
        "bra.uni W0_%=;\n\t"
        "W1_%=:\n\t}" :: "r"(a), "r"(parity) : "memory");
}
__device__ __forceinline__ void bulk_cp(uint32_t dst, const void* src,
                                        uint32_t bytes, uint32_t mbar) {
    asm volatile("cp.async.bulk.shared::cta.global.mbarrier::complete_tx::bytes "
                 "[%0], [%1], %2, [%3];"
                 :: "r"(dst), "l"(src), "r"(bytes), "r"(mbar) : "memory");
}

// ------------------------- prep kernels -------------------------------------
__global__ void k_prep(const float* __restrict__ bih, const float* __restrict__ bhh) {
    int i = blockIdx.x * blockDim.x + threadIdx.x;
    if (i < NG) g_bias[i] = bih[i] + bhh[i];
    if (i < NN) g_deg[i] = 1.0f;
}

// W blob: 6 chunks x [512 nperm][64 k] bf16, SW128 row-swizzled (granule
// g -> g ^ (np&7)). nperm = 4u+g -> n = 128g+u.
// c0: hi(Whh) k0-63; c1: hi(Whh) k64-127; c2/c3: lo(Whh);
// c4: kk<32 hi(Wih[kk]) else hi(Wih[kk-32]); c5: kk<32 lo(Wih[kk]) else 0.
__global__ void k_prep_wb(const float* __restrict__ Whh, const float* __restrict__ Wih) {
    int idx = blockIdx.x * blockDim.x + threadIdx.x;
    if (idx >= NCHUNK * 32768) return;
    int c = idx >> 15, e = idx & 32767;
    int np = e >> 6, kk = e & 63;
    int u = np >> 2, g = np & 3;
    int n = g * HH + u;
    float v = 0.f; bool lo = false; bool zero = false;
    if (c == 0)      { v = Whh[n * HH + kk]; }
    else if (c == 1) { v = Whh[n * HH + 64 + kk]; }
    else if (c == 2) { v = Whh[n * HH + kk];      lo = true; }
    else if (c == 3) { v = Whh[n * HH + 64 + kk]; lo = true; }
    else if (c == 4) { v = Wih[n * FF + (kk & 31)]; }
    else             { if (kk < 32) { v = Wih[n * FF + kk]; lo = true; } else zero = true; }
    unsigned short out;
    if (zero) out = 0;
    else {
        __nv_bfloat16 hi = __float2bfloat16(v);
        out = __bfloat16_as_ushort(lo ? __float2bfloat16(v - __bfloat162float(hi)) : hi);
    }
    // swizzled position: row np, byte = ((gnl ^ (np&7))<<4) + (kk&7)*2
    int gnl = kk >> 3;
    uint32_t boff = (uint32_t)c * CHUNK_BYTES + (uint32_t)np * 128 +
                    (uint32_t)((gnl ^ (np & 7)) << 4) + (uint32_t)((kk & 7) * 2);
    *(unsigned short*)((char*)g_Wblob + boff) = out;
}

__global__ void k_deg(const int* __restrict__ ei) {
    int e = blockIdx.x * blockDim.x + threadIdx.x;
    if (e < EE) atomicAdd(&g_deg[ei[EE + e]], 1.0f);
}
__global__ void k_dinv() {
    int n = blockIdx.x * blockDim.x + threadIdx.x;
    if (n < NN) g_dinv[n] = rsqrtf(g_deg[n]);
}
__global__ void k_norm(const int* __restrict__ ei) {
    int e = blockIdx.x * blockDim.x + threadIdx.x;
    if (e < EE) g_norm[e] = g_dinv[ei[e]] * g_dinv[ei[EE + e]];
}

// ------------------------- mma.sync LSTM ------------------------------------
// 250 CTAs x 512 threads (16 warps). Warp w: m-block (w&3)*16, n-cols
// 128*(w>>2). W streamed as 6 x 64KB bulk copies per step into a 2-slot
// ring (mbarrier complete_tx); 1 __syncthreads per chunk fences slot reuse.
__global__ void __launch_bounds__(512, 1) k_lstm_mma(const float* __restrict__ x) {
    extern __shared__ __align__(16) char sm[];
    const uint32_t sbase = (uint32_t)__cvta_generic_to_shared(sm);
    const int tid = threadIdx.x;
    const int lane = tid & 31;
    const int w = tid >> 5;
    const int mb = 16 * (w & 3);
    const int nb = 128 * (w >> 2);
    const int mbase = blockIdx.x * MROWS;
    const uint32_t mbarF0 = sbase + MBAR_OFF;       // full[0]
    const uint32_t mbarF1 = sbase + MBAR_OFF + 8;   // full[1]

    if (tid == 0) { mb_init(mbarF0, 1); mb_init(mbarF1, 1); }

    // zero A hi/lo
    {
        uint4 z = make_uint4(0, 0, 0, 0);
        for (int i = tid; i < 2176; i += 512) *(uint4*)(sm + i * 16) = z;
    }
    // bias as float4 per unit (i,f,g,o)
    if (tid < HH) {
        float4 b4 = make_float4(g_bias[tid], g_bias[HH + tid],
                                g_bias[2 * HH + tid], g_bias[3 * HH + tid]);
        *(float4*)(sm + BIAS_OFF + tid * 16) = b4;
    }
    // stage x(0)
    const int xr = tid >> 3, xf = (tid & 7) * 4;
    {
        const float* xp = x + (size_t)(mbase + xr) * (TT * FF) + xf;
        float4 v = __ldg((const float4*)xp);
        __nv_bfloat16 h0 = __float2bfloat16(v.x), h1 = __float2bfloat16(v.y);
        __nv_bfloat16 h2 = __float2bfloat16(v.z), h3 = __float2bfloat16(v.w);
        uint32_t h01 = (uint32_t)__bfloat16_as_ushort(h0) | ((uint32_t)__bfloat16_as_ushort(h1) << 16);
        uint32_t h23 = (uint32_t)__bfloat16_as_ushort(h2) | ((uint32_t)__bfloat16_as_ushort(h3) << 16);
        uint32_t l01 = bfbits(v.x - __bfloat162float(h0)) | (bfbits(v.y - __bfloat162float(h1)) << 16);
        uint32_t l23 = bfbits(v.z - __bfloat162float(h2)) | (bfbits(v.w - __bfloat162float(h3)) << 16);
        *(uint2*)(sm + XHI_OFF + (xr * PX + xf) * 2) = make_uint2(h01, h23);
        *(uint2*)(sm + XLO_OFF + (xr * PX + xf) * 2) = make_uint2(l01, l23);
    }

    // per-lane ldmatrix address pieces (A side identical to R8/R9)
    const uint32_t a_row = mb + (lane & 7) + (((lane >> 3) & 1) << 3);
    const uint32_t a_kh = (lane & 16) ? 8 : 0;
    const uint32_t aoff_hi = sbase + AHI_OFF + (a_row * PA + a_kh) * 2;
    const uint32_t aoff_lo = sbase + ALO_OFF + (a_row * PA + a_kh) * 2;
    const uint32_t xoff_hi = sbase + XHI_OFF + (a_row * PX + a_kh) * 2;
    const uint32_t xoff_lo = sbase + XLO_OFF + (a_row * PX + a_kh) * 2;
    // B side: row = nb + b_row + 32*tau + 16*h, 128B pitch, swizzled granules
    const uint32_t b_row = (lane & 7) + ((lane & 16) ? 8 : 0);
    const uint32_t kh = (lane >> 3) & 1;          // k-half within 32B group
    const uint32_t rx = lane & 7;                 // swizzle key
    const uint32_t bbase = sbase + BR_OFF + (nb + b_row) * 128;

    float cst[16];
#pragma unroll
    for (int i = 0; i < 16; i++) cst[i] = 0.f;

    const bool odd = lane & 1;
    const int rbase = (lane >> 2) + (odd ? 8 : 0);

    __syncthreads();
    // prologue: copy chunk 0 -> slot 0
    if (tid == 0) {
        mb_expect(mbarF0, CHUNK_BYTES);
        bulk_cp(sbase + BR_OFF, (const char*)g_Wblob, CHUNK_BYTES, mbarF0);
    }

    int ph0 = 0, ph1 = 0;

    for (int t = 0; t < TT; t++) {
        float acc[4][16];
#pragma unroll
        for (int i = 0; i < 4; i++)
#pragma unroll
            for (int j = 0; j < 16; j++) acc[i][j] = 0.f;

        for (int c = 0; c < NCHUNK; c++) {
            const int C = t * NCHUNK + c;
            __syncthreads();   // all warps done with chunk C-1 (slot (C+1)&1)

            if (tid == 0 && C + 1 < TT * NCHUNK) {
                int nc = (c + 1) % NCHUNK;
                uint32_t s = (C + 1) & 1;
                uint32_t mb2 = s ? mbarF1 : mbarF0;
                mb_expect(mb2, CHUNK_BYTES);
                bulk_cp(sbase + BR_OFF + s * CHUNK_BYTES,
                        (const char*)g_Wblob + (size_t)nc * CHUNK_BYTES,
                        CHUNK_BYTES, mb2);
            }
            // wait for chunk C's data
            if (C & 1) { mb_wait(mbarF1, ph1); ph1 ^= 1; }
            else       { mb_wait(mbarF0, ph0); ph0 ^= 1; }

            const uint32_t slotB = bbase + (uint32_t)(C & 1) * CHUNK_BYTES;
            const int ng2 = (c == 5) ? 2 : 4;
            const int two = (c < 2);

#pragma unroll 4
            for (int g2 = 0; g2 < ng2; g2++) {
                uint32_t aa;
                if (c < 2)       aa = aoff_hi + 128 * c + 32 * g2;
                else if (c < 4)  aa = aoff_hi + 128 * (c - 2) + 32 * g2;
                else if (c == 4) aa = (g2 < 2) ? (xoff_hi + 32 * g2)
                                               : (xoff_lo + 32 * (g2 - 2));
                else             aa = xoff_hi + 32 * g2;

                uint32_t a0, a1, a2, a3, e0, e1, e2, e3;
                ldsm4(a0, a1, a2, a3, aa);
                if (two) ldsm4(e0, e1, e2, e3, aoff_lo + 128 * c + 32 * g2);

                const uint32_t gx = (((uint32_t)(2 * g2) + kh) ^ rx) << 4;
#pragma unroll
                for (int tau = 0; tau < 4; tau++) {
                    uint32_t bt = slotB + tau * 4096 + gx;
                    uint32_t b0, b1, b2, b3, b4, b5, b6, b7;
                    ldsm4(b0, b1, b2, b3, bt);
                    ldsm4(b4, b5, b6, b7, bt + 2048);
                    mma16816(&acc[tau][0],  a0, a1, a2, a3, b0, b1);
                    mma16816(&acc[tau][4],  a0, a1, a2, a3, b2, b3);
                    mma16816(&acc[tau][8],  a0, a1, a2, a3, b4, b5);
                    mma16816(&acc[tau][12], a0, a1, a2, a3, b6, b7);
                    if (two) {
                        mma16816(&acc[tau][0],  e0, e1, e2, e3, b0, b1);
                        mma16816(&acc[tau][4],  e0, e1, e2, e3, b2, b3);
                        mma16816(&acc[tau][8],  e0, e1, e2, e3, b4, b5);
                        mma16816(&acc[tau][12], e0, e1, e2, e3, b6, b7);
                    }
                }
            }
        }

        // ---- gates (identical mapping to R8/R9) ----
        const bool last = (t == TT - 1);
#pragma unroll
        for (int tau = 0; tau < 4; tau++) {
#pragma unroll
            for (int f = 0; f < 4; f++) {
                const int idx = tau * 4 + f;
                float c0 = acc[tau][4 * f + 0], c1 = acc[tau][4 * f + 1];
                float c2 = acc[tau][4 * f + 2], c3 = acc[tau][4 * f + 3];
                float s0 = __shfl_xor_sync(0xffffffffu, c0, 1);
                float s1 = __shfl_xor_sync(0xffffffffu, c1, 1);
                float s2 = __shfl_xor_sync(0xffffffffu, c2, 1);
                float s3 = __shfl_xor_sync(0xffffffffu, c3, 1);
                float zi = odd ? s2 : c0;
                float zf = odd ? s3 : c1;
                float zg = odd ? c2 : s0;
                float zo = odd ? c3 : s1;
                const int u = (nb >> 2) + 8 * tau + 2 * f + ((lane & 3) >> 1);
                float4 b4 = *(const float4*)(sm + BIAS_OFF + u * 16);
                zi += b4.x; zf += b4.y; zg += b4.z; zo += b4.w;
                float ig = sigmf(zi), fg = sigmf(zf);
                float gg = tanhfast(zg), og = sigmf(zo);
                float nc = fg * cst[idx] + ig * gg;
                cst[idx] = nc;
                float h = og * tanhfast(nc);
                const int m = mb + rbase;
                if (last) {
                    g_h[(size_t)(mbase + m) * HH + u] = h;
                } else {
                    __nv_bfloat16 hh = __float2bfloat16(h);
                    __nv_bfloat16 hl = __float2bfloat16(h - __bfloat162float(hh));
                    *(__nv_bfloat16*)(sm + AHI_OFF + (m * PA + u) * 2) = hh;
                    *(__nv_bfloat16*)(sm + ALO_OFF + (m * PA + u) * 2) = hl;
                }
            }
        }

        if (!last) {
            const float* xp = x + (size_t)(mbase + xr) * (TT * FF) + (t + 1) * FF + xf;
            float4 v = __ldg((const float4*)xp);
            __nv_bfloat16 h0 = __float2bfloat16(v.x), h1 = __float2bfloat16(v.y);
            __nv_bfloat16 h2 = __float2bfloat16(v.z), h3 = __float2bfloat16(v.w);
            uint32_t h01 = (uint32_t)__bfloat16_as_ushort(h0) | ((uint32_t)__bfloat16_as_ushort(h1) << 16);
            uint32_t h23 = (uint32_t)__bfloat16_as_ushort(h2) | ((uint32_t)__bfloat16_as_ushort(h3) << 16);
            uint32_t l01 = bfbits(v.x - __bfloat162float(h0)) | (bfbits(v.y - __bfloat162float(h1)) << 16);
            uint32_t l23 = bfbits(v.z - __bfloat162float(h2)) | (bfbits(v.w - __bfloat162float(h3)) << 16);
            *(uint2*)(sm + XHI_OFF + (xr * PX + xf) * 2) = make_uint2(h01, h23);
            *(uint2*)(sm + XLO_OFF + (xr * PX + xf) * 2) = make_uint2(l01, l23);
        }
        // h/x writes fenced by the __syncthreads at the top of the next chunk
    }
}

// ------------------------- GCN + MLP ----------------------------------------
__global__ void k_xw(const float* __restrict__ gW) {
    __shared__ float hsm[16][HH];
    const int tid = threadIdx.x;
    const int rowbase = blockIdx.x * 16;
#pragma unroll
    for (int r = 0; r < 16; r++) {
        int idx = tid + r * 128;
        hsm[idx >> 7][idx & 127] = g_h[(size_t)rowbase * HH + idx];
    }
    __syncthreads();
    float acc[16];
#pragma unroll
    for (int r = 0; r < 16; r++) acc[r] = 0.f;
#pragma unroll 4
    for (int k = 0; k < HH; k++) {
        float wv = __ldg(&gW[k * GHD + tid]);
#pragma unroll
        for (int r = 0; r < 16; r++) acc[r] += hsm[r][k] * wv;
    }
#pragma unroll
    for (int r = 0; r < 16; r++)
        g_xw[(size_t)(rowbase + r) * GHD + tid] = acc[r];
}

__global__ void k_agg_zero() {
    size_t i = (size_t)blockIdx.x * blockDim.x + threadIdx.x;
    if (i < (size_t)BQ * NN * GHD) g_agg[i] = 0.f;
}

__global__ void k_scatter(const int* __restrict__ ei) {
    const int e = blockIdx.x, ch = threadIdx.x;
    int s, d; float wv;
    if (e < EE) { s = ei[e]; d = ei[EE + e]; wv = g_norm[e]; }
    else { s = d = e - EE; float di = g_dinv[s]; wv = di * di; }
#pragma unroll
    for (int b = 0; b < BQ; b++) {
        float v = g_xw[((size_t)b * NN + s) * GHD + ch] * wv;
        atomicAdd(&g_agg[((size_t)b * NN + d) * GHD + ch], v);
    }
}

__global__ void k_mlp(const float* __restrict__ gb, const float* __restrict__ W1,
                      const float* __restrict__ b1, const float* __restrict__ W2,
                      const float* __restrict__ b2, float* __restrict__ out) {
    __shared__ float in_s[GHD];
    __shared__ float red[64];
    const int m = blockIdx.x, ch = threadIdx.x;
    in_s[ch] = g_agg[(size_t)m * GHD + ch] + __ldg(&gb[ch]);
    __syncthreads();
    if (ch < 64) {
        float s = __ldg(&b1[ch]);
#pragma unroll 8
        for (int k = 0; k < GHD; k++) s += in_s[k] * __ldg(&W1[k * 64 + ch]);
        float h1 = s * sigmf(s);
        red[ch] = h1 * __ldg(&W2[ch]);
    }
    __syncthreads();
    if (ch == 0) {
        float s = __ldg(&b2[0]);
#pragma unroll
        for (int j = 0; j < 64; j++) s += red[j];
        out[m] = s;
    }
}

// ------------------------- launch --------------------------------------------
extern "C" void kernel_launch(void* const* d_in, const int* in_sizes, int n_in,
                              void* d_out, int out_size) {
    const float* x   = (const float*)d_in[0];
    const int*   ei  = (const int*)d_in[1];
    const float* Wih = (const float*)d_in[2];
    const float* Whh = (const float*)d_in[3];
    const float* bih = (const float*)d_in[4];
    const float* bhh = (const float*)d_in[5];
    const float* gW  = (const float*)d_in[6];
    const float* gb  = (const float*)d_in[7];
    const float* W1  = (const float*)d_in[8];
    const float* b1  = (const float*)d_in[9];
    const float* W2  = (const float*)d_in[10];
    const float* b2  = (const float*)d_in[11];
    float* out = (float*)d_out;

    cudaFuncSetAttribute(k_lstm_mma, cudaFuncAttributeMaxDynamicSharedMemorySize,
                         DYN_BYTES);

    // k_lstm_mma is the 4th launch -> profiler's fixed sampling slot
    k_prep<<<(NN + 255) / 256, 256>>>(bih, bhh);
    k_prep_wb<<<(NCHUNK * 32768 + 255) / 256, 256>>>(Whh, Wih);
    k_deg<<<(EE + 255) / 256, 256>>>(ei);
    k_lstm_mma<<<MM / MROWS, 512, DYN_BYTES>>>(x);
    k_dinv<<<(NN + 255) / 256, 256>>>();
    k_norm<<<(EE + 255) / 256, 256>>>(ei);

    k_xw<<<MM / 16, 128>>>(gW);
    k_agg_zero<<<((size_t)BQ * NN * GHD + 255) / 256, 256>>>();
    k_scatter<<<EE + NN, 128>>>(ei);
    k_mlp<<<MM, 128>>>(gb, W1, b1, W2, b2, out);
}

// round 11
// speedup vs baseline: 3.2991x; 1.6524x over previous
#include <cuda_runtime.h>
#include <cuda_bf16.h>
#include <cstddef>
#include <cstdint>

#define BQ 8
#define NN 2000
#define TT 64
#define FF 32
#define HH 128
#define NG 512
#define EE 32000
#define MM 16000
#define GHD 128

// ---- mma LSTM geometry ----
#define MROWS 64            // rows per CTA
#define NCHUNK 3            // 64KB W chunks per step (W in bf16-hi only)
#define CHUNK_BYTES 65536
#define PA 136              // A (h) pitch in bf16 elems
#define PX 72               // x pitch in bf16 elems

// smem layout (bytes)
#define AHI_OFF 0
#define ALO_OFF 17408
#define XHI_OFF 34816
#define XLO_OFF 44032
#define BR_OFF  53248                      // 2 x 65536 ring
#define BIAS_OFF (BR_OFF + 2 * CHUNK_BYTES)  // 184320
#define MBAR_OFF (BIAS_OFF + 2048)           // 186368
#define DYN_BYTES (MBAR_OFF + 128)           // 186496

// ------------------------- device scratch ----------------------------------
__device__ __align__(16) unsigned short g_Wblob[NCHUNK * 32768];
__device__ __align__(16) float g_bias[NG];
__device__ float g_deg[NN];
__device__ float g_dinv[NN];
__device__ float g_norm[EE];
__device__ __align__(16) float g_h[MM * HH];
__device__ __align__(16) float g_xw[MM * GHD];
__device__ __align__(16) float g_agg[(size_t)BQ * NN * GHD];

// ------------------------- helpers -----------------------------------------
__device__ __forceinline__ float sigmf(float x) {
    return __fdividef(1.f, 1.f + __expf(-x));
}
__device__ __forceinline__ float tanhfast(float x) {
    return __fdividef(2.f, 1.f + __expf(-2.f * x)) - 1.f;
}
__device__ __forceinline__ void ldsm4(uint32_t& r0, uint32_t& r1, uint32_t& r2,
                                      uint32_t& r3, uint32_t addr) {
    asm volatile("ldmatrix.sync.aligned.m8n8.x4.shared.b16 {%0,%1,%2,%3}, [%4];"
                 : "=r"(r0), "=r"(r1), "=r"(r2), "=r"(r3) : "r"(addr));
}
__device__ __forceinline__ void mma16816(float* d, uint32_t a0, uint32_t a1,
                                         uint32_t a2, uint32_t a3,
                                         uint32_t b0, uint32_t b1) {
    asm volatile(
        "mma.sync.aligned.m16n8k16.row.col.f32.bf16.bf16.f32 "
        "{%0,%1,%2,%3}, {%4,%5,%6,%7}, {%8,%9}, {%0,%1,%2,%3};"
        : "+f"(d[0]), "+f"(d[1]), "+f"(d[2]), "+f"(d[3])
        : "r"(a0), "r"(a1), "r"(a2), "r"(a3), "r"(b0), "r"(b1));
}
__device__ __forceinline__ uint32_t bfbits(float v) {
    return (uint32_t)__bfloat16_as_ushort(__float2bfloat16(v));
}
__device__ __forceinline__ void mb_init(uint32_t a, uint32_t c) {
    asm volatile("mbarrier.init.shared.b64 [%0], %1;" :: "r"(a), "r"(c) : "memory");
}
__device__ __forceinline__ void mb_expect(uint32_t a, uint32_t bytes) {
    asm volatile("mbarrier.arrive.expect_tx.shared.b64 _, [%0], %1;"
                 :: "r"(a), "r"(bytes) : "memory");
}
__device__ __forceinline__ void mb_wait(uint32_t a, uint32_t parity) {
    asm volatile(
        "{\n\t.reg .pred P1;\n\t"
        "W0_%=:\n\t"
        "mbarrier.try_wait.parity.acquire.cta.shared::cta.b64 P1, [%0], %1, 0x989680;\n\t"
        "@P1 bra.uni W1_%=;\n\t"
        "bra.uni W0_%=;\n\t"
        "W1_%=:\n\t}" :: "r"(a), "r"(parity) : "memory");
}
__device__ __forceinline__ void bulk_cp(uint32_t dst, const void* src,
                                        uint32_t bytes, uint32_t mbar) {
    asm volatile("cp.async.bulk.shared::cta.global.mbarrier::complete_tx::bytes "
                 "[%0], [%1], %2, [%3];"
                 :: "r"(dst), "l"(src), "r"(bytes), "r"(mbar) : "memory");
}

// ------------------------- prep kernels -------------------------------------
__global__ void k_prep(const float* __restrict__ bih, const float* __restrict__ bhh) {
    int i = blockIdx.x * blockDim.x + threadIdx.x;
    if (i < NG) g_bias[i] = bih[i] + bhh[i];
    if (i < NN) g_deg[i] = 1.0f;
}

// W blob: 3 chunks x [512 nperm][64 k] bf16 (hi only), SW128 row-swizzled.
// nperm = 4u+g -> n = 128g+u.
// c0: Whh k0-63; c1: Whh k64-127; c2: Wih[kk&31] duplicated halves.
__global__ void k_prep_wb(const float* __restrict__ Whh, const float* __restrict__ Wih) {
    int idx = blockIdx.x * blockDim.x + threadIdx.x;
    if (idx >= NCHUNK * 32768) return;
    int c = idx >> 15, e = idx & 32767;
    int np = e >> 6, kk = e & 63;
    int u = np >> 2, g = np & 3;
    int n = g * HH + u;
    float v;
    if (c == 0)      v = Whh[n * HH + kk];
    else if (c == 1) v = Whh[n * HH + 64 + kk];
    else             v = Wih[n * FF + (kk & 31)];
    unsigned short out = __bfloat16_as_ushort(__float2bfloat16(v));
    int gnl = kk >> 3;
    uint32_t boff = (uint32_t)c * CHUNK_BYTES + (uint32_t)np * 128 +
                    (uint32_t)((gnl ^ (np & 7)) << 4) + (uint32_t)((kk & 7) * 2);
    *(unsigned short*)((char*)g_Wblob + boff) = out;
}

__global__ void k_deg(const int* __restrict__ ei) {
    int e = blockIdx.x * blockDim.x + threadIdx.x;
    if (e < EE) atomicAdd(&g_deg[ei[EE + e]], 1.0f);
}
__global__ void k_dinv() {
    int n = blockIdx.x * blockDim.x + threadIdx.x;
    if (n < NN) g_dinv[n] = rsqrtf(g_deg[n]);
}
__global__ void k_norm(const int* __restrict__ ei) {
    int e = blockIdx.x * blockDim.x + threadIdx.x;
    if (e < EE) g_norm[e] = g_dinv[ei[e]] * g_dinv[ei[EE + e]];
}

// ------------------------- mma.sync LSTM ------------------------------------
// 250 CTAs x 512 threads (16 warps). Warp w: m-block (w&3)*16, n-cols
// 128*(w>>2). W (bf16-hi) streamed as 3 x 64KB bulk copies per step into a
// 2-slot ring; h/x keep hi+lo split (A-side 2-term, W 1-term).
__global__ void __launch_bounds__(512, 1) k_lstm_mma(const float* __restrict__ x) {
    extern __shared__ __align__(16) char sm[];
    const uint32_t sbase = (uint32_t)__cvta_generic_to_shared(sm);
    const int tid = threadIdx.x;
    const int lane = tid & 31;
    const int w = tid >> 5;
    const int mb = 16 * (w & 3);
    const int nb = 128 * (w >> 2);
    const int mbase = blockIdx.x * MROWS;
    const uint32_t mbarF0 = sbase + MBAR_OFF;
    const uint32_t mbarF1 = sbase + MBAR_OFF + 8;

    if (tid == 0) { mb_init(mbarF0, 1); mb_init(mbarF1, 1); }

    // zero A hi/lo
    {
        uint4 z = make_uint4(0, 0, 0, 0);
        for (int i = tid; i < 2176; i += 512) *(uint4*)(sm + i * 16) = z;
    }
    // bias as float4 per unit (i,f,g,o)
    if (tid < HH) {
        float4 b4 = make_float4(g_bias[tid], g_bias[HH + tid],
                                g_bias[2 * HH + tid], g_bias[3 * HH + tid]);
        *(float4*)(sm + BIAS_OFF + tid * 16) = b4;
    }
    // stage x(0)
    const int xr = tid >> 3, xf = (tid & 7) * 4;
    {
        const float* xp = x + (size_t)(mbase + xr) * (TT * FF) + xf;
        float4 v = __ldg((const float4*)xp);
        __nv_bfloat16 h0 = __float2bfloat16(v.x), h1 = __float2bfloat16(v.y);
        __nv_bfloat16 h2 = __float2bfloat16(v.z), h3 = __float2bfloat16(v.w);
        uint32_t h01 = (uint32_t)__bfloat16_as_ushort(h0) | ((uint32_t)__bfloat16_as_ushort(h1) << 16);
        uint32_t h23 = (uint32_t)__bfloat16_as_ushort(h2) | ((uint32_t)__bfloat16_as_ushort(h3) << 16);
        uint32_t l01 = bfbits(v.x - __bfloat162float(h0)) | (bfbits(v.y - __bfloat162float(h1)) << 16);
        uint32_t l23 = bfbits(v.z - __bfloat162float(h2)) | (bfbits(v.w - __bfloat162float(h3)) << 16);
        *(uint2*)(sm + XHI_OFF + (xr * PX + xf) * 2) = make_uint2(h01, h23);
        *(uint2*)(sm + XLO_OFF + (xr * PX + xf) * 2) = make_uint2(l01, l23);
    }

    // per-lane ldmatrix address pieces
    const uint32_t a_row = mb + (lane & 7) + (((lane >> 3) & 1) << 3);
    const uint32_t a_kh = (lane & 16) ? 8 : 0;
    const uint32_t aoff_hi = sbase + AHI_OFF + (a_row * PA + a_kh) * 2;
    const uint32_t aoff_lo = sbase + ALO_OFF + (a_row * PA + a_kh) * 2;
    const uint32_t xoff_hi = sbase + XHI_OFF + (a_row * PX + a_kh) * 2;
    const uint32_t xoff_lo = sbase + XLO_OFF + (a_row * PX + a_kh) * 2;
    const uint32_t b_row = (lane & 7) + ((lane & 16) ? 8 : 0);
    const uint32_t kh = (lane >> 3) & 1;
    const uint32_t rx = lane & 7;
    const uint32_t bbase = sbase + BR_OFF + (nb + b_row) * 128;

    float cst[16];
#pragma unroll
    for (int i = 0; i < 16; i++) cst[i] = 0.f;

    const bool odd = lane & 1;
    const int rbase = (lane >> 2) + (odd ? 8 : 0);

    __syncthreads();
    if (tid == 0) {
        mb_expect(mbarF0, CHUNK_BYTES);
        bulk_cp(sbase + BR_OFF, (const char*)g_Wblob, CHUNK_BYTES, mbarF0);
    }

    int ph0 = 0, ph1 = 0;

    for (int t = 0; t < TT; t++) {
        float acc[4][16];
#pragma unroll
        for (int i = 0; i < 4; i++)
#pragma unroll
            for (int j = 0; j < 16; j++) acc[i][j] = 0.f;

#pragma unroll
        for (int c = 0; c < NCHUNK; c++) {
            const int C = t * NCHUNK + c;
            __syncthreads();   // all warps done with chunk C-1

            if (tid == 0 && C + 1 < TT * NCHUNK) {
                int nc = (c + 1) % NCHUNK;
                uint32_t s = (C + 1) & 1;
                uint32_t mb2 = s ? mbarF1 : mbarF0;
                mb_expect(mb2, CHUNK_BYTES);
                bulk_cp(sbase + BR_OFF + s * CHUNK_BYTES,
                        (const char*)g_Wblob + (size_t)nc * CHUNK_BYTES,
                        CHUNK_BYTES, mb2);
            }
            if (C & 1) { mb_wait(mbarF1, ph1); ph1 ^= 1; }
            else       { mb_wait(mbarF0, ph0); ph0 ^= 1; }

            const uint32_t slotB = bbase + (uint32_t)(C & 1) * CHUNK_BYTES;
            const int two = (c < 2);

#pragma unroll
            for (int g2 = 0; g2 < 4; g2++) {
                uint32_t aa;
                if (c < 2)  aa = aoff_hi + 128 * c + 32 * g2;
                else        aa = (g2 < 2) ? (xoff_hi + 32 * g2)
                                          : (xoff_lo + 32 * (g2 - 2));

                uint32_t a0, a1, a2, a3, e0, e1, e2, e3;
                ldsm4(a0, a1, a2, a3, aa);
                if (two) ldsm4(e0, e1, e2, e3, aoff_lo + 128 * c + 32 * g2);

                const uint32_t gx = (((uint32_t)(2 * g2) + kh) ^ rx) << 4;
#pragma unroll
                for (int tau = 0; tau < 4; tau++) {
                    uint32_t bt = slotB + tau * 4096 + gx;
                    uint32_t b0, b1, b2, b3, b4, b5, b6, b7;
                    ldsm4(b0, b1, b2, b3, bt);
                    ldsm4(b4, b5, b6, b7, bt + 2048);
                    mma16816(&acc[tau][0],  a0, a1, a2, a3, b0, b1);
                    mma16816(&acc[tau][4],  a0, a1, a2, a3, b2, b3);
                    mma16816(&acc[tau][8],  a0, a1, a2, a3, b4, b5);
                    mma16816(&acc[tau][12], a0, a1, a2, a3, b6, b7);
                    if (two) {
                        mma16816(&acc[tau][0],  e0, e1, e2, e3, b0, b1);
                        mma16816(&acc[tau][4],  e0, e1, e2, e3, b2, b3);
                        mma16816(&acc[tau][8],  e0, e1, e2, e3, b4, b5);
                        mma16816(&acc[tau][12], e0, e1, e2, e3, b6, b7);
                    }
                }
            }
        }

        // ---- gates ----
        const bool last = (t == TT - 1);
#pragma unroll
        for (int tau = 0; tau < 4; tau++) {
#pragma unroll
            for (int f = 0; f < 4; f++) {
                const int idx = tau * 4 + f;
                float c0 = acc[tau][4 * f + 0], c1 = acc[tau][4 * f + 1];
                float c2 = acc[tau][4 * f + 2], c3 = acc[tau][4 * f + 3];
                float s0 = __shfl_xor_sync(0xffffffffu, c0, 1);
                float s1 = __shfl_xor_sync(0xffffffffu, c1, 1);
                float s2 = __shfl_xor_sync(0xffffffffu, c2, 1);
                float s3 = __shfl_xor_sync(0xffffffffu, c3, 1);
                float zi = odd ? s2 : c0;
                float zf = odd ? s3 : c1;
                float zg = odd ? c2 : s0;
                float zo = odd ? c3 : s1;
                const int u = (nb >> 2) + 8 * tau + 2 * f + ((lane & 3) >> 1);
                float4 b4 = *(const float4*)(sm + BIAS_OFF + u * 16);
                zi += b4.x; zf += b4.y; zg += b4.z; zo += b4.w;
                float ig = sigmf(zi), fg = sigmf(zf);
                float gg = tanhfast(zg), og = sigmf(zo);
                float nc = fg * cst[idx] + ig * gg;
                cst[idx] = nc;
                float h = og * tanhfast(nc);
                const int m = mb + rbase;
                if (last) {
                    g_h[(size_t)(mbase + m) * HH + u] = h;
                } else {
                    __nv_bfloat16 hh = __float2bfloat16(h);
                    __nv_bfloat16 hl = __float2bfloat16(h - __bfloat162float(hh));
                    *(__nv_bfloat16*)(sm + AHI_OFF + (m * PA + u) * 2) = hh;
                    *(__nv_bfloat16*)(sm + ALO_OFF + (m * PA + u) * 2) = hl;
                }
            }
        }

        if (!last) {
            const float* xp = x + (size_t)(mbase + xr) * (TT * FF) + (t + 1) * FF + xf;
            float4 v = __ldg((const float4*)xp);
            __nv_bfloat16 h0 = __float2bfloat16(v.x), h1 = __float2bfloat16(v.y);
            __nv_bfloat16 h2 = __float2bfloat16(v.z), h3 = __float2bfloat16(v.w);
            uint32_t h01 = (uint32_t)__bfloat16_as_ushort(h0) | ((uint32_t)__bfloat16_as_ushort(h1) << 16);
            uint32_t h23 = (uint32_t)__bfloat16_as_ushort(h2) | ((uint32_t)__bfloat16_as_ushort(h3) << 16);
            uint32_t l01 = bfbits(v.x - __bfloat162float(h0)) | (bfbits(v.y - __bfloat162float(h1)) << 16);
            uint32_t l23 = bfbits(v.z - __bfloat162float(h2)) | (bfbits(v.w - __bfloat162float(h3)) << 16);
            *(uint2*)(sm + XHI_OFF + (xr * PX + xf) * 2) = make_uint2(h01, h23);
            *(uint2*)(sm + XLO_OFF + (xr * PX + xf) * 2) = make_uint2(l01, l23);
        }
        // h/x writes fenced by the __syncthreads at the top of the next chunk
    }
}

// ------------------------- GCN + MLP ----------------------------------------
__global__ void k_xw(const float* __restrict__ gW) {
    __shared__ float hsm[16][HH];
    const int tid = threadIdx.x;
    const int rowbase = blockIdx.x * 16;
#pragma unroll
    for (int r = 0; r < 16; r++) {
        int idx = tid + r * 128;
        hsm[idx >> 7][idx & 127] = g_h[(size_t)rowbase * HH + idx];
    }
    __syncthreads();
    float acc[16];
#pragma unroll
    for (int r = 0; r < 16; r++) acc[r] = 0.f;
#pragma unroll 4
    for (int k = 0; k < HH; k++) {
        float wv = __ldg(&gW[k * GHD + tid]);
#pragma unroll
        for (int r = 0; r < 16; r++) acc[r] += hsm[r][k] * wv;
    }
#pragma unroll
    for (int r = 0; r < 16; r++)
        g_xw[(size_t)(rowbase + r) * GHD + tid] = acc[r];
}

__global__ void k_agg_zero() {
    size_t i = (size_t)blockIdx.x * blockDim.x + threadIdx.x;
    if (i < (size_t)BQ * NN * GHD) g_agg[i] = 0.f;
}

__global__ void k_scatter(const int* __restrict__ ei) {
    const int e = blockIdx.x, ch = threadIdx.x;
    int s, d; float wv;
    if (e < EE) { s = ei[e]; d = ei[EE + e]; wv = g_norm[e]; }
    else { s = d = e - EE; float di = g_dinv[s]; wv = di * di; }
#pragma unroll
    for (int b = 0; b < BQ; b++) {
        float v = g_xw[((size_t)b * NN + s) * GHD + ch] * wv;
        atomicAdd(&g_agg[((size_t)b * NN + d) * GHD + ch], v);
    }
}

__global__ void k_mlp(const float* __restrict__ gb, const float* __restrict__ W1,
                      const float* __restrict__ b1, const float* __restrict__ W2,
                      const float* __restrict__ b2, float* __restrict__ out) {
    __shared__ float in_s[GHD];
    __shared__ float red[64];
    const int m = blockIdx.x, ch = threadIdx.x;
    in_s[ch] = g_agg[(size_t)m * GHD + ch] + __ldg(&gb[ch]);
    __syncthreads();
    if (ch < 64) {
        float s = __ldg(&b1[ch]);
#pragma unroll 8
        for (int k = 0; k < GHD; k++) s += in_s[k] * __ldg(&W1[k * 64 + ch]);
        float h1 = s * sigmf(s);
        red[ch] = h1 * __ldg(&W2[ch]);
    }
    __syncthreads();
    if (ch == 0) {
        float s = __ldg(&b2[0]);
#pragma unroll
        for (int j = 0; j < 64; j++) s += red[j];
        out[m] = s;
    }
}

// ------------------------- launch --------------------------------------------
extern "C" void kernel_launch(void* const* d_in, const int* in_sizes, int n_in,
                              void* d_out, int out_size) {
    const float* x   = (const float*)d_in[0];
    const int*   ei  = (const int*)d_in[1];
    const float* Wih = (const float*)d_in[2];
    const float* Whh = (const float*)d_in[3];
    const float* bih = (const float*)d_in[4];
    const float* bhh = (const float*)d_in[5];
    const float* gW  = (const float*)d_in[6];
    const float* gb  = (const float*)d_in[7];
    const float* W1  = (const float*)d_in[8];
    const float* b1  = (const float*)d_in[9];
    const float* W2  = (const float*)d_in[10];
    const float* b2  = (const float*)d_in[11];
    float* out = (float*)d_out;

    cudaFuncSetAttribute(k_lstm_mma, cudaFuncAttributeMaxDynamicSharedMemorySize,
                         DYN_BYTES);

    // k_lstm_mma is the 4th launch -> profiler's fixed sampling slot
    k_prep<<<(NN + 255) / 256, 256>>>(bih, bhh);
    k_prep_wb<<<(NCHUNK * 32768 + 255) / 256, 256>>>(Whh, Wih);
    k_deg<<<(EE + 255) / 256, 256>>>(ei);
    k_lstm_mma<<<MM / MROWS, 512, DYN_BYTES>>>(x);
    k_dinv<<<(NN + 255) / 256, 256>>>();
    k_norm<<<(EE + 255) / 256, 256>>>(ei);

    k_xw<<<MM / 16, 128>>>(gW);
    k_agg_zero<<<((size_t)BQ * NN * GHD + 255) / 256, 256>>>();
    k_scatter<<<EE + NN, 128>>>(ei);
    k_mlp<<<MM, 128>>>(gb, W1, b1, W2, b2, out);
}

// round 12
// speedup vs baseline: 3.4641x; 1.0500x over previous
#include <cuda_runtime.h>
#include <cuda_bf16.h>
#include <cstddef>
#include <cstdint>

#define BQ 8
#define NN 2000
#define TT 64
#define FF 32
#define HH 128
#define NG 512
#define EE 32000
#define MM 16000
#define GHD 128

// ---- mma LSTM geometry ----
#define MROWS 64            // rows per CTA
#define PA 136              // A (h) pitch in bf16 elems
#define PX 72               // x pitch in bf16 elems

// W resident in smem: c0/c1 = Whh-hi [512][64k] @128B pitch (swizzled),
// c2 = Wih-hi [512][32k] @80B pitch (mod-8 conflict-free, unswizzled)
#define W2_OFF 131072
#define W_BYTES 172032      // 65536*2 + 40960

// smem layout (bytes)
#define WR_OFF  0
#define AHI_OFF 172032
#define ALO_OFF 189440
#define XHI_OFF 206848
#define XLO_OFF 216064
#define BIAS_OFF 225280
#define MBAR_OFF 227328
#define DYN_BYTES 227344

// ------------------------- device scratch ----------------------------------
__device__ __align__(16) unsigned short g_Wblob[W_BYTES / 2];
__device__ __align__(16) float g_bias[NG];
__device__ float g_deg[NN];
__device__ float g_dinv[NN];
__device__ float g_norm[EE];
__device__ __align__(16) float g_h[MM * HH];
__device__ __align__(16) float g_xw[MM * GHD];
__device__ __align__(16) float g_agg[(size_t)BQ * NN * GHD];

// ------------------------- helpers -----------------------------------------
__device__ __forceinline__ float sigmf(float x) {
    return __fdividef(1.f, 1.f + __expf(-x));
}
__device__ __forceinline__ float tanhfast(float x) {
    return __fdividef(2.f, 1.f + __expf(-2.f * x)) - 1.f;
}
__device__ __forceinline__ void ldsm4(uint32_t& r0, uint32_t& r1, uint32_t& r2,
                                      uint32_t& r3, uint32_t addr) {
    asm volatile("ldmatrix.sync.aligned.m8n8.x4.shared.b16 {%0,%1,%2,%3}, [%4];"
                 : "=r"(r0), "=r"(r1), "=r"(r2), "=r"(r3) : "r"(addr));
}
__device__ __forceinline__ void mma16816(float* d, uint32_t a0, uint32_t a1,
                                         uint32_t a2, uint32_t a3,
                                         uint32_t b0, uint32_t b1) {
    asm volatile(
        "mma.sync.aligned.m16n8k16.row.col.f32.bf16.bf16.f32 "
        "{%0,%1,%2,%3}, {%4,%5,%6,%7}, {%8,%9}, {%0,%1,%2,%3};"
        : "+f"(d[0]), "+f"(d[1]), "+f"(d[2]), "+f"(d[3])
        : "r"(a0), "r"(a1), "r"(a2), "r"(a3), "r"(b0), "r"(b1));
}
__device__ __forceinline__ uint32_t bfbits(float v) {
    return (uint32_t)__bfloat16_as_ushort(__float2bfloat16(v));
}
__device__ __forceinline__ void mb_init(uint32_t a, uint32_t c) {
    asm volatile("mbarrier.init.shared.b64 [%0], %1;" :: "r"(a), "r"(c) : "memory");
}
__device__ __forceinline__ void mb_expect(uint32_t a, uint32_t bytes) {
    asm volatile("mbarrier.arrive.expect_tx.shared.b64 _, [%0], %1;"
                 :: "r"(a), "r"(bytes) : "memory");
}
__device__ __forceinline__ void mb_wait(uint32_t a, uint32_t parity) {
    asm volatile(
        "{\n\t.reg .pred P1;\n\t"
        "W0_%=:\n\t"
        "mbarrier.try_wait.parity.acquire.cta.shared::cta.b64 P1, [%0], %1, 0x989680;\n\t"
        "@P1 bra.uni W1_%=;\n\t"
        "bra.uni W0_%=;\n\t"
        "W1_%=:\n\t}" :: "r"(a), "r"(parity) : "memory");
}
__device__ __forceinline__ void bulk_cp(uint32_t dst, const void* src,
                                        uint32_t bytes, uint32_t mbar) {
    asm volatile("cp.async.bulk.shared::cta.global.mbarrier::complete_tx::bytes "
                 "[%0], [%1], %2, [%3];"
                 :: "r"(dst), "l"(src), "r"(bytes), "r"(mbar) : "memory");
}

// ------------------------- prep kernels -------------------------------------
__global__ void k_prep(const float* __restrict__ bih, const float* __restrict__ bhh) {
    int i = blockIdx.x * blockDim.x + threadIdx.x;
    if (i < NG) g_bias[i] = bih[i] + bhh[i];
    if (i < NN) g_deg[i] = 1.0f;
}

// W blob: c0/c1 = Whh-hi [512 np][64 k] bf16, 128B pitch, SW128 row-swizzle.
// c2 = Wih-hi [512 np][32 k] bf16, 80B pitch, no swizzle (mod-8 free).
// nperm = 4u+g -> n = 128g+u.
__global__ void k_prep_wb(const float* __restrict__ Whh, const float* __restrict__ Wih) {
    int idx = blockIdx.x * blockDim.x + threadIdx.x;
    // c0/c1: 2*32768 elems
    if (idx < 65536) {
        int c = idx >> 15, e = idx & 32767;
        int np = e >> 6, kk = e & 63;
        int u = np >> 2, g = np & 3;
        int n = g * HH + u;
        float v = Whh[n * HH + 64 * c + kk];
        int gnl = kk >> 3;
        uint32_t boff = (uint32_t)c * 65536 + (uint32_t)np * 128 +
                        (uint32_t)((gnl ^ (np & 7)) << 4) + (uint32_t)((kk & 7) * 2);
        *(unsigned short*)((char*)g_Wblob + boff) =
            __bfloat16_as_ushort(__float2bfloat16(v));
    } else if (idx < 65536 + 16384) {
        int e = idx - 65536;
        int np = e >> 5, kk = e & 31;
        int u = np >> 2, g = np & 3;
        int n = g * HH + u;
        float v = Wih[n * FF + kk];
        uint32_t boff = (uint32_t)W2_OFF + (uint32_t)np * 80 +
                        (uint32_t)((kk >> 3) << 4) + (uint32_t)((kk & 7) * 2);
        *(unsigned short*)((char*)g_Wblob + boff) =
            __bfloat16_as_ushort(__float2bfloat16(v));
    }
}

__global__ void k_deg(const int* __restrict__ ei) {
    int e = blockIdx.x * blockDim.x + threadIdx.x;
    if (e < EE) atomicAdd(&g_deg[ei[EE + e]], 1.0f);
}
__global__ void k_dinv() {
    int n = blockIdx.x * blockDim.x + threadIdx.x;
    if (n < NN) g_dinv[n] = rsqrtf(g_deg[n]);
}
__global__ void k_norm(const int* __restrict__ ei) {
    int e = blockIdx.x * blockDim.x + threadIdx.x;
    if (e < EE) g_norm[e] = g_dinv[ei[e]] * g_dinv[ei[EE + e]];
}

// ------------------------- mma.sync LSTM ------------------------------------
// 250 CTAs x 512 threads (16 warps). Warp w: m-block (w&3)*16, n-cols
// 128*(w>>2). W (bf16-hi, 168KB) loaded ONCE into smem; per step:
// GEMM (resident W) -> barrier -> gates/epilogue -> barrier. No copies.
__global__ void __launch_bounds__(512, 1) k_lstm_mma(const float* __restrict__ x) {
    extern __shared__ __align__(16) char sm[];
    const uint32_t sbase = (uint32_t)__cvta_generic_to_shared(sm);
    const int tid = threadIdx.x;
    const int lane = tid & 31;
    const int w = tid >> 5;
    const int mb = 16 * (w & 3);
    const int nb = 128 * (w >> 2);
    const int mbase = blockIdx.x * MROWS;
    const uint32_t mbarF0 = sbase + MBAR_OFF;

    if (tid == 0) mb_init(mbarF0, 1);

    // zero A hi/lo
    {
        uint4 z = make_uint4(0, 0, 0, 0);
        for (int i = tid; i < 2176; i += 512)
            *(uint4*)(sm + AHI_OFF + i * 16) = z;
    }
    // bias as float4 per unit (i,f,g,o)
    if (tid < HH) {
        float4 b4 = make_float4(g_bias[tid], g_bias[HH + tid],
                                g_bias[2 * HH + tid], g_bias[3 * HH + tid]);
        *(float4*)(sm + BIAS_OFF + tid * 16) = b4;
    }
    // stage x(0)
    const int xr = tid >> 3, xf = (tid & 7) * 4;
    {
        const float* xp = x + (size_t)(mbase + xr) * (TT * FF) + xf;
        float4 v = __ldg((const float4*)xp);
        __nv_bfloat16 h0 = __float2bfloat16(v.x), h1 = __float2bfloat16(v.y);
        __nv_bfloat16 h2 = __float2bfloat16(v.z), h3 = __float2bfloat16(v.w);
        uint32_t h01 = (uint32_t)__bfloat16_as_ushort(h0) | ((uint32_t)__bfloat16_as_ushort(h1) << 16);
        uint32_t h23 = (uint32_t)__bfloat16_as_ushort(h2) | ((uint32_t)__bfloat16_as_ushort(h3) << 16);
        uint32_t l01 = bfbits(v.x - __bfloat162float(h0)) | (bfbits(v.y - __bfloat162float(h1)) << 16);
        uint32_t l23 = bfbits(v.z - __bfloat162float(h2)) | (bfbits(v.w - __bfloat162float(h3)) << 16);
        *(uint2*)(sm + XHI_OFF + (xr * PX + xf) * 2) = make_uint2(h01, h23);
        *(uint2*)(sm + XLO_OFF + (xr * PX + xf) * 2) = make_uint2(l01, l23);
    }
    __syncthreads();   // mbar init + A zeroing visible
    if (tid == 0) {
        mb_expect(mbarF0, W_BYTES);
        bulk_cp(sbase + WR_OFF, (const char*)g_Wblob, W_BYTES, mbarF0);
    }

    // per-lane ldmatrix address pieces
    const uint32_t a_row = mb + (lane & 7) + (((lane >> 3) & 1) << 3);
    const uint32_t a_kh = (lane & 16) ? 8 : 0;
    const uint32_t aoff_hi = sbase + AHI_OFF + (a_row * PA + a_kh) * 2;
    const uint32_t aoff_lo = sbase + ALO_OFF + (a_row * PA + a_kh) * 2;
    const uint32_t xoff_hi = sbase + XHI_OFF + (a_row * PX + a_kh) * 2;
    const uint32_t xoff_lo = sbase + XLO_OFF + (a_row * PX + a_kh) * 2;
    const uint32_t b_row = (lane & 7) + ((lane & 16) ? 8 : 0);
    const uint32_t kh = (lane >> 3) & 1;
    const uint32_t rx = lane & 7;
    const uint32_t bbase = sbase + WR_OFF + (nb + b_row) * 128;   // c0/c1
    const uint32_t b2base = sbase + WR_OFF + W2_OFF + (nb + b_row) * 80;  // c2

    float cst[16];
#pragma unroll
    for (int i = 0; i < 16; i++) cst[i] = 0.f;

    const bool odd = lane & 1;
    const int rbase = (lane >> 2) + (odd ? 8 : 0);

    mb_wait(mbarF0, 0);   // W resident
    __syncthreads();

    for (int t = 0; t < TT; t++) {
        float acc[4][16];
#pragma unroll
        for (int i = 0; i < 4; i++)
#pragma unroll
            for (int j = 0; j < 16; j++) acc[i][j] = 0.f;

        // ---- c0/c1: h(hi+lo) x Whh-hi ----
#pragma unroll
        for (int c = 0; c < 2; c++) {
            const uint32_t slotB = bbase + (uint32_t)c * 65536;
#pragma unroll
            for (int g2 = 0; g2 < 4; g2++) {
                uint32_t a0, a1, a2, a3, e0, e1, e2, e3;
                ldsm4(a0, a1, a2, a3, aoff_hi + 128 * c + 32 * g2);
                ldsm4(e0, e1, e2, e3, aoff_lo + 128 * c + 32 * g2);
                const uint32_t gx = (((uint32_t)(2 * g2) + kh) ^ rx) << 4;
#pragma unroll
                for (int tau = 0; tau < 4; tau++) {
                    uint32_t bt = slotB + tau * 4096 + gx;
                    uint32_t b0, b1, b2, b3, b4, b5, b6, b7;
                    ldsm4(b0, b1, b2, b3, bt);
                    ldsm4(b4, b5, b6, b7, bt + 2048);
                    mma16816(&acc[tau][0],  a0, a1, a2, a3, b0, b1);
                    mma16816(&acc[tau][4],  a0, a1, a2, a3, b2, b3);
                    mma16816(&acc[tau][8],  a0, a1, a2, a3, b4, b5);
                    mma16816(&acc[tau][12], a0, a1, a2, a3, b6, b7);
                    mma16816(&acc[tau][0],  e0, e1, e2, e3, b0, b1);
                    mma16816(&acc[tau][4],  e0, e1, e2, e3, b2, b3);
                    mma16816(&acc[tau][8],  e0, e1, e2, e3, b4, b5);
                    mma16816(&acc[tau][12], e0, e1, e2, e3, b6, b7);
                }
            }
        }
        // ---- c2: x(hi+lo) x Wih-hi, B frags reused for both A terms ----
#pragma unroll
        for (int g2 = 0; g2 < 2; g2++) {
            uint32_t a0, a1, a2, a3, e0, e1, e2, e3;
            ldsm4(a0, a1, a2, a3, xoff_hi + 32 * g2);
            ldsm4(e0, e1, e2, e3, xoff_lo + 32 * g2);
            const uint32_t gx = ((uint32_t)(2 * g2) + kh) << 4;
#pragma unroll
            for (int tau = 0; tau < 4; tau++) {
                uint32_t bt = b2base + tau * 2560 + gx;
                uint32_t b0, b1, b2, b3, b4, b5, b6, b7;
                ldsm4(b0, b1, b2, b3, bt);
                ldsm4(b4, b5, b6, b7, bt + 1280);
                mma16816(&acc[tau][0],  a0, a1, a2, a3, b0, b1);
                mma16816(&acc[tau][4],  a0, a1, a2, a3, b2, b3);
                mma16816(&acc[tau][8],  a0, a1, a2, a3, b4, b5);
                mma16816(&acc[tau][12], a0, a1, a2, a3, b6, b7);
                mma16816(&acc[tau][0],  e0, e1, e2, e3, b0, b1);
                mma16816(&acc[tau][4],  e0, e1, e2, e3, b2, b3);
                mma16816(&acc[tau][8],  e0, e1, e2, e3, b4, b5);
                mma16816(&acc[tau][12], e0, e1, e2, e3, b6, b7);
            }
        }

        __syncthreads();   // all warps finished reading A/X

        // ---- gates ----
        const bool last = (t == TT - 1);
#pragma unroll
        for (int tau = 0; tau < 4; tau++) {
#pragma unroll
            for (int f = 0; f < 4; f++) {
                const int idx = tau * 4 + f;
                float c0 = acc[tau][4 * f + 0], c1 = acc[tau][4 * f + 1];
                float c2 = acc[tau][4 * f + 2], c3 = acc[tau][4 * f + 3];
                float s0 = __shfl_xor_sync(0xffffffffu, c0, 1);
                float s1 = __shfl_xor_sync(0xffffffffu, c1, 1);
                float s2 = __shfl_xor_sync(0xffffffffu, c2, 1);
                float s3 = __shfl_xor_sync(0xffffffffu, c3, 1);
                float zi = odd ? s2 : c0;
                float zf = odd ? s3 : c1;
                float zg = odd ? c2 : s0;
                float zo = odd ? c3 : s1;
                const int u = (nb >> 2) + 8 * tau + 2 * f + ((lane & 3) >> 1);
                float4 b4 = *(const float4*)(sm + BIAS_OFF + u * 16);
                zi += b4.x; zf += b4.y; zg += b4.z; zo += b4.w;
                float ig = sigmf(zi), fg = sigmf(zf);
                float gg = tanhfast(zg), og = sigmf(zo);
                float nc = fg * cst[idx] + ig * gg;
                cst[idx] = nc;
                float h = og * tanhfast(nc);
                const int m = mb + rbase;
                if (last) {
                    g_h[(size_t)(mbase + m) * HH + u] = h;
                } else {
                    __nv_bfloat16 hh = __float2bfloat16(h);
                    __nv_bfloat16 hl = __float2bfloat16(h - __bfloat162float(hh));
                    *(__nv_bfloat16*)(sm + AHI_OFF + (m * PA + u) * 2) = hh;
                    *(__nv_bfloat16*)(sm + ALO_OFF + (m * PA + u) * 2) = hl;
                }
            }
        }

        if (!last) {
            const float* xp = x + (size_t)(mbase + xr) * (TT * FF) + (t + 1) * FF + xf;
            float4 v = __ldg((const float4*)xp);
            __nv_bfloat16 h0 = __float2bfloat16(v.x), h1 = __float2bfloat16(v.y);
            __nv_bfloat16 h2 = __float2bfloat16(v.z), h3 = __float2bfloat16(v.w);
            uint32_t h01 = (uint32_t)__bfloat16_as_ushort(h0) | ((uint32_t)__bfloat16_as_ushort(h1) << 16);
            uint32_t h23 = (uint32_t)__bfloat16_as_ushort(h2) | ((uint32_t)__bfloat16_as_ushort(h3) << 16);
            uint32_t l01 = bfbits(v.x - __bfloat162float(h0)) | (bfbits(v.y - __bfloat162float(h1)) << 16);
            uint32_t l23 = bfbits(v.z - __bfloat162float(h2)) | (bfbits(v.w - __bfloat162float(h3)) << 16);
            *(uint2*)(sm + XHI_OFF + (xr * PX + xf) * 2) = make_uint2(h01, h23);
            *(uint2*)(sm + XLO_OFF + (xr * PX + xf) * 2) = make_uint2(l01, l23);
        }
        __syncthreads();   // h/x writes visible before next GEMM
    }
}

// ------------------------- GCN + MLP ----------------------------------------
__global__ void k_xw(const float* __restrict__ gW) {
    __shared__ float hsm[16][HH];
    const int tid = threadIdx.x;
    const int rowbase = blockIdx.x * 16;
#pragma unroll
    for (int r = 0; r < 16; r++) {
        int idx = tid + r * 128;
        hsm[idx >> 7][idx & 127] = g_h[(size_t)rowbase * HH + idx];
    }
    __syncthreads();
    float acc[16];
#pragma unroll
    for (int r = 0; r < 16; r++) acc[r] = 0.f;
#pragma unroll 4
    for (int k = 0; k < HH; k++) {
        float wv = __ldg(&gW[k * GHD + tid]);
#pragma unroll
        for (int r = 0; r < 16; r++) acc[r] += hsm[r][k] * wv;
    }
#pragma unroll
    for (int r = 0; r < 16; r++)
        g_xw[(size_t)(rowbase + r) * GHD + tid] = acc[r];
}

__global__ void k_agg_zero() {
    size_t i = (size_t)blockIdx.x * blockDim.x + threadIdx.x;
    if (i < (size_t)BQ * NN * GHD) g_agg[i] = 0.f;
}

__global__ void k_scatter(const int* __restrict__ ei) {
    const int e = blockIdx.x, ch = threadIdx.x;
    int s, d; float wv;
    if (e < EE) { s = ei[e]; d = ei[EE + e]; wv = g_norm[e]; }
    else { s = d = e - EE; float di = g_dinv[s]; wv = di * di; }
#pragma unroll
    for (int b = 0; b < BQ; b++) {
        float v = g_xw[((size_t)b * NN + s) * GHD + ch] * wv;
        atomicAdd(&g_agg[((size_t)b * NN + d) * GHD + ch], v);
    }
}

__global__ void k_mlp(const float* __restrict__ gb, const float* __restrict__ W1,
                      const float* __restrict__ b1, const float* __restrict__ W2,
                      const float* __restrict__ b2, float* __restrict__ out) {
    __shared__ float in_s[GHD];
    __shared__ float red[64];
    const int m = blockIdx.x, ch = threadIdx.x;
    in_s[ch] = g_agg[(size_t)m * GHD + ch] + __ldg(&gb[ch]);
    __syncthreads();
    if (ch < 64) {
        float s = __ldg(&b1[ch]);
#pragma unroll 8
        for (int k = 0; k < GHD; k++) s += in_s[k] * __ldg(&W1[k * 64 + ch]);
        float h1 = s * sigmf(s);
        red[ch] = h1 * __ldg(&W2[ch]);
    }
    __syncthreads();
    if (ch == 0) {
        float s = __ldg(&b2[0]);
#pragma unroll
        for (int j = 0; j < 64; j++) s += red[j];
        out[m] = s;
    }
}

// ------------------------- launch --------------------------------------------
extern "C" void kernel_launch(void* const* d_in, const int* in_sizes, int n_in,
                              void* d_out, int out_size) {
    const float* x   = (const float*)d_in[0];
    const int*   ei  = (const int*)d_in[1];
    const float* Wih = (const float*)d_in[2];
    const float* Whh = (const float*)d_in[3];
    const float* bih = (const float*)d_in[4];
    const float* bhh = (const float*)d_in[5];
    const float* gW  = (const float*)d_in[6];
    const float* gb  = (const float*)d_in[7];
    const float* W1  = (const float*)d_in[8];
    const float* b1  = (const float*)d_in[9];
    const float* W2  = (const float*)d_in[10];
    const float* b2  = (const float*)d_in[11];
    float* out = (float*)d_out;

    cudaFuncSetAttribute(k_lstm_mma, cudaFuncAttributeMaxDynamicSharedMemorySize,
                         DYN_BYTES);

    // k_lstm_mma is the 4th launch -> profiler's fixed sampling slot
    k_prep<<<(NN + 255) / 256, 256>>>(bih, bhh);
    k_prep_wb<<<(81920 + 255) / 256, 256>>>(Whh, Wih);
    k_deg<<<(EE + 255) / 256, 256>>>(ei);
    k_lstm_mma<<<MM / MROWS, 512, DYN_BYTES>>>(x);
    k_dinv<<<(NN + 255) / 256, 256>>>();
    k_norm<<<(EE + 255) / 256, 256>>>(ei);

    k_xw<<<MM / 16, 128>>>(gW);
    k_agg_zero<<<((size_t)BQ * NN * GHD + 255) / 256, 256>>>();
    k_scatter<<<EE + NN, 128>>>(ei);
    k_mlp<<<MM, 128>>>(gb, W1, b1, W2, b2, out);
}

// round 13
// speedup vs baseline: 3.8833x; 1.1210x over previous
#include <cuda_runtime.h>
#include <cuda_bf16.h>
#include <cstddef>
#include <cstdint>

#define BQ 8
#define NN 2000
#define TT 64
#define FF 32
#define HH 128
#define NG 512
#define EE 32000
#define MM 16000
#define GHD 128

// ---- mma LSTM geometry ----
#define MROWS 64            // rows per CTA
#define PA 136              // A (h) pitch in bf16 elems
#define PX 72               // x pitch in bf16 elems

// W resident in smem: c0/c1 = Whh-hi [512][64k] @128B pitch (swizzled),
// c2 = Wih-hi [512][32k] @80B pitch (mod-8 conflict-free, unswizzled)
#define W2_OFF 131072
#define W_BYTES 172032      // 65536*2 + 40960

// smem layout (bytes)
#define WR_OFF  0
#define AHI_OFF 172032
#define ALO_OFF 189440
#define XHI_OFF 206848
#define XLO_OFF 216064
#define BIAS_OFF 225280
#define MBAR_OFF 227328
#define DYN_BYTES 227344

// ------------------------- device scratch ----------------------------------
__device__ __align__(16) unsigned short g_Wblob[W_BYTES / 2];
__device__ __align__(16) float g_bias[NG];
__device__ float g_deg[NN];
__device__ float g_dinv[NN];
__device__ float g_norm[EE];
__device__ __align__(16) float g_h[MM * HH];
__device__ __align__(16) float g_xw[MM * GHD];
__device__ __align__(16) float g_agg[(size_t)BQ * NN * GHD];

// ------------------------- helpers -----------------------------------------
__device__ __forceinline__ float tanha(float x) {
    float y;
    asm("tanh.approx.f32 %0, %1;" : "=f"(y) : "f"(x));
    return y;
}
__device__ __forceinline__ float sigma(float x) {   // 0.5 + 0.5*tanh(x/2)
    return fmaf(0.5f, tanha(0.5f * x), 0.5f);
}
__device__ __forceinline__ float sigmf(float x) {   // exact (non-LSTM kernels)
    return __fdividef(1.f, 1.f + __expf(-x));
}
__device__ __forceinline__ void ldsm4(uint32_t& r0, uint32_t& r1, uint32_t& r2,
                                      uint32_t& r3, uint32_t addr) {
    asm volatile("ldmatrix.sync.aligned.m8n8.x4.shared.b16 {%0,%1,%2,%3}, [%4];"
                 : "=r"(r0), "=r"(r1), "=r"(r2), "=r"(r3) : "r"(addr));
}
__device__ __forceinline__ void mma16816(float* d, uint32_t a0, uint32_t a1,
                                         uint32_t a2, uint32_t a3,
                                         uint32_t b0, uint32_t b1) {
    asm volatile(
        "mma.sync.aligned.m16n8k16.row.col.f32.bf16.bf16.f32 "
        "{%0,%1,%2,%3}, {%4,%5,%6,%7}, {%8,%9}, {%0,%1,%2,%3};"
        : "+f"(d[0]), "+f"(d[1]), "+f"(d[2]), "+f"(d[3])
        : "r"(a0), "r"(a1), "r"(a2), "r"(a3), "r"(b0), "r"(b1));
}
__device__ __forceinline__ uint32_t bfbits(float v) {
    return (uint32_t)__bfloat16_as_ushort(__float2bfloat16(v));
}
__device__ __forceinline__ void mb_init(uint32_t a, uint32_t c) {
    asm volatile("mbarrier.init.shared.b64 [%0], %1;" :: "r"(a), "r"(c) : "memory");
}
__device__ __forceinline__ void mb_expect(uint32_t a, uint32_t bytes) {
    asm volatile("mbarrier.arrive.expect_tx.shared.b64 _, [%0], %1;"
                 :: "r"(a), "r"(bytes) : "memory");
}
__device__ __forceinline__ void mb_wait(uint32_t a, uint32_t parity) {
    asm volatile(
        "{\n\t.reg .pred P1;\n\t"
        "W0_%=:\n\t"
        "mbarrier.try_wait.parity.acquire.cta.shared::cta.b64 P1, [%0], %1, 0x989680;\n\t"
        "@P1 bra.uni W1_%=;\n\t"
        "bra.uni W0_%=;\n\t"
        "W1_%=:\n\t}" :: "r"(a), "r"(parity) : "memory");
}
__device__ __forceinline__ void bulk_cp(uint32_t dst, const void* src,
                                        uint32_t bytes, uint32_t mbar) {
    asm volatile("cp.async.bulk.shared::cta.global.mbarrier::complete_tx::bytes "
                 "[%0], [%1], %2, [%3];"
                 :: "r"(dst), "l"(src), "r"(bytes), "r"(mbar) : "memory");
}

// ------------------------- prep kernels -------------------------------------
__global__ void k_prep(const float* __restrict__ bih, const float* __restrict__ bhh) {
    int i = blockIdx.x * blockDim.x + threadIdx.x;
    if (i < NG) g_bias[i] = bih[i] + bhh[i];
    if (i < NN) g_deg[i] = 1.0f;
}

// W blob, shuffle-free gate layout. Column np -> (unit u, gate g):
//   v = np>>4, rem = np&15, half = rem>>3 (0:(i,f) 1:(g,o)),
//   w = (rem>>1)&3, gl = rem&1, g = 2*half+gl, u = 4v+w, n = g*128+u.
// c0/c1 = Whh-hi [512 np][64 k] @128B pitch SW128; c2 = Wih-hi [512][32] @80B.
__global__ void k_prep_wb(const float* __restrict__ Whh, const float* __restrict__ Wih) {
    int idx = blockIdx.x * blockDim.x + threadIdx.x;
    if (idx < 65536) {
        int c = idx >> 15, e = idx & 32767;
        int np = e >> 6, kk = e & 63;
        int v = np >> 4, rem = np & 15;
        int g = 2 * (rem >> 3) + (rem & 1);
        int u = 4 * v + ((rem >> 1) & 3);
        int n = g * HH + u;
        float val = Whh[n * HH + 64 * c + kk];
        int gnl = kk >> 3;
        uint32_t boff = (uint32_t)c * 65536 + (uint32_t)np * 128 +
                        (uint32_t)((gnl ^ (np & 7)) << 4) + (uint32_t)((kk & 7) * 2);
        *(unsigned short*)((char*)g_Wblob + boff) =
            __bfloat16_as_ushort(__float2bfloat16(val));
    } else if (idx < 65536 + 16384) {
        int e = idx - 65536;
        int np = e >> 5, kk = e & 31;
        int v = np >> 4, rem = np & 15;
        int g = 2 * (rem >> 3) + (rem & 1);
        int u = 4 * v + ((rem >> 1) & 3);
        int n = g * HH + u;
        float val = Wih[n * FF + kk];
        uint32_t boff = (uint32_t)W2_OFF + (uint32_t)np * 80 +
                        (uint32_t)((kk >> 3) << 4) + (uint32_t)((kk & 7) * 2);
        *(unsigned short*)((char*)g_Wblob + boff) =
            __bfloat16_as_ushort(__float2bfloat16(val));
    }
}

__global__ void k_deg(const int* __restrict__ ei) {
    int e = blockIdx.x * blockDim.x + threadIdx.x;
    if (e < EE) atomicAdd(&g_deg[ei[EE + e]], 1.0f);
}
__global__ void k_dinv() {
    int n = blockIdx.x * blockDim.x + threadIdx.x;
    if (n < NN) g_dinv[n] = rsqrtf(g_deg[n]);
}
__global__ void k_norm(const int* __restrict__ ei) {
    int e = blockIdx.x * blockDim.x + threadIdx.x;
    if (e < EE) g_norm[e] = g_dinv[ei[e]] * g_dinv[ei[EE + e]];
}

// ------------------------- mma.sync LSTM ------------------------------------
// 250 CTAs x 512 threads (16 warps). W (bf16-hi, 168KB) resident in smem.
// Shuffle-free epilogue: n8 block pairs hold (i,f)/(g,o) per unit, so each
// thread's c-regs contain complete gate sets. tanh.approx gates.
__global__ void __launch_bounds__(512, 1) k_lstm_mma(const float* __restrict__ x) {
    extern __shared__ __align__(16) char sm[];
    const uint32_t sbase = (uint32_t)__cvta_generic_to_shared(sm);
    const int tid = threadIdx.x;
    const int lane = tid & 31;
    const int w = tid >> 5;
    const int mb = 16 * (w & 3);
    const int nb = 128 * (w >> 2);
    const int mbase = blockIdx.x * MROWS;
    const uint32_t mbarF0 = sbase + MBAR_OFF;

    if (tid == 0) mb_init(mbarF0, 1);

    // zero A hi/lo
    {
        uint4 z = make_uint4(0, 0, 0, 0);
        for (int i = tid; i < 2176; i += 512)
            *(uint4*)(sm + AHI_OFF + i * 16) = z;
    }
    // bias as float4 per unit (i,f,g,o)
    if (tid < HH) {
        float4 b4 = make_float4(g_bias[tid], g_bias[HH + tid],
                                g_bias[2 * HH + tid], g_bias[3 * HH + tid]);
        *(float4*)(sm + BIAS_OFF + tid * 16) = b4;
    }
    // stage x(0)
    const int xr = tid >> 3, xf = (tid & 7) * 4;
    {
        const float* xp = x + (size_t)(mbase + xr) * (TT * FF) + xf;
        float4 v = __ldg((const float4*)xp);
        __nv_bfloat16 h0 = __float2bfloat16(v.x), h1 = __float2bfloat16(v.y);
        __nv_bfloat16 h2 = __float2bfloat16(v.z), h3 = __float2bfloat16(v.w);
        uint32_t h01 = (uint32_t)__bfloat16_as_ushort(h0) | ((uint32_t)__bfloat16_as_ushort(h1) << 16);
        uint32_t h23 = (uint32_t)__bfloat16_as_ushort(h2) | ((uint32_t)__bfloat16_as_ushort(h3) << 16);
        uint32_t l01 = bfbits(v.x - __bfloat162float(h0)) | (bfbits(v.y - __bfloat162float(h1)) << 16);
        uint32_t l23 = bfbits(v.z - __bfloat162float(h2)) | (bfbits(v.w - __bfloat162float(h3)) << 16);
        *(uint2*)(sm + XHI_OFF + (xr * PX + xf) * 2) = make_uint2(h01, h23);
        *(uint2*)(sm + XLO_OFF + (xr * PX + xf) * 2) = make_uint2(l01, l23);
    }
    __syncthreads();   // mbar init + A zeroing visible
    if (tid == 0) {
        mb_expect(mbarF0, W_BYTES);
        bulk_cp(sbase + WR_OFF, (const char*)g_Wblob, W_BYTES, mbarF0);
    }

    // per-lane ldmatrix address pieces
    const uint32_t a_row = mb + (lane & 7) + (((lane >> 3) & 1) << 3);
    const uint32_t a_kh = (lane & 16) ? 8 : 0;
    const uint32_t aoff_hi = sbase + AHI_OFF + (a_row * PA + a_kh) * 2;
    const uint32_t aoff_lo = sbase + ALO_OFF + (a_row * PA + a_kh) * 2;
    const uint32_t xoff_hi = sbase + XHI_OFF + (a_row * PX + a_kh) * 2;
    const uint32_t xoff_lo = sbase + XLO_OFF + (a_row * PX + a_kh) * 2;
    const uint32_t b_row = (lane & 7) + ((lane & 16) ? 8 : 0);
    const uint32_t kh = (lane >> 3) & 1;
    const uint32_t rx = lane & 7;
    const uint32_t bbase = sbase + WR_OFF + (nb + b_row) * 128;   // c0/c1
    const uint32_t b2base = sbase + WR_OFF + W2_OFF + (nb + b_row) * 80;  // c2

    float cst[16];
#pragma unroll
    for (int i = 0; i < 16; i++) cst[i] = 0.f;

    const int q2 = lane & 3;
    const int r0 = lane >> 2;

    mb_wait(mbarF0, 0);   // W resident
    __syncthreads();

    for (int t = 0; t < TT; t++) {
        float acc[4][16];
#pragma unroll
        for (int i = 0; i < 4; i++)
#pragma unroll
            for (int j = 0; j < 16; j++) acc[i][j] = 0.f;

        // ---- c0/c1: h(hi+lo) x Whh-hi ----
#pragma unroll
        for (int c = 0; c < 2; c++) {
            const uint32_t slotB = bbase + (uint32_t)c * 65536;
#pragma unroll
            for (int g2 = 0; g2 < 4; g2++) {
                uint32_t a0, a1, a2, a3, e0, e1, e2, e3;
                ldsm4(a0, a1, a2, a3, aoff_hi + 128 * c + 32 * g2);
                ldsm4(e0, e1, e2, e3, aoff_lo + 128 * c + 32 * g2);
                const uint32_t gx = (((uint32_t)(2 * g2) + kh) ^ rx) << 4;
#pragma unroll
                for (int tau = 0; tau < 4; tau++) {
                    uint32_t bt = slotB + tau * 4096 + gx;
                    uint32_t b0, b1, b2, b3, b4, b5, b6, b7;
                    ldsm4(b0, b1, b2, b3, bt);
                    ldsm4(b4, b5, b6, b7, bt + 2048);
                    mma16816(&acc[tau][0],  a0, a1, a2, a3, b0, b1);
                    mma16816(&acc[tau][4],  a0, a1, a2, a3, b2, b3);
                    mma16816(&acc[tau][8],  a0, a1, a2, a3, b4, b5);
                    mma16816(&acc[tau][12], a0, a1, a2, a3, b6, b7);
                    mma16816(&acc[tau][0],  e0, e1, e2, e3, b0, b1);
                    mma16816(&acc[tau][4],  e0, e1, e2, e3, b2, b3);
                    mma16816(&acc[tau][8],  e0, e1, e2, e3, b4, b5);
                    mma16816(&acc[tau][12], e0, e1, e2, e3, b6, b7);
                }
            }
        }
        // ---- c2: x(hi+lo) x Wih-hi ----
#pragma unroll
        for (int g2 = 0; g2 < 2; g2++) {
            uint32_t a0, a1, a2, a3, e0, e1, e2, e3;
            ldsm4(a0, a1, a2, a3, xoff_hi + 32 * g2);
            ldsm4(e0, e1, e2, e3, xoff_lo + 32 * g2);
            const uint32_t gx = ((uint32_t)(2 * g2) + kh) << 4;
#pragma unroll
            for (int tau = 0; tau < 4; tau++) {
                uint32_t bt = b2base + tau * 2560 + gx;
                uint32_t b0, b1, b2, b3, b4, b5, b6, b7;
                ldsm4(b0, b1, b2, b3, bt);
                ldsm4(b4, b5, b6, b7, bt + 1280);
                mma16816(&acc[tau][0],  a0, a1, a2, a3, b0, b1);
                mma16816(&acc[tau][4],  a0, a1, a2, a3, b2, b3);
                mma16816(&acc[tau][8],  a0, a1, a2, a3, b4, b5);
                mma16816(&acc[tau][12], a0, a1, a2, a3, b6, b7);
                mma16816(&acc[tau][0],  e0, e1, e2, e3, b0, b1);
                mma16816(&acc[tau][4],  e0, e1, e2, e3, b2, b3);
                mma16816(&acc[tau][8],  e0, e1, e2, e3, b4, b5);
                mma16816(&acc[tau][12], e0, e1, e2, e3, b6, b7);
            }
        }

        __syncthreads();   // all warps finished reading A/X

        // ---- gates: shuffle-free. Block pair (2fp, 2fp+1) = (i,f)/(g,o)
        // of unit u = nb/4 + 8*tau + 4*fp + q2; rows r0 and r0+8.
        const bool last = (t == TT - 1);
#pragma unroll
        for (int tau = 0; tau < 4; tau++) {
#pragma unroll
            for (int fp = 0; fp < 2; fp++) {
                const int bA = 8 * fp;
                const int u = (nb >> 2) + 8 * tau + 4 * fp + q2;
                float4 b4 = *(const float4*)(sm + BIAS_OFF + u * 16);
                const int idx = (tau * 2 + fp) * 2;
#pragma unroll
                for (int rr = 0; rr < 2; rr++) {
                    float zi = acc[tau][bA + 2 * rr + 0] + b4.x;
                    float zf = acc[tau][bA + 2 * rr + 1] + b4.y;
                    float zg = acc[tau][bA + 4 + 2 * rr + 0] + b4.z;
                    float zo = acc[tau][bA + 4 + 2 * rr + 1] + b4.w;
                    float ig = sigma(zi), fg = sigma(zf);
                    float gg = tanha(zg), og = sigma(zo);
                    float nc = fg * cst[idx + rr] + ig * gg;
                    cst[idx + rr] = nc;
                    float h = og * tanha(nc);
                    const int m = mb + r0 + 8 * rr;
                    if (last) {
                        g_h[(size_t)(mbase + m) * HH + u] = h;
                    } else {
                        __nv_bfloat16 hh = __float2bfloat16(h);
                        __nv_bfloat16 hl = __float2bfloat16(h - __bfloat162float(hh));
                        *(__nv_bfloat16*)(sm + AHI_OFF + (m * PA + u) * 2) = hh;
                        *(__nv_bfloat16*)(sm + ALO_OFF + (m * PA + u) * 2) = hl;
                    }
                }
            }
        }

        if (!last) {
            const float* xp = x + (size_t)(mbase + xr) * (TT * FF) + (t + 1) * FF + xf;
            float4 v = __ldg((const float4*)xp);
            __nv_bfloat16 h0 = __float2bfloat16(v.x), h1 = __float2bfloat16(v.y);
            __nv_bfloat16 h2 = __float2bfloat16(v.z), h3 = __float2bfloat16(v.w);
            uint32_t h01 = (uint32_t)__bfloat16_as_ushort(h0) | ((uint32_t)__bfloat16_as_ushort(h1) << 16);
            uint32_t h23 = (uint32_t)__bfloat16_as_ushort(h2) | ((uint32_t)__bfloat16_as_ushort(h3) << 16);
            uint32_t l01 = bfbits(v.x - __bfloat162float(h0)) | (bfbits(v.y - __bfloat162float(h1)) << 16);
            uint32_t l23 = bfbits(v.z - __bfloat162float(h2)) | (bfbits(v.w - __bfloat162float(h3)) << 16);
            *(uint2*)(sm + XHI_OFF + (xr * PX + xf) * 2) = make_uint2(h01, h23);
            *(uint2*)(sm + XLO_OFF + (xr * PX + xf) * 2) = make_uint2(l01, l23);
        }
        __syncthreads();   // h/x writes visible before next GEMM
    }
}

// ------------------------- GCN + MLP ----------------------------------------
__global__ void k_xw(const float* __restrict__ gW) {
    __shared__ float hsm[16][HH];
    const int tid = threadIdx.x;
    const int rowbase = blockIdx.x * 16;
#pragma unroll
    for (int r = 0; r < 16; r++) {
        int idx = tid + r * 128;
        hsm[idx >> 7][idx & 127] = g_h[(size_t)rowbase * HH + idx];
    }
    __syncthreads();
    float acc[16];
#pragma unroll
    for (int r = 0; r < 16; r++) acc[r] = 0.f;
#pragma unroll 4
    for (int k = 0; k < HH; k++) {
        float wv = __ldg(&gW[k * GHD + tid]);
#pragma unroll
        for (int r = 0; r < 16; r++) acc[r] += hsm[r][k] * wv;
    }
#pragma unroll
    for (int r = 0; r < 16; r++)
        g_xw[(size_t)(rowbase + r) * GHD + tid] = acc[r];
}

__global__ void k_agg_zero() {
    size_t i = (size_t)blockIdx.x * blockDim.x + threadIdx.x;
    if (i < (size_t)BQ * NN * GHD) g_agg[i] = 0.f;
}

__global__ void k_scatter(const int* __restrict__ ei) {
    const int e = blockIdx.x, ch = threadIdx.x;
    int s, d; float wv;
    if (e < EE) { s = ei[e]; d = ei[EE + e]; wv = g_norm[e]; }
    else { s = d = e - EE; float di = g_dinv[s]; wv = di * di; }
#pragma unroll
    for (int b = 0; b < BQ; b++) {
        float v = g_xw[((size_t)b * NN + s) * GHD + ch] * wv;
        atomicAdd(&g_agg[((size_t)b * NN + d) * GHD + ch], v);
    }
}

__global__ void k_mlp(const float* __restrict__ gb, const float* __restrict__ W1,
                      const float* __restrict__ b1, const float* __restrict__ W2,
                      const float* __restrict__ b2, float* __restrict__ out) {
    __shared__ float in_s[GHD];
    __shared__ float red[64];
    const int m = blockIdx.x, ch = threadIdx.x;
    in_s[ch] = g_agg[(size_t)m * GHD + ch] + __ldg(&gb[ch]);
    __syncthreads();
    if (ch < 64) {
        float s = __ldg(&b1[ch]);
#pragma unroll 8
        for (int k = 0; k < GHD; k++) s += in_s[k] * __ldg(&W1[k * 64 + ch]);
        float h1 = s * sigmf(s);
        red[ch] = h1 * __ldg(&W2[ch]);
    }
    __syncthreads();
    if (ch == 0) {
        float s = __ldg(&b2[0]);
#pragma unroll
        for (int j = 0; j < 64; j++) s += red[j];
        out[m] = s;
    }
}

// ------------------------- launch --------------------------------------------
extern "C" void kernel_launch(void* const* d_in, const int* in_sizes, int n_in,
                              void* d_out, int out_size) {
    const float* x   = (const float*)d_in[0];
    const int*   ei  = (const int*)d_in[1];
    const float* Wih = (const float*)d_in[2];
    const float* Whh = (const float*)d_in[3];
    const float* bih = (const float*)d_in[4];
    const float* bhh = (const float*)d_in[5];
    const float* gW  = (const float*)d_in[6];
    const float* gb  = (const float*)d_in[7];
    const float* W1  = (const float*)d_in[8];
    const float* b1  = (const float*)d_in[9];
    const float* W2  = (const float*)d_in[10];
    const float* b2  = (const float*)d_in[11];
    float* out = (float*)d_out;

    cudaFuncSetAttribute(k_lstm_mma, cudaFuncAttributeMaxDynamicSharedMemorySize,
                         DYN_BYTES);

    // k_lstm_mma is the 4th launch -> profiler's fixed sampling slot
    k_prep<<<(NN + 255) / 256, 256>>>(bih, bhh);
    k_prep_wb<<<(81920 + 255) / 256, 256>>>(Whh, Wih);
    k_deg<<<(EE + 255) / 256, 256>>>(ei);
    k_lstm_mma<<<MM / MROWS, 512, DYN_BYTES>>>(x);
    k_dinv<<<(NN + 255) / 256, 256>>>();
    k_norm<<<(EE + 255) / 256, 256>>>(ei);

    k_xw<<<MM / 16, 128>>>(gW);
    k_agg_zero<<<((size_t)BQ * NN * GHD + 255) / 256, 256>>>();
    k_scatter<<<EE + NN, 128>>>(ei);
    k_mlp<<<MM, 128>>>(gb, W1, b1, W2, b2, out);
}

// round 14
// speedup vs baseline: 4.1827x; 1.0771x over previous
#include <cuda_runtime.h>
#include <cuda_bf16.h>
#include <cstddef>
#include <cstdint>

#define BQ 8
#define NN 2000
#define TT 64
#define FF 32
#define HH 128
#define NG 512
#define EE 32000
#define MM 16000
#define GHD 128

// ---- mma LSTM geometry ----
#define MROWS 64            // rows per CTA
#define PA 136              // A (h) pitch in bf16 elems
#define PX 72               // x pitch in bf16 elems

// W resident in smem: c0/c1 = Whh-hi [512][64k] @128B pitch (swizzled),
// c2 = Wih-hi [512][32k] @80B pitch (mod-8 conflict-free, unswizzled)
#define W2_OFF 131072
#define W_BYTES 172032      // 65536*2 + 40960

// smem layout (bytes)
#define WR_OFF  0
#define AHI_OFF 172032
#define ALO_OFF 189440
#define XHI_OFF 206848
#define BIAS_OFF 225280
#define MBAR_OFF 227328
#define DYN_BYTES 227344

// ------------------------- device scratch ----------------------------------
__device__ __align__(16) unsigned short g_Wblob[W_BYTES / 2];
__device__ __align__(16) float g_bias[NG];
__device__ float g_deg[NN];
__device__ float g_dinv[NN];
__device__ float g_norm[EE];
__device__ __align__(16) float g_h[MM * HH];
__device__ __align__(16) float g_xw[MM * GHD];
__device__ __align__(16) float g_agg[(size_t)BQ * NN * GHD];

// ------------------------- helpers -----------------------------------------
__device__ __forceinline__ float tanha(float x) {
    float y;
    asm("tanh.approx.f32 %0, %1;" : "=f"(y) : "f"(x));
    return y;
}
__device__ __forceinline__ float sigma(float x) {   // 0.5 + 0.5*tanh(x/2)
    return fmaf(0.5f, tanha(0.5f * x), 0.5f);
}
__device__ __forceinline__ float sigmf(float x) {   // exact (non-LSTM kernels)
    return __fdividef(1.f, 1.f + __expf(-x));
}
__device__ __forceinline__ void ldsm4(uint32_t& r0, uint32_t& r1, uint32_t& r2,
                                      uint32_t& r3, uint32_t addr) {
    asm volatile("ldmatrix.sync.aligned.m8n8.x4.shared.b16 {%0,%1,%2,%3}, [%4];"
                 : "=r"(r0), "=r"(r1), "=r"(r2), "=r"(r3) : "r"(addr));
}
__device__ __forceinline__ void mma16816(float* d, uint32_t a0, uint32_t a1,
                                         uint32_t a2, uint32_t a3,
                                         uint32_t b0, uint32_t b1) {
    asm volatile(
        "mma.sync.aligned.m16n8k16.row.col.f32.bf16.bf16.f32 "
        "{%0,%1,%2,%3}, {%4,%5,%6,%7}, {%8,%9}, {%0,%1,%2,%3};"
        : "+f"(d[0]), "+f"(d[1]), "+f"(d[2]), "+f"(d[3])
        : "r"(a0), "r"(a1), "r"(a2), "r"(a3), "r"(b0), "r"(b1));
}
__device__ __forceinline__ uint32_t bfbits(float v) {
    return (uint32_t)__bfloat16_as_ushort(__float2bfloat16(v));
}
__device__ __forceinline__ void mb_init(uint32_t a, uint32_t c) {
    asm volatile("mbarrier.init.shared.b64 [%0], %1;" :: "r"(a), "r"(c) : "memory");
}
__device__ __forceinline__ void mb_expect(uint32_t a, uint32_t bytes) {
    asm volatile("mbarrier.arrive.expect_tx.shared.b64 _, [%0], %1;"
                 :: "r"(a), "r"(bytes) : "memory");
}
__device__ __forceinline__ void mb_wait(uint32_t a, uint32_t parity) {
    asm volatile(
        "{\n\t.reg .pred P1;\n\t"
        "W0_%=:\n\t"
        "mbarrier.try_wait.parity.acquire.cta.shared::cta.b64 P1, [%0], %1, 0x989680;\n\t"
        "@P1 bra.uni W1_%=;\n\t"
        "bra.uni W0_%=;\n\t"
        "W1_%=:\n\t}" :: "r"(a), "r"(parity) : "memory");
}
__device__ __forceinline__ void bulk_cp(uint32_t dst, const void* src,
                                        uint32_t bytes, uint32_t mbar) {
    asm volatile("cp.async.bulk.shared::cta.global.mbarrier::complete_tx::bytes "
                 "[%0], [%1], %2, [%3];"
                 :: "r"(dst), "l"(src), "r"(bytes), "r"(mbar) : "memory");
}
__device__ __forceinline__ void group_bar(int id) {
    asm volatile("bar.sync %0, %1;" :: "r"(id), "r"(128) : "memory");
}

// ------------------------- prep kernels -------------------------------------
__global__ void k_prep(const float* __restrict__ bih, const float* __restrict__ bhh) {
    int i = blockIdx.x * blockDim.x + threadIdx.x;
    if (i < NG) g_bias[i] = bih[i] + bhh[i];
    if (i < NN) g_deg[i] = 1.0f;
}

// W blob, adjacent-unit gate layout. Column np -> (unit u, gate g):
//   c3 = np&7: q2 = c3>>1, gl = c3&1
//   j  = (np>>3)&3: fp = j>>1, half = j&1
//   tg = (np>>5)&3, wq = np>>7
//   u = 32*wq + 8*tg + 2*q2 + fp;  g = 2*half + gl;  n = g*128 + u
// c0/c1 = Whh-hi [512 np][64 k] @128B pitch SW128; c2 = Wih-hi [512][32] @80B.
__global__ void k_prep_wb(const float* __restrict__ Whh, const float* __restrict__ Wih) {
    int idx = blockIdx.x * blockDim.x + threadIdx.x;
    if (idx < 65536) {
        int c = idx >> 15, e = idx & 32767;
        int np = e >> 6, kk = e & 63;
        int q2 = (np >> 1) & 3, gl = np & 1;
        int fp = (np >> 4) & 1, half = (np >> 3) & 1;
        int tg = (np >> 5) & 3, wq = np >> 7;
        int u = 32 * wq + 8 * tg + 2 * q2 + fp;
        int g = 2 * half + gl;
        int n = g * HH + u;
        float val = Whh[n * HH + 64 * c + kk];
        int gnl = kk >> 3;
        uint32_t boff = (uint32_t)c * 65536 + (uint32_t)np * 128 +
                        (uint32_t)((gnl ^ (np & 7)) << 4) + (uint32_t)((kk & 7) * 2);
        *(unsigned short*)((char*)g_Wblob + boff) =
            __bfloat16_as_ushort(__float2bfloat16(val));
    } else if (idx < 65536 + 16384) {
        int e = idx - 65536;
        int np = e >> 5, kk = e & 31;
        int q2 = (np >> 1) & 3, gl = np & 1;
        int fp = (np >> 4) & 1, half = (np >> 3) & 1;
        int tg = (np >> 5) & 3, wq = np >> 7;
        int u = 32 * wq + 8 * tg + 2 * q2 + fp;
        int g = 2 * half + gl;
        int n = g * HH + u;
        float val = Wih[n * FF + kk];
        uint32_t boff = (uint32_t)W2_OFF + (uint32_t)np * 80 +
                        (uint32_t)((kk >> 3) << 4) + (uint32_t)((kk & 7) * 2);
        *(unsigned short*)((char*)g_Wblob + boff) =
            __bfloat16_as_ushort(__float2bfloat16(val));
    }
}

__global__ void k_deg(const int* __restrict__ ei) {
    int e = blockIdx.x * blockDim.x + threadIdx.x;
    if (e < EE) atomicAdd(&g_deg[ei[EE + e]], 1.0f);
}
__global__ void k_dinv() {
    int n = blockIdx.x * blockDim.x + threadIdx.x;
    if (n < NN) g_dinv[n] = rsqrtf(g_deg[n]);
}
__global__ void k_norm(const int* __restrict__ ei) {
    int e = blockIdx.x * blockDim.x + threadIdx.x;
    if (e < EE) g_norm[e] = g_dinv[ei[e]] * g_dinv[ei[EE + e]];
}

// ------------------------- mma.sync LSTM ------------------------------------
// 250 CTAs x 512 threads (16 warps). W (bf16-hi, 168KB) resident in smem.
// Warp w: m-block (w&3)*16, n-cols 128*(w>>2). The 4 warps sharing an
// m-block form an independent group synchronized by named barriers — the
// recurrence is closed over the group (h writes and A reads are group-local).
// x enters as single bf16 term; h keeps hi+lo split.
__global__ void __launch_bounds__(512, 1) k_lstm_mma(const float* __restrict__ x) {
    extern __shared__ __align__(16) char sm[];
    const uint32_t sbase = (uint32_t)__cvta_generic_to_shared(sm);
    const int tid = threadIdx.x;
    const int lane = tid & 31;
    const int w = tid >> 5;
    const int mb = 16 * (w & 3);
    const int nb = 128 * (w >> 2);
    const int grp = 1 + (w & 3);
    const int mbase = blockIdx.x * MROWS;
    const uint32_t mbarF0 = sbase + MBAR_OFF;

    if (tid == 0) mb_init(mbarF0, 1);

    // zero A hi/lo
    {
        uint4 z = make_uint4(0, 0, 0, 0);
        for (int i = tid; i < 2176; i += 512)
            *(uint4*)(sm + AHI_OFF + i * 16) = z;
    }
    // bias as float4 per unit (i,f,g,o)
    if (tid < HH) {
        float4 b4 = make_float4(g_bias[tid], g_bias[HH + tid],
                                g_bias[2 * HH + tid], g_bias[3 * HH + tid]);
        *(float4*)(sm + BIAS_OFF + tid * 16) = b4;
    }
    // group-local x staging geometry: gtid 0..127 within group
    const int gtid = (w >> 2) * 32 + lane;
    const int xr = mb + (gtid >> 3);        // row within CTA (this group's rows)
    const int xf = (gtid & 7) * 4;
    // stage x(0) hi only
    {
        const float* xp = x + (size_t)(mbase + xr) * (TT * FF) + xf;
        float4 v = __ldg((const float4*)xp);
        uint32_t h01 = bfbits(v.x) | (bfbits(v.y) << 16);
        uint32_t h23 = bfbits(v.z) | (bfbits(v.w) << 16);
        *(uint2*)(sm + XHI_OFF + (xr * PX + xf) * 2) = make_uint2(h01, h23);
    }
    __syncthreads();   // mbar init + A zeroing visible (block-wide, once)
    if (tid == 0) {
        mb_expect(mbarF0, W_BYTES);
        bulk_cp(sbase + WR_OFF, (const char*)g_Wblob, W_BYTES, mbarF0);
    }

    // per-lane ldmatrix address pieces
    const uint32_t a_row = mb + (lane & 7) + (((lane >> 3) & 1) << 3);
    const uint32_t a_kh = (lane & 16) ? 8 : 0;
    const uint32_t aoff_hi = sbase + AHI_OFF + (a_row * PA + a_kh) * 2;
    const uint32_t aoff_lo = sbase + ALO_OFF + (a_row * PA + a_kh) * 2;
    const uint32_t xoff_hi = sbase + XHI_OFF + (a_row * PX + a_kh) * 2;
    const uint32_t b_row = (lane & 7) + ((lane & 16) ? 8 : 0);
    const uint32_t kh = (lane >> 3) & 1;
    const uint32_t rx = lane & 7;
    const uint32_t bbase = sbase + WR_OFF + (nb + b_row) * 128;   // c0/c1
    const uint32_t b2base = sbase + WR_OFF + W2_OFF + (nb + b_row) * 80;  // c2

    float cst[16];
#pragma unroll
    for (int i = 0; i < 16; i++) cst[i] = 0.f;

    const int q2 = lane & 3;
    const int r0 = lane >> 2;

    mb_wait(mbarF0, 0);   // W resident
    __syncthreads();

    for (int t = 0; t < TT; t++) {
        float acc[4][16];
#pragma unroll
        for (int i = 0; i < 4; i++)
#pragma unroll
            for (int j = 0; j < 16; j++) acc[i][j] = 0.f;

        // ---- c0/c1: h(hi+lo) x Whh-hi ----
#pragma unroll
        for (int c = 0; c < 2; c++) {
            const uint32_t slotB = bbase + (uint32_t)c * 65536;
#pragma unroll
            for (int g2 = 0; g2 < 4; g2++) {
                uint32_t a0, a1, a2, a3, e0, e1, e2, e3;
                ldsm4(a0, a1, a2, a3, aoff_hi + 128 * c + 32 * g2);
                ldsm4(e0, e1, e2, e3, aoff_lo + 128 * c + 32 * g2);
                const uint32_t gx = (((uint32_t)(2 * g2) + kh) ^ rx) << 4;
#pragma unroll
                for (int tau = 0; tau < 4; tau++) {
                    uint32_t bt = slotB + tau * 4096 + gx;
                    uint32_t b0, b1, b2, b3, b4, b5, b6, b7;
                    ldsm4(b0, b1, b2, b3, bt);
                    ldsm4(b4, b5, b6, b7, bt + 2048);
                    mma16816(&acc[tau][0],  a0, a1, a2, a3, b0, b1);
                    mma16816(&acc[tau][4],  a0, a1, a2, a3, b2, b3);
                    mma16816(&acc[tau][8],  a0, a1, a2, a3, b4, b5);
                    mma16816(&acc[tau][12], a0, a1, a2, a3, b6, b7);
                    mma16816(&acc[tau][0],  e0, e1, e2, e3, b0, b1);
                    mma16816(&acc[tau][4],  e0, e1, e2, e3, b2, b3);
                    mma16816(&acc[tau][8],  e0, e1, e2, e3, b4, b5);
                    mma16816(&acc[tau][12], e0, e1, e2, e3, b6, b7);
                }
            }
        }
        // ---- c2: x(hi) x Wih-hi, single term ----
#pragma unroll
        for (int g2 = 0; g2 < 2; g2++) {
            uint32_t a0, a1, a2, a3;
            ldsm4(a0, a1, a2, a3, xoff_hi + 32 * g2);
            const uint32_t gx = ((uint32_t)(2 * g2) + kh) << 4;
#pragma unroll
            for (int tau = 0; tau < 4; tau++) {
                uint32_t bt = b2base + tau * 2560 + gx;
                uint32_t b0, b1, b2, b3, b4, b5, b6, b7;
                ldsm4(b0, b1, b2, b3, bt);
                ldsm4(b4, b5, b6, b7, bt + 1280);
                mma16816(&acc[tau][0],  a0, a1, a2, a3, b0, b1);
                mma16816(&acc[tau][4],  a0, a1, a2, a3, b2, b3);
                mma16816(&acc[tau][8],  a0, a1, a2, a3, b4, b5);
                mma16816(&acc[tau][12], a0, a1, a2, a3, b6, b7);
            }
        }

        group_bar(grp);   // this group's warps finished reading its A rows

        // ---- gates: thread owns adjacent units u0 = base+8tau+2q2 (fp=0)
        // and u0+1 (fp=1); rows r0, r0+8. Packed 4B hi/lo stores.
        const bool last = (t == TT - 1);
#pragma unroll
        for (int tau = 0; tau < 4; tau++) {
            const int u0 = (nb >> 2) + 8 * tau + 2 * q2;
            float4 bE = *(const float4*)(sm + BIAS_OFF + u0 * 16);
            float4 bO = *(const float4*)(sm + BIAS_OFF + u0 * 16 + 16);
#pragma unroll
            for (int rr = 0; rr < 2; rr++) {
                // fp = 0 (unit u0): blocks tau.0 / tau.1
                float zi = acc[tau][2 * rr] + bE.x;
                float zf = acc[tau][2 * rr + 1] + bE.y;
                float zg = acc[tau][4 + 2 * rr] + bE.z;
                float zo = acc[tau][5 + 2 * rr] + bE.w;
                float ig = sigma(zi), fg = sigma(zf);
                float gg = tanha(zg), og = sigma(zo);
                int i0 = tau * 4 + rr;
                float nc = fg * cst[i0] + ig * gg;
                cst[i0] = nc;
                float h0 = og * tanha(nc);
                // fp = 1 (unit u0+1): blocks tau.2 / tau.3
                zi = acc[tau][8 + 2 * rr] + bO.x;
                zf = acc[tau][9 + 2 * rr] + bO.y;
                zg = acc[tau][12 + 2 * rr] + bO.z;
                zo = acc[tau][13 + 2 * rr] + bO.w;
                ig = sigma(zi); fg = sigma(zf);
                gg = tanha(zg); og = sigma(zo);
                int i1 = tau * 4 + 2 + rr;
                nc = fg * cst[i1] + ig * gg;
                cst[i1] = nc;
                float h1 = og * tanha(nc);

                const int m = mb + r0 + 8 * rr;
                if (last) {
                    *(float2*)&g_h[(size_t)(mbase + m) * HH + u0] =
                        make_float2(h0, h1);
                } else {
                    __nv_bfloat16 hh0 = __float2bfloat16(h0);
                    __nv_bfloat16 hh1 = __float2bfloat16(h1);
                    uint32_t hiP = (uint32_t)__bfloat16_as_ushort(hh0) |
                                   ((uint32_t)__bfloat16_as_ushort(hh1) << 16);
                    uint32_t loP = bfbits(h0 - __bfloat162float(hh0)) |
                                   (bfbits(h1 - __bfloat162float(hh1)) << 16);
                    *(uint32_t*)(sm + AHI_OFF + (m * PA + u0) * 2) = hiP;
                    *(uint32_t*)(sm + ALO_OFF + (m * PA + u0) * 2) = loP;
                }
            }
        }

        if (!last) {
            // stage x(t+1) hi only (group-local rows)
            const float* xp = x + (size_t)(mbase + xr) * (TT * FF) + (t + 1) * FF + xf;
            float4 v = __ldg((const float4*)xp);
            uint32_t h01 = bfbits(v.x) | (bfbits(v.y) << 16);
            uint32_t h23 = bfbits(v.z) | (bfbits(v.w) << 16);
            *(uint2*)(sm + XHI_OFF + (xr * PX + xf) * 2) = make_uint2(h01, h23);
        }
        group_bar(grp);   // h/x writes visible to this group before next GEMM
    }
}

// ------------------------- GCN + MLP ----------------------------------------
__global__ void k_xw(const float* __restrict__ gW) {
    __shared__ float hsm[16][HH];
    const int tid = threadIdx.x;
    const int rowbase = blockIdx.x * 16;
#pragma unroll
    for (int r = 0; r < 16; r++) {
        int idx = tid + r * 128;
        hsm[idx >> 7][idx & 127] = g_h[(size_t)rowbase * HH + idx];
    }
    __syncthreads();
    float acc[16];
#pragma unroll
    for (int r = 0; r < 16; r++) acc[r] = 0.f;
#pragma unroll 4
    for (int k = 0; k < HH; k++) {
        float wv = __ldg(&gW[k * GHD + tid]);
#pragma unroll
        for (int r = 0; r < 16; r++) acc[r] += hsm[r][k] * wv;
    }
#pragma unroll
    for (int r = 0; r < 16; r++)
        g_xw[(size_t)(rowbase + r) * GHD + tid] = acc[r];
}

__global__ void k_agg_zero() {
    size_t i = (size_t)blockIdx.x * blockDim.x + threadIdx.x;
    if (i < (size_t)BQ * NN * GHD) g_agg[i] = 0.f;
}

__global__ void k_scatter(const int* __restrict__ ei) {
    const int e = blockIdx.x, ch = threadIdx.x;
    int s, d; float wv;
    if (e < EE) { s = ei[e]; d = ei[EE + e]; wv = g_norm[e]; }
    else { s = d = e - EE; float di = g_dinv[s]; wv = di * di; }
#pragma unroll
    for (int b = 0; b < BQ; b++) {
        float v = g_xw[((size_t)b * NN + s) * GHD + ch] * wv;
        atomicAdd(&g_agg[((size_t)b * NN + d) * GHD + ch], v);
    }
}

__global__ void k_mlp(const float* __restrict__ gb, const float* __restrict__ W1,
                      const float* __restrict__ b1, const float* __restrict__ W2,
                      const float* __restrict__ b2, float* __restrict__ out) {
    __shared__ float in_s[GHD];
    __shared__ float red[64];
    const int m = blockIdx.x, ch = threadIdx.x;
    in_s[ch] = g_agg[(size_t)m * GHD + ch] + __ldg(&gb[ch]);
    __syncthreads();
    if (ch < 64) {
        float s = __ldg(&b1[ch]);
#pragma unroll 8
        for (int k = 0; k < GHD; k++) s += in_s[k] * __ldg(&W1[k * 64 + ch]);
        float h1 = s * sigmf(s);
        red[ch] = h1 * __ldg(&W2[ch]);
    }
    __syncthreads();
    if (ch == 0) {
        float s = __ldg(&b2[0]);
#pragma unroll
        for (int j = 0; j < 64; j++) s += red[j];
        out[m] = s;
    }
}

// ------------------------- launch --------------------------------------------
extern "C" void kernel_launch(void* const* d_in, const int* in_sizes, int n_in,
                              void* d_out, int out_size) {
    const float* x   = (const float*)d_in[0];
    const int*   ei  = (const int*)d_in[1];
    const float* Wih = (const float*)d_in[2];
    const float* Whh = (const float*)d_in[3];
    const float* bih = (const float*)d_in[4];
    const float* bhh = (const float*)d_in[5];
    const float* gW  = (const float*)d_in[6];
    const float* gb  = (const float*)d_in[7];
    const float* W1  = (const float*)d_in[8];
    const float* b1  = (const float*)d_in[9];
    const float* W2  = (const float*)d_in[10];
    const float* b2  = (const float*)d_in[11];
    float* out = (float*)d_out;

    cudaFuncSetAttribute(k_lstm_mma, cudaFuncAttributeMaxDynamicSharedMemorySize,
                         DYN_BYTES);

    // k_lstm_mma is the 4th launch -> profiler's fixed sampling slot
    k_prep<<<(NN + 255) / 256, 256>>>(bih, bhh);
    k_prep_wb<<<(81920 + 255) / 256, 256>>>(Whh, Wih);
    k_deg<<<(EE + 255) / 256, 256>>>(ei);
    k_lstm_mma<<<MM / MROWS, 512, DYN_BYTES>>>(x);
    k_dinv<<<(NN + 255) / 256, 256>>>();
    k_norm<<<(EE + 255) / 256, 256>>>(ei);

    k_xw<<<MM / 16, 128>>>(gW);
    k_agg_zero<<<((size_t)BQ * NN * GHD + 255) / 256, 256>>>();
    k_scatter<<<EE + NN, 128>>>(ei);
    k_mlp<<<MM, 128>>>(gb, W1, b1, W2, b2, out);
}

// round 15
// speedup vs baseline: 4.8498x; 1.1595x over previous
#include <cuda_runtime.h>
#include <cuda_bf16.h>
#include <cstddef>
#include <cstdint>

#define BQ 8
#define NN 2000
#define TT 64
#define FF 32
#define HH 128
#define NG 512
#define EE 32000
#define MM 16000
#define GHD 128

// ---- mma LSTM geometry ----
#define MROWS 64            // rows per CTA
#define PA 136              // A (h) pitch in bf16 elems
#define PX 72               // x pitch in bf16 elems

// W resident in smem: c0/c1 = Whh-hi [512][64k] @128B pitch (swizzled),
// c2 = Wih-hi [512][32k] @80B pitch (mod-8 conflict-free, unswizzled)
#define W2_OFF 131072
#define W_BYTES 172032      // 65536*2 + 40960

// smem layout (bytes)
#define WR_OFF  0
#define AHI_OFF 172032
#define ALO_OFF 189440
#define XHI_OFF 206848
#define BIAS_OFF 225280
#define MBAR_OFF 227328
#define DYN_BYTES 227344

// ------------------------- device scratch ----------------------------------
__device__ __align__(16) unsigned short g_Wblob[W_BYTES / 2];
__device__ __align__(16) float g_bias[NG];
__device__ float g_deg[NN];
__device__ float g_dinv[NN];
__device__ float g_norm[EE];
__device__ __align__(16) float g_h[MM * HH];
__device__ __align__(16) float g_xw[MM * GHD];
__device__ __align__(16) float g_agg[(size_t)BQ * NN * GHD];

// ------------------------- helpers -----------------------------------------
__device__ __forceinline__ float tanha(float x) {
    float y;
    asm("tanh.approx.f32 %0, %1;" : "=f"(y) : "f"(x));
    return y;
}
__device__ __forceinline__ float sigma(float x) {   // 0.5 + 0.5*tanh(x/2)
    return fmaf(0.5f, tanha(0.5f * x), 0.5f);
}
__device__ __forceinline__ float sigmf(float x) {   // exact (non-LSTM kernels)
    return __fdividef(1.f, 1.f + __expf(-x));
}
__device__ __forceinline__ void ldsm4(uint32_t& r0, uint32_t& r1, uint32_t& r2,
                                      uint32_t& r3, uint32_t addr) {
    asm volatile("ldmatrix.sync.aligned.m8n8.x4.shared.b16 {%0,%1,%2,%3}, [%4];"
                 : "=r"(r0), "=r"(r1), "=r"(r2), "=r"(r3) : "r"(addr));
}
__device__ __forceinline__ void mma16816(float* d, uint32_t a0, uint32_t a1,
                                         uint32_t a2, uint32_t a3,
                                         uint32_t b0, uint32_t b1) {
    asm volatile(
        "mma.sync.aligned.m16n8k16.row.col.f32.bf16.bf16.f32 "
        "{%0,%1,%2,%3}, {%4,%5,%6,%7}, {%8,%9}, {%0,%1,%2,%3};"
        : "+f"(d[0]), "+f"(d[1]), "+f"(d[2]), "+f"(d[3])
        : "r"(a0), "r"(a1), "r"(a2), "r"(a3), "r"(b0), "r"(b1));
}
__device__ __forceinline__ uint32_t bfbits(float v) {
    return (uint32_t)__bfloat16_as_ushort(__float2bfloat16(v));
}
__device__ __forceinline__ void mb_init(uint32_t a, uint32_t c) {
    asm volatile("mbarrier.init.shared.b64 [%0], %1;" :: "r"(a), "r"(c) : "memory");
}
__device__ __forceinline__ void mb_expect(uint32_t a, uint32_t bytes) {
    asm volatile("mbarrier.arrive.expect_tx.shared.b64 _, [%0], %1;"
                 :: "r"(a), "r"(bytes) : "memory");
}
__device__ __forceinline__ void mb_wait(uint32_t a, uint32_t parity) {
    asm volatile(
        "{\n\t.reg .pred P1;\n\t"
        "W0_%=:\n\t"
        "mbarrier.try_wait.parity.acquire.cta.shared::cta.b64 P1, [%0], %1, 0x989680;\n\t"
        "@P1 bra.uni W1_%=;\n\t"
        "bra.uni W0_%=;\n\t"
        "W1_%=:\n\t}" :: "r"(a), "r"(parity) : "memory");
}
__device__ __forceinline__ void bulk_cp(uint32_t dst, const void* src,
                                        uint32_t bytes, uint32_t mbar) {
    asm volatile("cp.async.bulk.shared::cta.global.mbarrier::complete_tx::bytes "
                 "[%0], [%1], %2, [%3];"
                 :: "r"(dst), "l"(src), "r"(bytes), "r"(mbar) : "memory");
}
__device__ __forceinline__ void group_bar(int id) {
    asm volatile("bar.sync %0, %1;" :: "r"(id), "r"(128) : "memory");
}

// ------------------------- prep kernels -------------------------------------
__global__ void k_prep(const float* __restrict__ bih, const float* __restrict__ bhh) {
    int i = blockIdx.x * blockDim.x + threadIdx.x;
    if (i < NG) g_bias[i] = bih[i] + bhh[i];
    if (i < NN) g_deg[i] = 1.0f;
}

// W blob, adjacent-unit gate layout. Column np -> (unit u, gate g):
//   c3 = np&7: q2 = c3>>1, gl = c3&1
//   j  = (np>>3)&3: fp = j>>1, half = j&1
//   tg = (np>>5)&3, wq = np>>7
//   u = 32*wq + 8*tg + 2*q2 + fp;  g = 2*half + gl;  n = g*128 + u
// c0/c1 = Whh-hi [512 np][64 k] @128B pitch SW128; c2 = Wih-hi [512][32] @80B.
__global__ void k_prep_wb(const float* __restrict__ Whh, const float* __restrict__ Wih) {
    int idx = blockIdx.x * blockDim.x + threadIdx.x;
    if (idx < 65536) {
        int c = idx >> 15, e = idx & 32767;
        int np = e >> 6, kk = e & 63;
        int q2 = (np >> 1) & 3, gl = np & 1;
        int fp = (np >> 4) & 1, half = (np >> 3) & 1;
        int tg = (np >> 5) & 3, wq = np >> 7;
        int u = 32 * wq + 8 * tg + 2 * q2 + fp;
        int g = 2 * half + gl;
        int n = g * HH + u;
        float val = Whh[n * HH + 64 * c + kk];
        int gnl = kk >> 3;
        uint32_t boff = (uint32_t)c * 65536 + (uint32_t)np * 128 +
                        (uint32_t)((gnl ^ (np & 7)) << 4) + (uint32_t)((kk & 7) * 2);
        *(unsigned short*)((char*)g_Wblob + boff) =
            __bfloat16_as_ushort(__float2bfloat16(val));
    } else if (idx < 65536 + 16384) {
        int e = idx - 65536;
        int np = e >> 5, kk = e & 31;
        int q2 = (np >> 1) & 3, gl = np & 1;
        int fp = (np >> 4) & 1, half = (np >> 3) & 1;
        int tg = (np >> 5) & 3, wq = np >> 7;
        int u = 32 * wq + 8 * tg + 2 * q2 + fp;
        int g = 2 * half + gl;
        int n = g * HH + u;
        float val = Wih[n * FF + kk];
        uint32_t boff = (uint32_t)W2_OFF + (uint32_t)np * 80 +
                        (uint32_t)((kk >> 3) << 4) + (uint32_t)((kk & 7) * 2);
        *(unsigned short*)((char*)g_Wblob + boff) =
            __bfloat16_as_ushort(__float2bfloat16(val));
    }
}

__global__ void k_deg(const int* __restrict__ ei) {
    int e = blockIdx.x * blockDim.x + threadIdx.x;
    if (e < EE) atomicAdd(&g_deg[ei[EE + e]], 1.0f);
}
__global__ void k_dinv() {
    int n = blockIdx.x * blockDim.x + threadIdx.x;
    if (n < NN) g_dinv[n] = rsqrtf(g_deg[n]);
}
__global__ void k_norm(const int* __restrict__ ei) {
    int e = blockIdx.x * blockDim.x + threadIdx.x;
    if (e < EE) g_norm[e] = g_dinv[ei[e]] * g_dinv[ei[EE + e]];
}

// ------------------------- mma.sync LSTM ------------------------------------
// 250 CTAs x 512 threads (16 warps). W (bf16-hi, 168KB) resident in smem.
// Warp w: m-block 16*(w>>2), n-cols 128*(w&3)  [TRANSPOSED MAPPING].
// Each recurrence group (one m-block, 4 warps) is spread across all 4 SMSPs,
// so every scheduler hosts one warp of each group: when a group runs its
// MUFU epilogue, the other groups' MMAs keep the tensor pipe fed.
__global__ void __launch_bounds__(512, 1) k_lstm_mma(const float* __restrict__ x) {
    extern __shared__ __align__(16) char sm[];
    const uint32_t sbase = (uint32_t)__cvta_generic_to_shared(sm);
    const int tid = threadIdx.x;
    const int lane = tid & 31;
    const int w = tid >> 5;
    const int mb = 16 * (w >> 2);    // TRANSPOSED: m-block from upper bits
    const int nb = 128 * (w & 3);    //             n-quad from SMSP bits
    const int grp = 1 + (w >> 2);
    const int mbase = blockIdx.x * MROWS;
    const uint32_t mbarF0 = sbase + MBAR_OFF;

    if (tid == 0) mb_init(mbarF0, 1);

    // zero A hi/lo
    {
        uint4 z = make_uint4(0, 0, 0, 0);
        for (int i = tid; i < 2176; i += 512)
            *(uint4*)(sm + AHI_OFF + i * 16) = z;
    }
    // bias as float4 per unit (i,f,g,o)
    if (tid < HH) {
        float4 b4 = make_float4(g_bias[tid], g_bias[HH + tid],
                                g_bias[2 * HH + tid], g_bias[3 * HH + tid]);
        *(float4*)(sm + BIAS_OFF + tid * 16) = b4;
    }
    // group-local x staging geometry: gtid 0..127 within group
    const int gtid = (w & 3) * 32 + lane;
    const int xr = mb + (gtid >> 3);        // row within CTA (this group's rows)
    const int xf = (gtid & 7) * 4;
    // stage x(0) hi only
    {
        const float* xp = x + (size_t)(mbase + xr) * (TT * FF) + xf;
        float4 v = __ldg((const float4*)xp);
        uint32_t h01 = bfbits(v.x) | (bfbits(v.y) << 16);
        uint32_t h23 = bfbits(v.z) | (bfbits(v.w) << 16);
        *(uint2*)(sm + XHI_OFF + (xr * PX + xf) * 2) = make_uint2(h01, h23);
    }
    __syncthreads();   // mbar init + A zeroing visible (block-wide, once)
    if (tid == 0) {
        mb_expect(mbarF0, W_BYTES);
        bulk_cp(sbase + WR_OFF, (const char*)g_Wblob, W_BYTES, mbarF0);
    }

    // per-lane ldmatrix address pieces
    const uint32_t a_row = mb + (lane & 7) + (((lane >> 3) & 1) << 3);
    const uint32_t a_kh = (lane & 16) ? 8 : 0;
    const uint32_t aoff_hi = sbase + AHI_OFF + (a_row * PA + a_kh) * 2;
    const uint32_t aoff_lo = sbase + ALO_OFF + (a_row * PA + a_kh) * 2;
    const uint32_t xoff_hi = sbase + XHI_OFF + (a_row * PX + a_kh) * 2;
    const uint32_t b_row = (lane & 7) + ((lane & 16) ? 8 : 0);
    const uint32_t kh = (lane >> 3) & 1;
    const uint32_t rx = lane & 7;
    const uint32_t bbase = sbase + WR_OFF + (nb + b_row) * 128;   // c0/c1
    const uint32_t b2base = sbase + WR_OFF + W2_OFF + (nb + b_row) * 80;  // c2

    float cst[16];
#pragma unroll
    for (int i = 0; i < 16; i++) cst[i] = 0.f;

    const int q2 = lane & 3;
    const int r0 = lane >> 2;

    mb_wait(mbarF0, 0);   // W resident
    __syncthreads();

    for (int t = 0; t < TT; t++) {
        float acc[4][16];
#pragma unroll
        for (int i = 0; i < 4; i++)
#pragma unroll
            for (int j = 0; j < 16; j++) acc[i][j] = 0.f;

        // ---- c0/c1: h(hi+lo) x Whh-hi ----
#pragma unroll
        for (int c = 0; c < 2; c++) {
            const uint32_t slotB = bbase + (uint32_t)c * 65536;
#pragma unroll
            for (int g2 = 0; g2 < 4; g2++) {
                uint32_t a0, a1, a2, a3, e0, e1, e2, e3;
                ldsm4(a0, a1, a2, a3, aoff_hi + 128 * c + 32 * g2);
                ldsm4(e0, e1, e2, e3, aoff_lo + 128 * c + 32 * g2);
                const uint32_t gx = (((uint32_t)(2 * g2) + kh) ^ rx) << 4;
#pragma unroll
                for (int tau = 0; tau < 4; tau++) {
                    uint32_t bt = slotB + tau * 4096 + gx;
                    uint32_t b0, b1, b2, b3, b4, b5, b6, b7;
                    ldsm4(b0, b1, b2, b3, bt);
                    ldsm4(b4, b5, b6, b7, bt + 2048);
                    mma16816(&acc[tau][0],  a0, a1, a2, a3, b0, b1);
                    mma16816(&acc[tau][4],  a0, a1, a2, a3, b2, b3);
                    mma16816(&acc[tau][8],  a0, a1, a2, a3, b4, b5);
                    mma16816(&acc[tau][12], a0, a1, a2, a3, b6, b7);
                    mma16816(&acc[tau][0],  e0, e1, e2, e3, b0, b1);
                    mma16816(&acc[tau][4],  e0, e1, e2, e3, b2, b3);
                    mma16816(&acc[tau][8],  e0, e1, e2, e3, b4, b5);
                    mma16816(&acc[tau][12], e0, e1, e2, e3, b6, b7);
                }
            }
        }
        // ---- c2: x(hi) x Wih-hi, single term ----
#pragma unroll
        for (int g2 = 0; g2 < 2; g2++) {
            uint32_t a0, a1, a2, a3;
            ldsm4(a0, a1, a2, a3, xoff_hi + 32 * g2);
            const uint32_t gx = ((uint32_t)(2 * g2) + kh) << 4;
#pragma unroll
            for (int tau = 0; tau < 4; tau++) {
                uint32_t bt = b2base + tau * 2560 + gx;
                uint32_t b0, b1, b2, b3, b4, b5, b6, b7;
                ldsm4(b0, b1, b2, b3, bt);
                ldsm4(b4, b5, b6, b7, bt + 1280);
                mma16816(&acc[tau][0],  a0, a1, a2, a3, b0, b1);
                mma16816(&acc[tau][4],  a0, a1, a2, a3, b2, b3);
                mma16816(&acc[tau][8],  a0, a1, a2, a3, b4, b5);
                mma16816(&acc[tau][12], a0, a1, a2, a3, b6, b7);
            }
        }

        group_bar(grp);   // this group's warps finished reading its A rows

        // ---- gates: thread owns adjacent units u0 = base+8tau+2q2 (fp=0)
        // and u0+1 (fp=1); rows r0, r0+8. Packed 4B hi/lo stores.
        const bool last = (t == TT - 1);
#pragma unroll
        for (int tau = 0; tau < 4; tau++) {
            const int u0 = (nb >> 2) + 8 * tau + 2 * q2;
            float4 bE = *(const float4*)(sm + BIAS_OFF + u0 * 16);
            float4 bO = *(const float4*)(sm + BIAS_OFF + u0 * 16 + 16);
#pragma unroll
            for (int rr = 0; rr < 2; rr++) {
                // fp = 0 (unit u0): blocks tau.0 / tau.1
                float zi = acc[tau][2 * rr] + bE.x;
                float zf = acc[tau][2 * rr + 1] + bE.y;
                float zg = acc[tau][4 + 2 * rr] + bE.z;
                float zo = acc[tau][5 + 2 * rr] + bE.w;
                float ig = sigma(zi), fg = sigma(zf);
                float gg = tanha(zg), og = sigma(zo);
                int i0 = tau * 4 + rr;
                float nc = fg * cst[i0] + ig * gg;
                cst[i0] = nc;
                float h0 = og * tanha(nc);
                // fp = 1 (unit u0+1): blocks tau.2 / tau.3
                zi = acc[tau][8 + 2 * rr] + bO.x;
                zf = acc[tau][9 + 2 * rr] + bO.y;
                zg = acc[tau][12 + 2 * rr] + bO.z;
                zo = acc[tau][13 + 2 * rr] + bO.w;
                ig = sigma(zi); fg = sigma(zf);
                gg = tanha(zg); og = sigma(zo);
                int i1 = tau * 4 + 2 + rr;
                nc = fg * cst[i1] + ig * gg;
                cst[i1] = nc;
                float h1 = og * tanha(nc);

                const int m = mb + r0 + 8 * rr;
                if (last) {
                    *(float2*)&g_h[(size_t)(mbase + m) * HH + u0] =
                        make_float2(h0, h1);
                } else {
                    __nv_bfloat16 hh0 = __float2bfloat16(h0);
                    __nv_bfloat16 hh1 = __float2bfloat16(h1);
                    uint32_t hiP = (uint32_t)__bfloat16_as_ushort(hh0) |
                                   ((uint32_t)__bfloat16_as_ushort(hh1) << 16);
                    uint32_t loP = bfbits(h0 - __bfloat162float(hh0)) |
                                   (bfbits(h1 - __bfloat162float(hh1)) << 16);
                    *(uint32_t*)(sm + AHI_OFF + (m * PA + u0) * 2) = hiP;
                    *(uint32_t*)(sm + ALO_OFF + (m * PA + u0) * 2) = loP;
                }
            }
        }

        if (!last) {
            // stage x(t+1) hi only (group-local rows)
            const float* xp = x + (size_t)(mbase + xr) * (TT * FF) + (t + 1) * FF + xf;
            float4 v = __ldg((const float4*)xp);
            uint32_t h01 = bfbits(v.x) | (bfbits(v.y) << 16);
            uint32_t h23 = bfbits(v.z) | (bfbits(v.w) << 16);
            *(uint2*)(sm + XHI_OFF + (xr * PX + xf) * 2) = make_uint2(h01, h23);
        }
        group_bar(grp);   // h/x writes visible to this group before next GEMM
    }
}

// ------------------------- GCN + MLP ----------------------------------------
__global__ void k_xw(const float* __restrict__ gW) {
    __shared__ float hsm[16][HH];
    const int tid = threadIdx.x;
    const int rowbase = blockIdx.x * 16;
#pragma unroll
    for (int r = 0; r < 16; r++) {
        int idx = tid + r * 128;
        hsm[idx >> 7][idx & 127] = g_h[(size_t)rowbase * HH + idx];
    }
    __syncthreads();
    float acc[16];
#pragma unroll
    for (int r = 0; r < 16; r++) acc[r] = 0.f;
#pragma unroll 4
    for (int k = 0; k < HH; k++) {
        float wv = __ldg(&gW[k * GHD + tid]);
#pragma unroll
        for (int r = 0; r < 16; r++) acc[r] += hsm[r][k] * wv;
    }
#pragma unroll
    for (int r = 0; r < 16; r++)
        g_xw[(size_t)(rowbase + r) * GHD + tid] = acc[r];
}

__global__ void k_agg_zero() {
    size_t i = (size_t)blockIdx.x * blockDim.x + threadIdx.x;
    if (i < (size_t)BQ * NN * GHD) g_agg[i] = 0.f;
}

__global__ void k_scatter(const int* __restrict__ ei) {
    const int e = blockIdx.x, ch = threadIdx.x;
    int s, d; float wv;
    if (e < EE) { s = ei[e]; d = ei[EE + e]; wv = g_norm[e]; }
    else { s = d = e - EE; float di = g_dinv[s]; wv = di * di; }
#pragma unroll
    for (int b = 0; b < BQ; b++) {
        float v = g_xw[((size_t)b * NN + s) * GHD + ch] * wv;
        atomicAdd(&g_agg[((size_t)b * NN + d) * GHD + ch], v);
    }
}

__global__ void k_mlp(const float* __restrict__ gb, const float* __restrict__ W1,
                      const float* __restrict__ b1, const float* __restrict__ W2,
                      const float* __restrict__ b2, float* __restrict__ out) {
    __shared__ float in_s[GHD];
    __shared__ float red[64];
    const int m = blockIdx.x, ch = threadIdx.x;
    in_s[ch] = g_agg[(size_t)m * GHD + ch] + __ldg(&gb[ch]);
    __syncthreads();
    if (ch < 64) {
        float s = __ldg(&b1[ch]);
#pragma unroll 8
        for (int k = 0; k < GHD; k++) s += in_s[k] * __ldg(&W1[k * 64 + ch]);
        float h1 = s * sigmf(s);
        red[ch] = h1 * __ldg(&W2[ch]);
    }
    __syncthreads();
    if (ch == 0) {
        float s = __ldg(&b2[0]);
#pragma unroll
        for (int j = 0; j < 64; j++) s += red[j];
        out[m] = s;
    }
}

// ------------------------- launch --------------------------------------------
extern "C" void kernel_launch(void* const* d_in, const int* in_sizes, int n_in,
                              void* d_out, int out_size) {
    const float* x   = (const float*)d_in[0];
    const int*   ei  = (const int*)d_in[1];
    const float* Wih = (const float*)d_in[2];
    const float* Whh = (const float*)d_in[3];
    const float* bih = (const float*)d_in[4];
    const float* bhh = (const float*)d_in[5];
    const float* gW  = (const float*)d_in[6];
    const float* gb  = (const float*)d_in[7];
    const float* W1  = (const float*)d_in[8];
    const float* b1  = (const float*)d_in[9];
    const float* W2  = (const float*)d_in[10];
    const float* b2  = (const float*)d_in[11];
    float* out = (float*)d_out;

    cudaFuncSetAttribute(k_lstm_mma, cudaFuncAttributeMaxDynamicSharedMemorySize,
                         DYN_BYTES);

    // k_lstm_mma is the 4th launch -> profiler's fixed sampling slot
    k_prep<<<(NN + 255) / 256, 256>>>(bih, bhh);
    k_prep_wb<<<(81920 + 255) / 256, 256>>>(Whh, Wih);
    k_deg<<<(EE + 255) / 256, 256>>>(ei);
    k_lstm_mma<<<MM / MROWS, 512, DYN_BYTES>>>(x);
    k_dinv<<<(NN + 255) / 256, 256>>>();
    k_norm<<<(EE + 255) / 256, 256>>>(ei);

    k_xw<<<MM / 16, 128>>>(gW);
    k_agg_zero<<<((size_t)BQ * NN * GHD + 255) / 256, 256>>>();
    k_scatter<<<EE + NN, 128>>>(ei);
    k_mlp<<<MM, 128>>>(gb, W1, b1, W2, b2, out);
}

// round 16
// speedup vs baseline: 4.8540x; 1.0009x over previous
#include <cuda_runtime.h>
#include <cuda_bf16.h>
#include <cstddef>
#include <cstdint>

#define BQ 8
#define NN 2000
#define TT 64
#define FF 32
#define HH 128
#define NG 512
#define EE 32000
#define MM 16000
#define GHD 128

// ---- mma LSTM geometry ----
#define MROWS 64            // rows per CTA
#define PA 136              // A (h) pitch in bf16 elems
#define PX 72               // x pitch in bf16 elems

// W resident in smem: c0/c1 = Whh-hi [512][64k] @128B pitch (swizzled),
// c2 = Wih-hi [512][32k] @80B pitch (mod-8 conflict-free, unswizzled)
#define W2_OFF 131072
#define W_BYTES 172032      // 65536*2 + 40960

// smem layout (bytes)
#define WR_OFF  0
#define AHI_OFF 172032
#define ALO_OFF 189440
#define XHI_OFF 206848
#define BIAS_OFF 225280
#define MBAR_OFF 227328
#define DYN_BYTES 227344

// ------------------------- device scratch ----------------------------------
__device__ __align__(16) unsigned short g_Wblob[W_BYTES / 2];
__device__ __align__(16) float g_bias[NG];
__device__ float g_deg[NN];
__device__ float g_dinv[NN];
__device__ float g_norm[EE];
__device__ __align__(16) float g_h[MM * HH];
__device__ __align__(16) float g_xw[MM * GHD];
__device__ __align__(16) float g_agg[(size_t)BQ * NN * GHD];

// ------------------------- helpers -----------------------------------------
__device__ __forceinline__ float tanha(float x) {
    float y;
    asm("tanh.approx.f32 %0, %1;" : "=f"(y) : "f"(x));
    return y;
}
__device__ __forceinline__ float sigma(float x) {   // 0.5 + 0.5*tanh(x/2)
    return fmaf(0.5f, tanha(0.5f * x), 0.5f);
}
__device__ __forceinline__ float sigmf(float x) {   // exact (non-LSTM kernels)
    return __fdividef(1.f, 1.f + __expf(-x));
}
__device__ __forceinline__ void ldsm4(uint32_t& r0, uint32_t& r1, uint32_t& r2,
                                      uint32_t& r3, uint32_t addr) {
    asm volatile("ldmatrix.sync.aligned.m8n8.x4.shared.b16 {%0,%1,%2,%3}, [%4];"
                 : "=r"(r0), "=r"(r1), "=r"(r2), "=r"(r3) : "r"(addr));
}
__device__ __forceinline__ void mma16816(float* d, uint32_t a0, uint32_t a1,
                                         uint32_t a2, uint32_t a3,
                                         uint32_t b0, uint32_t b1) {
    asm volatile(
        "mma.sync.aligned.m16n8k16.row.col.f32.bf16.bf16.f32 "
        "{%0,%1,%2,%3}, {%4,%5,%6,%7}, {%8,%9}, {%0,%1,%2,%3};"
        : "+f"(d[0]), "+f"(d[1]), "+f"(d[2]), "+f"(d[3])
        : "r"(a0), "r"(a1), "r"(a2), "r"(a3), "r"(b0), "r"(b1));
}
__device__ __forceinline__ uint32_t bfbits(float v) {
    return (uint32_t)__bfloat16_as_ushort(__float2bfloat16(v));
}
__device__ __forceinline__ void mb_init(uint32_t a, uint32_t c) {
    asm volatile("mbarrier.init.shared.b64 [%0], %1;" :: "r"(a), "r"(c) : "memory");
}
__device__ __forceinline__ void mb_expect(uint32_t a, uint32_t bytes) {
    asm volatile("mbarrier.arrive.expect_tx.shared.b64 _, [%0], %1;"
                 :: "r"(a), "r"(bytes) : "memory");
}
__device__ __forceinline__ void mb_wait(uint32_t a, uint32_t parity) {
    asm volatile(
        "{\n\t.reg .pred P1;\n\t"
        "W0_%=:\n\t"
        "mbarrier.try_wait.parity.acquire.cta.shared::cta.b64 P1, [%0], %1, 0x989680;\n\t"
        "@P1 bra.uni W1_%=;\n\t"
        "bra.uni W0_%=;\n\t"
        "W1_%=:\n\t}" :: "r"(a), "r"(parity) : "memory");
}
__device__ __forceinline__ void bulk_cp(uint32_t dst, const void* src,
                                        uint32_t bytes, uint32_t mbar) {
    asm volatile("cp.async.bulk.shared::cta.global.mbarrier::complete_tx::bytes "
                 "[%0], [%1], %2, [%3];"
                 :: "r"(dst), "l"(src), "r"(bytes), "r"(mbar) : "memory");
}
__device__ __forceinline__ void group_bar(int id) {
    asm volatile("bar.sync %0, %1;" :: "r"(id), "r"(128) : "memory");
}

// ------------------------- prep kernels -------------------------------------
__global__ void k_prep(const float* __restrict__ bih, const float* __restrict__ bhh) {
    int i = blockIdx.x * blockDim.x + threadIdx.x;
    if (i < NG) g_bias[i] = bih[i] + bhh[i];
    if (i < NN) g_deg[i] = 1.0f;
}

// W blob, adjacent-unit gate layout. Column np -> (unit u, gate g):
//   c3 = np&7: q2 = c3>>1, gl = c3&1
//   j  = (np>>3)&3: fp = j>>1, half = j&1
//   tg = (np>>5)&3, wq = np>>7
//   u = 32*wq + 8*tg + 2*q2 + fp;  g = 2*half + gl;  n = g*128 + u
// c0/c1 = Whh-hi [512 np][64 k] @128B pitch SW128; c2 = Wih-hi [512][32] @80B.
__global__ void k_prep_wb(const float* __restrict__ Whh, const float* __restrict__ Wih) {
    int idx = blockIdx.x * blockDim.x + threadIdx.x;
    if (idx < 65536) {
        int c = idx >> 15, e = idx & 32767;
        int np = e >> 6, kk = e & 63;
        int q2 = (np >> 1) & 3, gl = np & 1;
        int fp = (np >> 4) & 1, half = (np >> 3) & 1;
        int tg = (np >> 5) & 3, wq = np >> 7;
        int u = 32 * wq + 8 * tg + 2 * q2 + fp;
        int g = 2 * half + gl;
        int n = g * HH + u;
        float val = Whh[n * HH + 64 * c + kk];
        int gnl = kk >> 3;
        uint32_t boff = (uint32_t)c * 65536 + (uint32_t)np * 128 +
                        (uint32_t)((gnl ^ (np & 7)) << 4) + (uint32_t)((kk & 7) * 2);
        *(unsigned short*)((char*)g_Wblob + boff) =
            __bfloat16_as_ushort(__float2bfloat16(val));
    } else if (idx < 65536 + 16384) {
        int e = idx - 65536;
        int np = e >> 5, kk = e & 31;
        int q2 = (np >> 1) & 3, gl = np & 1;
        int fp = (np >> 4) & 1, half = (np >> 3) & 1;
        int tg = (np >> 5) & 3, wq = np >> 7;
        int u = 32 * wq + 8 * tg + 2 * q2 + fp;
        int g = 2 * half + gl;
        int n = g * HH + u;
        float val = Wih[n * FF + kk];
        uint32_t boff = (uint32_t)W2_OFF + (uint32_t)np * 80 +
                        (uint32_t)((kk >> 3) << 4) + (uint32_t)((kk & 7) * 2);
        *(unsigned short*)((char*)g_Wblob + boff) =
            __bfloat16_as_ushort(__float2bfloat16(val));
    }
}

__global__ void k_deg(const int* __restrict__ ei) {
    int e = blockIdx.x * blockDim.x + threadIdx.x;
    if (e < EE) atomicAdd(&g_deg[ei[EE + e]], 1.0f);
}
__global__ void k_dinv() {
    int n = blockIdx.x * blockDim.x + threadIdx.x;
    if (n < NN) g_dinv[n] = rsqrtf(g_deg[n]);
}
__global__ void k_norm(const int* __restrict__ ei) {
    int e = blockIdx.x * blockDim.x + threadIdx.x;
    if (e < EE) g_norm[e] = g_dinv[ei[e]] * g_dinv[ei[EE + e]];
}

// ------------------------- mma.sync LSTM ------------------------------------
// 250 CTAs x 512 threads (16 warps). W (bf16-hi, 168KB) resident in smem.
// Warp w: m-block 16*(w>>2), n-cols 128*(w&3) (group spread across SMSPs).
// NEW: groups are deliberately phase-skewed by ~1/4 step via a clock64 spin
// so that at any instant ~1 group runs its MUFU epilogue while the other 3
// keep the tensor pipe fed. Skew is self-sustaining (equal periods, group-
// local barriers). Deterministic: affects timing only.
__global__ void __launch_bounds__(512, 1) k_lstm_mma(const float* __restrict__ x) {
    extern __shared__ __align__(16) char sm[];
    const uint32_t sbase = (uint32_t)__cvta_generic_to_shared(sm);
    const int tid = threadIdx.x;
    const int lane = tid & 31;
    const int w = tid >> 5;
    const int mb = 16 * (w >> 2);    // m-block from upper bits
    const int nb = 128 * (w & 3);    // n-quad from SMSP bits
    const int grp = 1 + (w >> 2);
    const int mbase = blockIdx.x * MROWS;
    const uint32_t mbarF0 = sbase + MBAR_OFF;

    if (tid == 0) mb_init(mbarF0, 1);

    // zero A hi/lo
    {
        uint4 z = make_uint4(0, 0, 0, 0);
        for (int i = tid; i < 2176; i += 512)
            *(uint4*)(sm + AHI_OFF + i * 16) = z;
    }
    // bias as float4 per unit (i,f,g,o)
    if (tid < HH) {
        float4 b4 = make_float4(g_bias[tid], g_bias[HH + tid],
                                g_bias[2 * HH + tid], g_bias[3 * HH + tid]);
        *(float4*)(sm + BIAS_OFF + tid * 16) = b4;
    }
    // group-local x staging geometry: gtid 0..127 within group
    const int gtid = (w & 3) * 32 + lane;
    const int xr = mb + (gtid >> 3);        // row within CTA (this group's rows)
    const int xf = (gtid & 7) * 4;
    // stage x(0) hi only
    {
        const float* xp = x + (size_t)(mbase + xr) * (TT * FF) + xf;
        float4 v = __ldg((const float4*)xp);
        uint32_t h01 = bfbits(v.x) | (bfbits(v.y) << 16);
        uint32_t h23 = bfbits(v.z) | (bfbits(v.w) << 16);
        *(uint2*)(sm + XHI_OFF + (xr * PX + xf) * 2) = make_uint2(h01, h23);
    }
    __syncthreads();   // mbar init + A zeroing visible (block-wide, once)
    if (tid == 0) {
        mb_expect(mbarF0, W_BYTES);
        bulk_cp(sbase + WR_OFF, (const char*)g_Wblob, W_BYTES, mbarF0);
    }

    // per-lane ldmatrix address pieces
    const uint32_t a_row = mb + (lane & 7) + (((lane >> 3) & 1) << 3);
    const uint32_t a_kh = (lane & 16) ? 8 : 0;
    const uint32_t aoff_hi = sbase + AHI_OFF + (a_row * PA + a_kh) * 2;
    const uint32_t aoff_lo = sbase + ALO_OFF + (a_row * PA + a_kh) * 2;
    const uint32_t xoff_hi = sbase + XHI_OFF + (a_row * PX + a_kh) * 2;
    const uint32_t b_row = (lane & 7) + ((lane & 16) ? 8 : 0);
    const uint32_t kh = (lane >> 3) & 1;
    const uint32_t rx = lane & 7;
    const uint32_t bbase = sbase + WR_OFF + (nb + b_row) * 128;   // c0/c1
    const uint32_t b2base = sbase + WR_OFF + W2_OFF + (nb + b_row) * 80;  // c2

    float cst[16];
#pragma unroll
    for (int i = 0; i < 16; i++) cst[i] = 0.f;

    const int q2 = lane & 3;
    const int r0 = lane >> 2;

    mb_wait(mbarF0, 0);   // W resident
    __syncthreads();

    // deliberate phase skew: group g delays ~g * quarter-step
    {
        long long tgt = (long long)(w >> 2) * 3600;
        if (tgt > 0) {
            long long s0 = clock64();
            while (clock64() - s0 < tgt) { }
        }
    }

    for (int t = 0; t < TT; t++) {
        float acc[4][16];
#pragma unroll
        for (int i = 0; i < 4; i++)
#pragma unroll
            for (int j = 0; j < 16; j++) acc[i][j] = 0.f;

        // ---- c0/c1: h(hi+lo) x Whh-hi ----
#pragma unroll
        for (int c = 0; c < 2; c++) {
            const uint32_t slotB = bbase + (uint32_t)c * 65536;
#pragma unroll
            for (int g2 = 0; g2 < 4; g2++) {
                uint32_t a0, a1, a2, a3, e0, e1, e2, e3;
                ldsm4(a0, a1, a2, a3, aoff_hi + 128 * c + 32 * g2);
                ldsm4(e0, e1, e2, e3, aoff_lo + 128 * c + 32 * g2);
                const uint32_t gx = (((uint32_t)(2 * g2) + kh) ^ rx) << 4;
#pragma unroll
                for (int tau = 0; tau < 4; tau++) {
                    uint32_t bt = slotB + tau * 4096 + gx;
                    uint32_t b0, b1, b2, b3, b4, b5, b6, b7;
                    ldsm4(b0, b1, b2, b3, bt);
                    ldsm4(b4, b5, b6, b7, bt + 2048);
                    mma16816(&acc[tau][0],  a0, a1, a2, a3, b0, b1);
                    mma16816(&acc[tau][4],  a0, a1, a2, a3, b2, b3);
                    mma16816(&acc[tau][8],  a0, a1, a2, a3, b4, b5);
                    mma16816(&acc[tau][12], a0, a1, a2, a3, b6, b7);
                    mma16816(&acc[tau][0],  e0, e1, e2, e3, b0, b1);
                    mma16816(&acc[tau][4],  e0, e1, e2, e3, b2, b3);
                    mma16816(&acc[tau][8],  e0, e1, e2, e3, b4, b5);
                    mma16816(&acc[tau][12], e0, e1, e2, e3, b6, b7);
                }
            }
        }
        // ---- c2: x(hi) x Wih-hi, single term ----
#pragma unroll
        for (int g2 = 0; g2 < 2; g2++) {
            uint32_t a0, a1, a2, a3;
            ldsm4(a0, a1, a2, a3, xoff_hi + 32 * g2);
            const uint32_t gx = ((uint32_t)(2 * g2) + kh) << 4;
#pragma unroll
            for (int tau = 0; tau < 4; tau++) {
                uint32_t bt = b2base + tau * 2560 + gx;
                uint32_t b0, b1, b2, b3, b4, b5, b6, b7;
                ldsm4(b0, b1, b2, b3, bt);
                ldsm4(b4, b5, b6, b7, bt + 1280);
                mma16816(&acc[tau][0],  a0, a1, a2, a3, b0, b1);
                mma16816(&acc[tau][4],  a0, a1, a2, a3, b2, b3);
                mma16816(&acc[tau][8],  a0, a1, a2, a3, b4, b5);
                mma16816(&acc[tau][12], a0, a1, a2, a3, b6, b7);
            }
        }

        group_bar(grp);   // this group's warps finished reading its A rows

        // ---- gates: thread owns adjacent units u0 = base+8tau+2q2 (fp=0)
        // and u0+1 (fp=1); rows r0, r0+8. Packed 4B hi/lo stores.
        const bool last = (t == TT - 1);
#pragma unroll
        for (int tau = 0; tau < 4; tau++) {
            const int u0 = (nb >> 2) + 8 * tau + 2 * q2;
            float4 bE = *(const float4*)(sm + BIAS_OFF + u0 * 16);
            float4 bO = *(const float4*)(sm + BIAS_OFF + u0 * 16 + 16);
#pragma unroll
            for (int rr = 0; rr < 2; rr++) {
                // fp = 0 (unit u0): blocks tau.0 / tau.1
                float zi = acc[tau][2 * rr] + bE.x;
                float zf = acc[tau][2 * rr + 1] + bE.y;
                float zg = acc[tau][4 + 2 * rr] + bE.z;
                float zo = acc[tau][5 + 2 * rr] + bE.w;
                float ig = sigma(zi), fg = sigma(zf);
                float gg = tanha(zg), og = sigma(zo);
                int i0 = tau * 4 + rr;
                float nc = fg * cst[i0] + ig * gg;
                cst[i0] = nc;
                float h0 = og * tanha(nc);
                // fp = 1 (unit u0+1): blocks tau.2 / tau.3
                zi = acc[tau][8 + 2 * rr] + bO.x;
                zf = acc[tau][9 + 2 * rr] + bO.y;
                zg = acc[tau][12 + 2 * rr] + bO.z;
                zo = acc[tau][13 + 2 * rr] + bO.w;
                ig = sigma(zi); fg = sigma(zf);
                gg = tanha(zg); og = sigma(zo);
                int i1 = tau * 4 + 2 + rr;
                nc = fg * cst[i1] + ig * gg;
                cst[i1] = nc;
                float h1 = og * tanha(nc);

                const int m = mb + r0 + 8 * rr;
                if (last) {
                    *(float2*)&g_h[(size_t)(mbase + m) * HH + u0] =
                        make_float2(h0, h1);
                } else {
                    __nv_bfloat16 hh0 = __float2bfloat16(h0);
                    __nv_bfloat16 hh1 = __float2bfloat16(h1);
                    uint32_t hiP = (uint32_t)__bfloat16_as_ushort(hh0) |
                                   ((uint32_t)__bfloat16_as_ushort(hh1) << 16);
                    uint32_t loP = bfbits(h0 - __bfloat162float(hh0)) |
                                   (bfbits(h1 - __bfloat162float(hh1)) << 16);
                    *(uint32_t*)(sm + AHI_OFF + (m * PA + u0) * 2) = hiP;
                    *(uint32_t*)(sm + ALO_OFF + (m * PA + u0) * 2) = loP;
                }
            }
        }

        if (!last) {
            // stage x(t+1) hi only (group-local rows)
            const float* xp = x + (size_t)(mbase + xr) * (TT * FF) + (t + 1) * FF + xf;
            float4 v = __ldg((const float4*)xp);
            uint32_t h01 = bfbits(v.x) | (bfbits(v.y) << 16);
            uint32_t h23 = bfbits(v.z) | (bfbits(v.w) << 16);
            *(uint2*)(sm + XHI_OFF + (xr * PX + xf) * 2) = make_uint2(h01, h23);
        }
        group_bar(grp);   // h/x writes visible to this group before next GEMM
    }
}

// ------------------------- GCN + MLP ----------------------------------------
__global__ void k_xw(const float* __restrict__ gW) {
    __shared__ float hsm[16][HH];
    const int tid = threadIdx.x;
    const int rowbase = blockIdx.x * 16;
#pragma unroll
    for (int r = 0; r < 16; r++) {
        int idx = tid + r * 128;
        hsm[idx >> 7][idx & 127] = g_h[(size_t)rowbase * HH + idx];
    }
    __syncthreads();
    float acc[16];
#pragma unroll
    for (int r = 0; r < 16; r++) acc[r] = 0.f;
#pragma unroll 4
    for (int k = 0; k < HH; k++) {
        float wv = __ldg(&gW[k * GHD + tid]);
#pragma unroll
        for (int r = 0; r < 16; r++) acc[r] += hsm[r][k] * wv;
    }
#pragma unroll
    for (int r = 0; r < 16; r++)
        g_xw[(size_t)(rowbase + r) * GHD + tid] = acc[r];
}

__global__ void k_agg_zero() {
    size_t i = (size_t)blockIdx.x * blockDim.x + threadIdx.x;
    if (i < (size_t)BQ * NN * GHD) g_agg[i] = 0.f;
}

__global__ void k_scatter(const int* __restrict__ ei) {
    const int e = blockIdx.x, ch = threadIdx.x;
    int s, d; float wv;
    if (e < EE) { s = ei[e]; d = ei[EE + e]; wv = g_norm[e]; }
    else { s = d = e - EE; float di = g_dinv[s]; wv = di * di; }
#pragma unroll
    for (int b = 0; b < BQ; b++) {
        float v = g_xw[((size_t)b * NN + s) * GHD + ch] * wv;
        atomicAdd(&g_agg[((size_t)b * NN + d) * GHD + ch], v);
    }
}

__global__ void k_mlp(const float* __restrict__ gb, const float* __restrict__ W1,
                      const float* __restrict__ b1, const float* __restrict__ W2,
                      const float* __restrict__ b2, float* __restrict__ out) {
    __shared__ float in_s[GHD];
    __shared__ float red[64];
    const int m = blockIdx.x, ch = threadIdx.x;
    in_s[ch] = g_agg[(size_t)m * GHD + ch] + __ldg(&gb[ch]);
    __syncthreads();
    if (ch < 64) {
        float s = __ldg(&b1[ch]);
#pragma unroll 8
        for (int k = 0; k < GHD; k++) s += in_s[k] * __ldg(&W1[k * 64 + ch]);
        float h1 = s * sigmf(s);
        red[ch] = h1 * __ldg(&W2[ch]);
    }
    __syncthreads();
    if (ch == 0) {
        float s = __ldg(&b2[0]);
#pragma unroll
        for (int j = 0; j < 64; j++) s += red[j];
        out[m] = s;
    }
}

// ------------------------- launch --------------------------------------------
extern "C" void kernel_launch(void* const* d_in, const int* in_sizes, int n_in,
                              void* d_out, int out_size) {
    const float* x   = (const float*)d_in[0];
    const int*   ei  = (const int*)d_in[1];
    const float* Wih = (const float*)d_in[2];
    const float* Whh = (const float*)d_in[3];
    const float* bih = (const float*)d_in[4];
    const float* bhh = (const float*)d_in[5];
    const float* gW  = (const float*)d_in[6];
    const float* gb  = (const float*)d_in[7];
    const float* W1  = (const float*)d_in[8];
    const float* b1  = (const float*)d_in[9];
    const float* W2  = (const float*)d_in[10];
    const float* b2  = (const float*)d_in[11];
    float* out = (float*)d_out;

    cudaFuncSetAttribute(k_lstm_mma, cudaFuncAttributeMaxDynamicSharedMemorySize,
                         DYN_BYTES);

    // k_lstm_mma is the 4th launch -> profiler's fixed sampling slot
    k_prep<<<(NN + 255) / 256, 256>>>(bih, bhh);
    k_prep_wb<<<(81920 + 255) / 256, 256>>>(Whh, Wih);
    k_deg<<<(EE + 255) / 256, 256>>>(ei);
    k_lstm_mma<<<MM / MROWS, 512, DYN_BYTES>>>(x);
    k_dinv<<<(NN + 255) / 256, 256>>>();
    k_norm<<<(EE + 255) / 256, 256>>>(ei);

    k_xw<<<MM / 16, 128>>>(gW);
    k_agg_zero<<<((size_t)BQ * NN * GHD + 255) / 256, 256>>>();
    k_scatter<<<EE + NN, 128>>>(ei);
    k_mlp<<<MM, 128>>>(gb, W1, b1, W2, b2, out);
}

// round 17
// speedup vs baseline: 6.5176x; 1.3427x over previous
#include <cuda_runtime.h>
#include <cuda_fp16.h>
#include <cstddef>
#include <cstdint>

#define BQ 8
#define NN 2000
#define TT 64
#define FF 32
#define HH 128
#define NG 512
#define EE 32000
#define MM 16000
#define GHD 128

// ---- mma LSTM geometry (fp16 single-term) ----
#define MROWS 64            // rows per CTA
#define PA 136              // A (h) pitch in fp16 elems
#define PX 72               // x pitch in fp16 elems

// W resident in smem: c0/c1 = Whh [512][64k] fp16 @128B pitch (swizzled),
// c2 = Wih [512][32k] fp16 @80B pitch (mod-8 conflict-free)
#define W2_OFF 131072
#define W_BYTES 172032      // 65536*2 + 40960

// smem layout (bytes)
#define WR_OFF  0
#define AHI_OFF 172032
#define XHI_OFF 189440
#define BIAS_OFF 198656
#define MBAR_OFF 200704
#define DYN_BYTES 200768

// ------------------------- device scratch ----------------------------------
__device__ __align__(16) unsigned short g_Wblob[W_BYTES / 2];
__device__ __align__(16) float g_bias[NG];
__device__ float g_deg[NN];
__device__ float g_dinv[NN];
__device__ float g_norm[EE];
__device__ __align__(16) float g_h[MM * HH];
__device__ __align__(16) float g_xw[MM * GHD];
__device__ __align__(16) float g_agg[(size_t)BQ * NN * GHD];

// ------------------------- helpers -----------------------------------------
__device__ __forceinline__ float tanha(float x) {
    float y;
    asm("tanh.approx.f32 %0, %1;" : "=f"(y) : "f"(x));
    return y;
}
__device__ __forceinline__ float sigma(float x) {   // 0.5 + 0.5*tanh(x/2)
    return fmaf(0.5f, tanha(0.5f * x), 0.5f);
}
__device__ __forceinline__ float sigmf(float x) {   // exact (non-LSTM kernels)
    return __fdividef(1.f, 1.f + __expf(-x));
}
__device__ __forceinline__ void ldsm4(uint32_t& r0, uint32_t& r1, uint32_t& r2,
                                      uint32_t& r3, uint32_t addr) {
    asm volatile("ldmatrix.sync.aligned.m8n8.x4.shared.b16 {%0,%1,%2,%3}, [%4];"
                 : "=r"(r0), "=r"(r1), "=r"(r2), "=r"(r3) : "r"(addr));
}
__device__ __forceinline__ void mma16816(float* d, uint32_t a0, uint32_t a1,
                                         uint32_t a2, uint32_t a3,
                                         uint32_t b0, uint32_t b1) {
    asm volatile(
        "mma.sync.aligned.m16n8k16.row.col.f32.f16.f16.f32 "
        "{%0,%1,%2,%3}, {%4,%5,%6,%7}, {%8,%9}, {%0,%1,%2,%3};"
        : "+f"(d[0]), "+f"(d[1]), "+f"(d[2]), "+f"(d[3])
        : "r"(a0), "r"(a1), "r"(a2), "r"(a3), "r"(b0), "r"(b1));
}
__device__ __forceinline__ uint32_t h2bits(float a, float b) {
    __half2 p = __floats2half2_rn(a, b);
    return *(uint32_t*)&p;
}
__device__ __forceinline__ void mb_init(uint32_t a, uint32_t c) {
    asm volatile("mbarrier.init.shared.b64 [%0], %1;" :: "r"(a), "r"(c) : "memory");
}
__device__ __forceinline__ void mb_expect(uint32_t a, uint32_t bytes) {
    asm volatile("mbarrier.arrive.expect_tx.shared.b64 _, [%0], %1;"
                 :: "r"(a), "r"(bytes) : "memory");
}
__device__ __forceinline__ void mb_wait(uint32_t a, uint32_t parity) {
    asm volatile(
        "{\n\t.reg .pred P1;\n\t"
        "W0_%=:\n\t"
        "mbarrier.try_wait.parity.acquire.cta.shared::cta.b64 P1, [%0], %1, 0x989680;\n\t"
        "@P1 bra.uni W1_%=;\n\t"
        "bra.uni W0_%=;\n\t"
        "W1_%=:\n\t}" :: "r"(a), "r"(parity) : "memory");
}
__device__ __forceinline__ void bulk_cp(uint32_t dst, const void* src,
                                        uint32_t bytes, uint32_t mbar) {
    asm volatile("cp.async.bulk.shared::cta.global.mbarrier::complete_tx::bytes "
                 "[%0], [%1], %2, [%3];"
                 :: "r"(dst), "l"(src), "r"(bytes), "r"(mbar) : "memory");
}
__device__ __forceinline__ void group_bar(int id) {
    asm volatile("bar.sync %0, %1;" :: "r"(id), "r"(128) : "memory");
}

// ------------------------- prep kernels -------------------------------------
__global__ void k_prep(const float* __restrict__ bih, const float* __restrict__ bhh) {
    int i = blockIdx.x * blockDim.x + threadIdx.x;
    if (i < NG) g_bias[i] = bih[i] + bhh[i];
    if (i < NN) g_deg[i] = 1.0f;
}

// W blob, adjacent-unit gate layout, fp16. Column np -> (unit u, gate g):
//   q2 = (np>>1)&3, gl = np&1, fp = (np>>4)&1, half = (np>>3)&1,
//   tg = (np>>5)&3, wq = np>>7
//   u = 32*wq + 8*tg + 2*q2 + fp;  g = 2*half + gl;  n = g*128 + u
// c0/c1 = Whh [512 np][64 k] @128B pitch SW128; c2 = Wih [512][32] @80B.
__global__ void k_prep_wb(const float* __restrict__ Whh, const float* __restrict__ Wih) {
    int idx = blockIdx.x * blockDim.x + threadIdx.x;
    if (idx < 65536) {
        int c = idx >> 15, e = idx & 32767;
        int np = e >> 6, kk = e & 63;
        int q2 = (np >> 1) & 3, gl = np & 1;
        int fp = (np >> 4) & 1, half = (np >> 3) & 1;
        int tg = (np >> 5) & 3, wq = np >> 7;
        int u = 32 * wq + 8 * tg + 2 * q2 + fp;
        int g = 2 * half + gl;
        int n = g * HH + u;
        float val = Whh[n * HH + 64 * c + kk];
        int gnl = kk >> 3;
        uint32_t boff = (uint32_t)c * 65536 + (uint32_t)np * 128 +
                        (uint32_t)((gnl ^ (np & 7)) << 4) + (uint32_t)((kk & 7) * 2);
        __half hv = __float2half_rn(val);
        *(unsigned short*)((char*)g_Wblob + boff) = *(unsigned short*)&hv;
    } else if (idx < 65536 + 16384) {
        int e = idx - 65536;
        int np = e >> 5, kk = e & 31;
        int q2 = (np >> 1) & 3, gl = np & 1;
        int fp = (np >> 4) & 1, half = (np >> 3) & 1;
        int tg = (np >> 5) & 3, wq = np >> 7;
        int u = 32 * wq + 8 * tg + 2 * q2 + fp;
        int g = 2 * half + gl;
        int n = g * HH + u;
        float val = Wih[n * FF + kk];
        uint32_t boff = (uint32_t)W2_OFF + (uint32_t)np * 80 +
                        (uint32_t)((kk >> 3) << 4) + (uint32_t)((kk & 7) * 2);
        __half hv = __float2half_rn(val);
        *(unsigned short*)((char*)g_Wblob + boff) = *(unsigned short*)&hv;
    }
}

__global__ void k_deg(const int* __restrict__ ei) {
    int e = blockIdx.x * blockDim.x + threadIdx.x;
    if (e < EE) atomicAdd(&g_deg[ei[EE + e]], 1.0f);
}
__global__ void k_dinv() {
    int n = blockIdx.x * blockDim.x + threadIdx.x;
    if (n < NN) g_dinv[n] = rsqrtf(g_deg[n]);
}
__global__ void k_norm(const int* __restrict__ ei) {
    int e = blockIdx.x * blockDim.x + threadIdx.x;
    if (e < EE) g_norm[e] = g_dinv[ei[e]] * g_dinv[ei[EE + e]];
}

// ------------------------- mma.sync LSTM (fp16) ------------------------------
// 250 CTAs x 512 threads (16 warps). W (fp16, 168KB) resident in smem.
// Warp w: m-block 16*(w>>2), n-cols 128*(w&3) (group spread across SMSPs).
// fp16 single-term GEMM: 160 mma/warp/step (was 288 with bf16 split) —
// fp16's 10 mantissa bits beat the bf16 2-term split's dominant W error.
__global__ void __launch_bounds__(512, 1) k_lstm_mma(const float* __restrict__ x) {
    extern __shared__ __align__(16) char sm[];
    const uint32_t sbase = (uint32_t)__cvta_generic_to_shared(sm);
    const int tid = threadIdx.x;
    const int lane = tid & 31;
    const int w = tid >> 5;
    const int mb = 16 * (w >> 2);
    const int nb = 128 * (w & 3);
    const int grp = 1 + (w >> 2);
    const int mbase = blockIdx.x * MROWS;
    const uint32_t mbarF0 = sbase + MBAR_OFF;

    if (tid == 0) mb_init(mbarF0, 1);

    // zero A (h region): 64 rows x 272B = 17408B
    {
        uint4 z = make_uint4(0, 0, 0, 0);
        for (int i = tid; i < 1088; i += 512)
            *(uint4*)(sm + AHI_OFF + i * 16) = z;
    }
    // bias as float4 per unit (i,f,g,o)
    if (tid < HH) {
        float4 b4 = make_float4(g_bias[tid], g_bias[HH + tid],
                                g_bias[2 * HH + tid], g_bias[3 * HH + tid]);
        *(float4*)(sm + BIAS_OFF + tid * 16) = b4;
    }
    // group-local x staging geometry: gtid 0..127 within group
    const int gtid = (w & 3) * 32 + lane;
    const int xr = mb + (gtid >> 3);
    const int xf = (gtid & 7) * 4;
    // stage x(0) fp16
    {
        const float* xp = x + (size_t)(mbase + xr) * (TT * FF) + xf;
        float4 v = __ldg((const float4*)xp);
        *(uint2*)(sm + XHI_OFF + (xr * PX + xf) * 2) =
            make_uint2(h2bits(v.x, v.y), h2bits(v.z, v.w));
    }
    __syncthreads();
    if (tid == 0) {
        mb_expect(mbarF0, W_BYTES);
        bulk_cp(sbase + WR_OFF, (const char*)g_Wblob, W_BYTES, mbarF0);
    }

    // per-lane ldmatrix address pieces
    const uint32_t a_row = mb + (lane & 7) + (((lane >> 3) & 1) << 3);
    const uint32_t a_kh = (lane & 16) ? 8 : 0;
    const uint32_t aoff = sbase + AHI_OFF + (a_row * PA + a_kh) * 2;
    const uint32_t xoff = sbase + XHI_OFF + (a_row * PX + a_kh) * 2;
    const uint32_t b_row = (lane & 7) + ((lane & 16) ? 8 : 0);
    const uint32_t kh = (lane >> 3) & 1;
    const uint32_t rx = lane & 7;
    const uint32_t bbase = sbase + WR_OFF + (nb + b_row) * 128;   // c0/c1
    const uint32_t b2base = sbase + WR_OFF + W2_OFF + (nb + b_row) * 80;  // c2

    float cst[16];
#pragma unroll
    for (int i = 0; i < 16; i++) cst[i] = 0.f;

    const int q2 = lane & 3;
    const int r0 = lane >> 2;

    mb_wait(mbarF0, 0);   // W resident
    __syncthreads();

    for (int t = 0; t < TT; t++) {
        float acc[4][16];
#pragma unroll
        for (int i = 0; i < 4; i++)
#pragma unroll
            for (int j = 0; j < 16; j++) acc[i][j] = 0.f;

        // ---- c0/c1: h x Whh (single fp16 term) ----
#pragma unroll
        for (int c = 0; c < 2; c++) {
            const uint32_t slotB = bbase + (uint32_t)c * 65536;
#pragma unroll
            for (int g2 = 0; g2 < 4; g2++) {
                uint32_t a0, a1, a2, a3;
                ldsm4(a0, a1, a2, a3, aoff + 128 * c + 32 * g2);
                const uint32_t gx = (((uint32_t)(2 * g2) + kh) ^ rx) << 4;
#pragma unroll
                for (int tau = 0; tau < 4; tau++) {
                    uint32_t bt = slotB + tau * 4096 + gx;
                    uint32_t b0, b1, b2, b3, b4, b5, b6, b7;
                    ldsm4(b0, b1, b2, b3, bt);
                    ldsm4(b4, b5, b6, b7, bt + 2048);
                    mma16816(&acc[tau][0],  a0, a1, a2, a3, b0, b1);
                    mma16816(&acc[tau][4],  a0, a1, a2, a3, b2, b3);
                    mma16816(&acc[tau][8],  a0, a1, a2, a3, b4, b5);
                    mma16816(&acc[tau][12], a0, a1, a2, a3, b6, b7);
                }
            }
        }
        // ---- c2: x x Wih (single fp16 term) ----
#pragma unroll
        for (int g2 = 0; g2 < 2; g2++) {
            uint32_t a0, a1, a2, a3;
            ldsm4(a0, a1, a2, a3, xoff + 32 * g2);
            const uint32_t gx = ((uint32_t)(2 * g2) + kh) << 4;
#pragma unroll
            for (int tau = 0; tau < 4; tau++) {
                uint32_t bt = b2base + tau * 2560 + gx;
                uint32_t b0, b1, b2, b3, b4, b5, b6, b7;
                ldsm4(b0, b1, b2, b3, bt);
                ldsm4(b4, b5, b6, b7, bt + 1280);
                mma16816(&acc[tau][0],  a0, a1, a2, a3, b0, b1);
                mma16816(&acc[tau][4],  a0, a1, a2, a3, b2, b3);
                mma16816(&acc[tau][8],  a0, a1, a2, a3, b4, b5);
                mma16816(&acc[tau][12], a0, a1, a2, a3, b6, b7);
            }
        }

        group_bar(grp);   // this group's warps finished reading its A rows

        // ---- gates: thread owns adjacent units u0 = base+8tau+2q2 (fp=0)
        // and u0+1 (fp=1); rows r0, r0+8. Packed half2 stores.
        const bool last = (t == TT - 1);
#pragma unroll
        for (int tau = 0; tau < 4; tau++) {
            const int u0 = (nb >> 2) + 8 * tau + 2 * q2;
            float4 bE = *(const float4*)(sm + BIAS_OFF + u0 * 16);
            float4 bO = *(const float4*)(sm + BIAS_OFF + u0 * 16 + 16);
#pragma unroll
            for (int rr = 0; rr < 2; rr++) {
                float zi = acc[tau][2 * rr] + bE.x;
                float zf = acc[tau][2 * rr + 1] + bE.y;
                float zg = acc[tau][4 + 2 * rr] + bE.z;
                float zo = acc[tau][5 + 2 * rr] + bE.w;
                float ig = sigma(zi), fg = sigma(zf);
                float gg = tanha(zg), og = sigma(zo);
                int i0 = tau * 4 + rr;
                float nc = fg * cst[i0] + ig * gg;
                cst[i0] = nc;
                float h0 = og * tanha(nc);
                zi = acc[tau][8 + 2 * rr] + bO.x;
                zf = acc[tau][9 + 2 * rr] + bO.y;
                zg = acc[tau][12 + 2 * rr] + bO.z;
                zo = acc[tau][13 + 2 * rr] + bO.w;
                ig = sigma(zi); fg = sigma(zf);
                gg = tanha(zg); og = sigma(zo);
                int i1 = tau * 4 + 2 + rr;
                nc = fg * cst[i1] + ig * gg;
                cst[i1] = nc;
                float h1 = og * tanha(nc);

                const int m = mb + r0 + 8 * rr;
                if (last) {
                    *(float2*)&g_h[(size_t)(mbase + m) * HH + u0] =
                        make_float2(h0, h1);
                } else {
                    *(uint32_t*)(sm + AHI_OFF + (m * PA + u0) * 2) =
                        h2bits(h0, h1);
                }
            }
        }

        if (!last) {
            const float* xp = x + (size_t)(mbase + xr) * (TT * FF) + (t + 1) * FF + xf;
            float4 v = __ldg((const float4*)xp);
            *(uint2*)(sm + XHI_OFF + (xr * PX + xf) * 2) =
                make_uint2(h2bits(v.x, v.y), h2bits(v.z, v.w));
        }
        group_bar(grp);   // h/x writes visible to this group before next GEMM
    }
}

// ------------------------- GCN + MLP ----------------------------------------
__global__ void k_xw(const float* __restrict__ gW) {
    __shared__ float hsm[16][HH];
    const int tid = threadIdx.x;
    const int rowbase = blockIdx.x * 16;
#pragma unroll
    for (int r = 0; r < 16; r++) {
        int idx = tid + r * 128;
        hsm[idx >> 7][idx & 127] = g_h[(size_t)rowbase * HH + idx];
    }
    __syncthreads();
    float acc[16];
#pragma unroll
    for (int r = 0; r < 16; r++) acc[r] = 0.f;
#pragma unroll 4
    for (int k = 0; k < HH; k++) {
        float wv = __ldg(&gW[k * GHD + tid]);
#pragma unroll
        for (int r = 0; r < 16; r++) acc[r] += hsm[r][k] * wv;
    }
#pragma unroll
    for (int r = 0; r < 16; r++)
        g_xw[(size_t)(rowbase + r) * GHD + tid] = acc[r];
}

__global__ void k_agg_zero() {
    size_t i = (size_t)blockIdx.x * blockDim.x + threadIdx.x;
    if (i < (size_t)BQ * NN * GHD) g_agg[i] = 0.f;
}

__global__ void k_scatter(const int* __restrict__ ei) {
    const int e = blockIdx.x, ch = threadIdx.x;
    int s, d; float wv;
    if (e < EE) { s = ei[e]; d = ei[EE + e]; wv = g_norm[e]; }
    else { s = d = e - EE; float di = g_dinv[s]; wv = di * di; }
#pragma unroll
    for (int b = 0; b < BQ; b++) {
        float v = g_xw[((size_t)b * NN + s) * GHD + ch] * wv;
        atomicAdd(&g_agg[((size_t)b * NN + d) * GHD + ch], v);
    }
}

__global__ void k_mlp(const float* __restrict__ gb, const float* __restrict__ W1,
                      const float* __restrict__ b1, const float* __restrict__ W2,
                      const float* __restrict__ b2, float* __restrict__ out) {
    __shared__ float in_s[GHD];
    __shared__ float red[64];
    const int m = blockIdx.x, ch = threadIdx.x;
    in_s[ch] = g_agg[(size_t)m * GHD + ch] + __ldg(&gb[ch]);
    __syncthreads();
    if (ch < 64) {
        float s = __ldg(&b1[ch]);
#pragma unroll 8
        for (int k = 0; k < GHD; k++) s += in_s[k] * __ldg(&W1[k * 64 + ch]);
        float h1 = s * sigmf(s);
        red[ch] = h1 * __ldg(&W2[ch]);
    }
    __syncthreads();
    if (ch == 0) {
        float s = __ldg(&b2[0]);
#pragma unroll
        for (int j = 0; j < 64; j++) s += red[j];
        out[m] = s;
    }
}

// ------------------------- launch --------------------------------------------
extern "C" void kernel_launch(void* const* d_in, const int* in_sizes, int n_in,
                              void* d_out, int out_size) {
    const float* x   = (const float*)d_in[0];
    const int*   ei  = (const int*)d_in[1];
    const float* Wih = (const float*)d_in[2];
    const float* Whh = (const float*)d_in[3];
    const float* bih = (const float*)d_in[4];
    const float* bhh = (const float*)d_in[5];
    const float* gW  = (const float*)d_in[6];
    const float* gb  = (const float*)d_in[7];
    const float* W1  = (const float*)d_in[8];
    const float* b1  = (const float*)d_in[9];
    const float* W2  = (const float*)d_in[10];
    const float* b2  = (const float*)d_in[11];
    float* out = (float*)d_out;

    cudaFuncSetAttribute(k_lstm_mma, cudaFuncAttributeMaxDynamicSharedMemorySize,
                         DYN_BYTES);

    // k_lstm_mma is the 4th launch -> profiler's fixed sampling slot
    k_prep<<<(NN + 255) / 256, 256>>>(bih, bhh);
    k_prep_wb<<<(81920 + 255) / 256, 256>>>(Whh, Wih);
    k_deg<<<(EE + 255) / 256, 256>>>(ei);
    k_lstm_mma<<<MM / MROWS, 512, DYN_BYTES>>>(x);
    k_dinv<<<(NN + 255) / 256, 256>>>();
    k_norm<<<(EE + 255) / 256, 256>>>(ei);

    k_xw<<<MM / 16, 128>>>(gW);
    k_agg_zero<<<((size_t)BQ * NN * GHD + 255) / 256, 256>>>();
    k_scatter<<<EE + NN, 128>>>(ei);
    k_mlp<<<MM, 128>>>(gb, W1, b1, W2, b2, out);
}